// round 3
// baseline (speedup 1.0000x reference)
#include <cuda_runtime.h>
#include <cstddef>

#define B_ 4
#define L_ 512
#define HID_ 512
#define H_ 8
#define DH_ 64

// ---------------- scratch (device globals; no allocations allowed) ----------
__device__ float g_q[B_ * L_ * HID_];
__device__ float g_k[B_ * L_ * HID_];
__device__ float g_v[B_ * L_ * HID_];
__device__ float g_sc[B_ * H_ * L_ * L_];   // scores, then probs (in place)

// ---------------- packed f32x2 FMA ------------------------------------------
__device__ __forceinline__ void ffma2(float2& d, const float2 a, const float2 b) {
    asm("fma.rn.f32x2 %0, %1, %2, %0;"
        : "+l"(reinterpret_cast<unsigned long long&>(d))
        : "l"(reinterpret_cast<const unsigned long long&>(a)),
          "l"(reinterpret_cast<const unsigned long long&>(b)));
}
__device__ __forceinline__ float2 fdup(float a) { return make_float2(a, a); }

// ---------------- cp.async helpers ------------------------------------------
__device__ __forceinline__ void cp_async16(void* smem, const void* gmem) {
    unsigned s = (unsigned)__cvta_generic_to_shared(smem);
    asm volatile("cp.async.cg.shared.global [%0], [%1], 16;\n" :: "r"(s), "l"(gmem));
}
__device__ __forceinline__ void cp_commit() {
    asm volatile("cp.async.commit_group;\n");
}
template <int N>
__device__ __forceinline__ void cp_wait() {
    asm volatile("cp.async.wait_group %0;\n" :: "n"(N));
}

// =============================================================================
// K1: QKV projection.  C[m][n] = sum_k X[m][k] * W[n][k] + bias[n]
// BM=128, BN=64, BK=16, 256 threads, micro 8x4, double-buffered (reg-staged).
// grid (8, 16, 3) = 384 CTAs.
// =============================================================================
__global__ __launch_bounds__(256, 2) void k_proj(
    const float* __restrict__ X,
    const float* __restrict__ Wq, const float* __restrict__ bq,
    const float* __restrict__ Wk, const float* __restrict__ bk,
    const float* __restrict__ Wv, const float* __restrict__ bv)
{
    __shared__ float As[2][16][132];
    __shared__ float Bs[2][16][68];

    const float* W; const float* bias; float* C;
    if (blockIdx.z == 0)      { W = Wq; bias = bq; C = g_q; }
    else if (blockIdx.z == 1) { W = Wk; bias = bk; C = g_k; }
    else                      { W = Wv; bias = bv; C = g_v; }

    const int m0 = blockIdx.y * 128;
    const int n0 = blockIdx.x * 64;
    const int tid = threadIdx.x;
    const int tx = tid & 15, ty = tid >> 4;
    const int lrow = tid >> 2;
    const int lf   = tid & 3;

    float2 acc[4][4];
#pragma unroll
    for (int i = 0; i < 4; i++)
#pragma unroll
        for (int j = 0; j < 4; j++) acc[i][j] = make_float2(0.f, 0.f);

    // prefetch tile 0 into registers
    float4 a0r = *(const float4*)&X[(size_t)(m0 + lrow) * 512 + lf * 4];
    float4 a1r = *(const float4*)&X[(size_t)(m0 + lrow + 64) * 512 + lf * 4];
    float4 b0r = *(const float4*)&W[(size_t)(n0 + lrow) * 512 + lf * 4];

#pragma unroll 1
    for (int t = 0; t < 32; t++) {
        const int cur = t & 1;
        As[cur][lf * 4 + 0][lrow] = a0r.x; As[cur][lf * 4 + 1][lrow] = a0r.y;
        As[cur][lf * 4 + 2][lrow] = a0r.z; As[cur][lf * 4 + 3][lrow] = a0r.w;
        As[cur][lf * 4 + 0][lrow + 64] = a1r.x; As[cur][lf * 4 + 1][lrow + 64] = a1r.y;
        As[cur][lf * 4 + 2][lrow + 64] = a1r.z; As[cur][lf * 4 + 3][lrow + 64] = a1r.w;
        Bs[cur][lf * 4 + 0][lrow] = b0r.x; Bs[cur][lf * 4 + 1][lrow] = b0r.y;
        Bs[cur][lf * 4 + 2][lrow] = b0r.z; Bs[cur][lf * 4 + 3][lrow] = b0r.w;
        __syncthreads();

        if (t < 31) {
            int k0 = (t + 1) * 16;
            a0r = *(const float4*)&X[(size_t)(m0 + lrow) * 512 + k0 + lf * 4];
            a1r = *(const float4*)&X[(size_t)(m0 + lrow + 64) * 512 + k0 + lf * 4];
            b0r = *(const float4*)&W[(size_t)(n0 + lrow) * 512 + k0 + lf * 4];
        }

#pragma unroll
        for (int kk = 0; kk < 16; kk++) {
            float4 a0 = *(const float4*)&As[cur][kk][ty * 8];
            float4 a1 = *(const float4*)&As[cur][kk][ty * 8 + 4];
            float4 b4 = *(const float4*)&Bs[cur][kk][tx * 4];
            float2 a2[4] = { make_float2(a0.x, a0.y), make_float2(a0.z, a0.w),
                             make_float2(a1.x, a1.y), make_float2(a1.z, a1.w) };
            float bj[4] = { b4.x, b4.y, b4.z, b4.w };
#pragma unroll
            for (int j = 0; j < 4; j++) {
                float2 bd = fdup(bj[j]);
#pragma unroll
                for (int i = 0; i < 4; i++) ffma2(acc[i][j], a2[i], bd);
            }
        }
    }

    float bvv[4];
#pragma unroll
    for (int j = 0; j < 4; j++) bvv[j] = bias[n0 + tx * 4 + j];

#pragma unroll
    for (int i = 0; i < 4; i++) {
        int m = m0 + ty * 8 + 2 * i;
        *(float4*)&C[(size_t)m * 512 + n0 + tx * 4] =
            make_float4(acc[i][0].x + bvv[0], acc[i][1].x + bvv[1],
                        acc[i][2].x + bvv[2], acc[i][3].x + bvv[3]);
        *(float4*)&C[(size_t)(m + 1) * 512 + n0 + tx * 4] =
            make_float4(acc[i][0].y + bvv[0], acc[i][1].y + bvv[1],
                        acc[i][2].y + bvv[2], acc[i][3].y + bvv[3]);
    }
}

// =============================================================================
// K2: scores = q . k^T per (b,h).  BM=128(q), BN=64(k), K=64 fully resident.
// One load phase, one sync, 64 straight FMA steps. grid (8, 4, 32).
// =============================================================================
__global__ __launch_bounds__(256, 2) void k_scores()
{
    __shared__ float As[64][132];
    __shared__ float Bs[64][68];

    const int bh = blockIdx.z;
    const int b = bh >> 3, h = bh & 7;
    const int m0 = blockIdx.y * 128;
    const int n0 = blockIdx.x * 64;
    const float* A  = g_q + (size_t)b * L_ * HID_ + h * DH_;
    const float* Bm = g_k + (size_t)b * L_ * HID_ + h * DH_;
    float* C = g_sc + (size_t)bh * L_ * L_;

    const int tid = threadIdx.x;
    const int tx = tid & 15, ty = tid >> 4;
    const int lrow = tid >> 2;
    const int lf   = tid & 3;

#pragma unroll
    for (int c = 0; c < 4; c++) {
        int d0 = c * 16 + lf * 4;
        float4 a4 = *(const float4*)&A[(size_t)(m0 + lrow) * 512 + d0];
        As[d0 + 0][lrow] = a4.x; As[d0 + 1][lrow] = a4.y;
        As[d0 + 2][lrow] = a4.z; As[d0 + 3][lrow] = a4.w;
        float4 a5 = *(const float4*)&A[(size_t)(m0 + lrow + 64) * 512 + d0];
        As[d0 + 0][lrow + 64] = a5.x; As[d0 + 1][lrow + 64] = a5.y;
        As[d0 + 2][lrow + 64] = a5.z; As[d0 + 3][lrow + 64] = a5.w;
        float4 b4 = *(const float4*)&Bm[(size_t)(n0 + lrow) * 512 + d0];
        Bs[d0 + 0][lrow] = b4.x; Bs[d0 + 1][lrow] = b4.y;
        Bs[d0 + 2][lrow] = b4.z; Bs[d0 + 3][lrow] = b4.w;
    }
    __syncthreads();

    float2 acc[4][4];
#pragma unroll
    for (int i = 0; i < 4; i++)
#pragma unroll
        for (int j = 0; j < 4; j++) acc[i][j] = make_float2(0.f, 0.f);

#pragma unroll 16
    for (int kk = 0; kk < 64; kk++) {
        float4 a0 = *(const float4*)&As[kk][ty * 8];
        float4 a1 = *(const float4*)&As[kk][ty * 8 + 4];
        float4 b4 = *(const float4*)&Bs[kk][tx * 4];
        float2 a2[4] = { make_float2(a0.x, a0.y), make_float2(a0.z, a0.w),
                         make_float2(a1.x, a1.y), make_float2(a1.z, a1.w) };
        float bj[4] = { b4.x, b4.y, b4.z, b4.w };
#pragma unroll
        for (int j = 0; j < 4; j++) {
            float2 bd = fdup(bj[j]);
#pragma unroll
            for (int i = 0; i < 4; i++) ffma2(acc[i][j], a2[i], bd);
        }
    }

#pragma unroll
    for (int i = 0; i < 4; i++) {
        int m = m0 + ty * 8 + 2 * i;
        *(float4*)&C[(size_t)m * 512 + n0 + tx * 4] =
            make_float4(acc[i][0].x, acc[i][1].x, acc[i][2].x, acc[i][3].x);
        *(float4*)&C[(size_t)(m + 1) * 512 + n0 + tx * 4] =
            make_float4(acc[i][0].y, acc[i][1].y, acc[i][2].y, acc[i][3].y);
    }
}

// =============================================================================
// K3: fused per-(b,q). rels XOR-swizzled in smem via cp.async pipeline.
// Stage B: 4 independent accumulators + packed q layout.  Stage D: 4 accs.
// smem: rels 512x64 fp32 (swizzled, 128KB), sc_s[8][516], q_s[512]
// =============================================================================
#define SMEM_FUSED ((512 * 64 + 8 * 516 + 512) * 4)

__global__ __launch_bounds__(256) void k_fused(
    const float* __restrict__ rels,
    const float* __restrict__ heads,
    float* __restrict__ out)
{
    extern __shared__ float sm[];
    float4* rv  = (float4*)sm;          // 512 rows x 16 float4 (swizzled)
    float* sc_s = sm + 512 * 64;        // 8 * 516
    float* q_s  = sc_s + 8 * 516;       // 512: q_pair[p][d] float2; later reduce

    const int bq = blockIdx.x;
    const int b = bq >> 9, q = bq & 511;
    const int tid = threadIdx.x;
    const int lane = tid & 31, w = tid >> 5;

    const float* rg = rels + (size_t)bq * (512 * 64);

    float4 qv;
    if (tid < 128)
        qv = *(const float4*)&g_q[((size_t)b * L_ + q) * HID_ + tid * 4];

    // ---- issue 8 cp.async groups: group g = rels rows [64g, 64g+64) ----
#pragma unroll
    for (int g = 0; g < 8; g++) {
#pragma unroll
        for (int i = 0; i < 4; i++) {
            int flat = g * 1024 + i * 256 + tid;   // float4 index
            int row = flat >> 4, d4 = flat & 15;
            cp_async16(&rv[row * 16 + (d4 ^ (row & 15))], rg + (size_t)flat * 4);
        }
        cp_commit();
    }

    // q_pair layout: q_s[p*128 + d*2 + comp] = q[head 2p+comp][d]
    if (tid < 128) {
        int e = tid * 4;
#pragma unroll
        for (int i = 0; i < 4; i++) {
            int d = (e + i) & 63, h = (e + i) >> 6;
            float val = (i == 0) ? qv.x : (i == 1) ? qv.y : (i == 2) ? qv.z : qv.w;
            q_s[(h >> 1) * 128 + d * 2 + (h & 1)] = val;
        }
    }

    const int kl = tid >> 2;       // 0..63 within group
    const int p  = tid & 3;        // head pair
    const size_t hoff   = ((size_t)b * 512 + q) * 512;
    const size_t scoff0 = (((size_t)(b * 8 + 2 * p)) * 512 + q) * 512;
    const size_t scoff1 = scoff0 + (size_t)512 * 512;

    // preload group-0 scalars
    float hvc = heads[hoff + kl];
    float s0c = g_sc[scoff0 + kl];
    float s1c = g_sc[scoff1 + kl];

#define GROUP_BODY(G, NWAIT)                                                   \
    do {                                                                       \
        float hvn = 0.f, s0n = 0.f, s1n = 0.f;                                 \
        if ((G) < 7) {                                                         \
            int kn = ((G) + 1) * 64 + kl;                                      \
            hvn = heads[hoff + kn];                                            \
            s0n = g_sc[scoff0 + kn];                                           \
            s1n = g_sc[scoff1 + kn];                                           \
        }                                                                      \
        cp_wait<NWAIT>();                                                      \
        __syncthreads();                                                       \
        const int k = (G) * 64 + kl;                                           \
        float2 aA = make_float2(0.f, 0.f), aB = aA, aC = aA, aD = aA;          \
        _Pragma("unroll")                                                      \
        for (int d4 = 0; d4 < 16; d4++) {                                      \
            float4 r4  = rv[k * 16 + (d4 ^ (k & 15))];                         \
            float4 qp0 = *(const float4*)&q_s[p * 128 + d4 * 8];               \
            float4 qp1 = *(const float4*)&q_s[p * 128 + d4 * 8 + 4];           \
            ffma2(aA, fdup(r4.x), make_float2(qp0.x, qp0.y));                  \
            ffma2(aB, fdup(r4.y), make_float2(qp0.z, qp0.w));                  \
            ffma2(aC, fdup(r4.z), make_float2(qp1.x, qp1.y));                  \
            ffma2(aD, fdup(r4.w), make_float2(qp1.z, qp1.w));                  \
        }                                                                      \
        float2 acc = make_float2(aA.x + aB.x + aC.x + aD.x,                    \
                                 aA.y + aB.y + aC.y + aD.y);                   \
        sc_s[(2 * p) * 516 + k]     = (acc.x + s0c) * 0.125f + hvc;            \
        sc_s[(2 * p + 1) * 516 + k] = (acc.y + s1c) * 0.125f + hvc;            \
        hvc = hvn; s0c = s0n; s1c = s1n;                                       \
    } while (0)

    GROUP_BODY(0, 7); GROUP_BODY(1, 6); GROUP_BODY(2, 5); GROUP_BODY(3, 4);
    GROUP_BODY(4, 3); GROUP_BODY(5, 2); GROUP_BODY(6, 1); GROUP_BODY(7, 0);
#undef GROUP_BODY
    __syncthreads();

    // ---- stage C: softmax, warp w == head w ----
    {
        float* row = sc_s + w * 516;
        float vals[16];
        float mx = -1e30f;
#pragma unroll
        for (int i = 0; i < 16; i++) { vals[i] = row[i * 32 + lane]; mx = fmaxf(mx, vals[i]); }
#pragma unroll
        for (int o = 16; o; o >>= 1) mx = fmaxf(mx, __shfl_xor_sync(0xffffffffu, mx, o));
        float s = 0.f;
#pragma unroll
        for (int i = 0; i < 16; i++) { vals[i] = __expf(vals[i] - mx); s += vals[i]; }
#pragma unroll
        for (int o = 16; o; o >>= 1) s += __shfl_xor_sync(0xffffffffu, s, o);
        float inv = 1.f / s;
        float* pg = g_sc + (((size_t)(b * 8 + w)) * 512 + q) * 512;
#pragma unroll
        for (int i = 0; i < 16; i++) {
            float pv = vals[i] * inv;
            row[i * 32 + lane] = pv;
            pg[i * 32 + lane] = pv;
        }
    }
    __syncthreads();

    // ---- stage D: rel-ctx = probs . rels (k-split by 2, 4 accumulators) ----
    {
        const int ks = tid >> 7;
        const int r  = tid & 127;
        const int h  = r >> 4;
        const int dq = r & 15;
        float2 c0[2] = { make_float2(0.f, 0.f), make_float2(0.f, 0.f) };
        float2 c1[2] = { make_float2(0.f, 0.f), make_float2(0.f, 0.f) };
        const float* prow = sc_s + h * 516;
        const int kbeg = ks * 256;
#pragma unroll 8
        for (int k = kbeg; k < kbeg + 256; k += 4) {
            float4 p4 = *(const float4*)&prow[k];
            float pj[4] = { p4.x, p4.y, p4.z, p4.w };
#pragma unroll
            for (int j = 0; j < 4; j++) {
                float4 r4 = rv[(k + j) * 16 + (dq ^ ((k + j) & 15))];
                float2 pd = fdup(pj[j]);
                ffma2(c0[j & 1], pd, make_float2(r4.x, r4.y));
                ffma2(c1[j & 1], pd, make_float2(r4.z, r4.w));
            }
        }
        float2 c0f = make_float2(c0[0].x + c0[1].x, c0[0].y + c0[1].y);
        float2 c1f = make_float2(c1[0].x + c1[1].x, c1[0].y + c1[1].y);
        if (ks == 1) {
            *(float4*)&q_s[r * 4] = make_float4(c0f.x, c0f.y, c1f.x, c1f.y);
        }
        __syncthreads();
        if (ks == 0) {
            float4 t = *(const float4*)&q_s[r * 4];
            float4 o = make_float4(c0f.x + t.x, c0f.y + t.y, c1f.x + t.z, c1f.y + t.w);
            *(float4*)&out[(size_t)bq * 512 + h * 64 + dq * 4] = o;
        }
    }
}

// =============================================================================
// K4: ctx += probs @ v per (b,h).  BM=64, BN=64, BK=16, double-buffered.
// grid (8, 32) = 256 CTAs, up to 4 CTAs/SM.
// =============================================================================
__global__ __launch_bounds__(256, 4) void k_ctx(float* __restrict__ out)
{
    __shared__ float As[2][16][68];
    __shared__ float Bs[2][16][68];

    const int bh = blockIdx.y;
    const int b = bh >> 3, h = bh & 7;
    const int m0 = blockIdx.x * 64;
    const float* P = g_sc + (size_t)bh * L_ * L_;
    const float* V = g_v + (size_t)b * L_ * HID_ + h * DH_;

    const int tid = threadIdx.x;
    const int tx = tid & 15, ty = tid >> 4;
    const int lrow = tid >> 2;
    const int lf   = tid & 3;
    const int vrow = tid >> 4;
    const int vc   = tid & 15;

    float2 acc[2][4];
#pragma unroll
    for (int i = 0; i < 2; i++)
#pragma unroll
        for (int j = 0; j < 4; j++) acc[i][j] = make_float2(0.f, 0.f);

    float4 a4r = *(const float4*)&P[(size_t)(m0 + lrow) * 512 + lf * 4];
    float4 b4r = *(const float4*)&V[(size_t)vrow * 512 + vc * 4];

#pragma unroll 1
    for (int t = 0; t < 32; t++) {
        const int cur = t & 1;
        As[cur][lf * 4 + 0][lrow] = a4r.x; As[cur][lf * 4 + 1][lrow] = a4r.y;
        As[cur][lf * 4 + 2][lrow] = a4r.z; As[cur][lf * 4 + 3][lrow] = a4r.w;
        *(float4*)&Bs[cur][vrow][vc * 4] = b4r;
        __syncthreads();

        if (t < 31) {
            int k0 = (t + 1) * 16;
            a4r = *(const float4*)&P[(size_t)(m0 + lrow) * 512 + k0 + lf * 4];
            b4r = *(const float4*)&V[(size_t)(k0 + vrow) * 512 + vc * 4];
        }

#pragma unroll
        for (int kk = 0; kk < 16; kk++) {
            float4 a4 = *(const float4*)&As[cur][kk][ty * 4];
            float4 b4 = *(const float4*)&Bs[cur][kk][tx * 4];
            float2 a2[2] = { make_float2(a4.x, a4.y), make_float2(a4.z, a4.w) };
            float bj[4] = { b4.x, b4.y, b4.z, b4.w };
#pragma unroll
            for (int j = 0; j < 4; j++) {
                float2 bd = fdup(bj[j]);
#pragma unroll
                for (int i = 0; i < 2; i++) ffma2(acc[i][j], a2[i], bd);
            }
        }
    }

#pragma unroll
    for (int i = 0; i < 2; i++) {
        int m = m0 + ty * 4 + 2 * i;
        float4* p0 = (float4*)&out[((size_t)b * 512 + m) * 512 + h * 64 + tx * 4];
        float4 c0 = *p0;
        c0.x += acc[i][0].x; c0.y += acc[i][1].x; c0.z += acc[i][2].x; c0.w += acc[i][3].x;
        *p0 = c0;
        float4* p1 = (float4*)&out[((size_t)b * 512 + m + 1) * 512 + h * 64 + tx * 4];
        float4 c1 = *p1;
        c1.x += acc[i][0].y; c1.y += acc[i][1].y; c1.z += acc[i][2].y; c1.w += acc[i][3].y;
        *p1 = c1;
    }
}

// =============================================================================
extern "C" void kernel_launch(void* const* d_in, const int* in_sizes, int n_in,
                              void* d_out, int out_size)
{
    const float* hidden = (const float*)d_in[0];
    const float* heads  = (const float*)d_in[1];
    const float* rels   = (const float*)d_in[2];
    const float* Wq = (const float*)d_in[3];
    const float* bq = (const float*)d_in[4];
    const float* Wk = (const float*)d_in[5];
    const float* bk = (const float*)d_in[6];
    const float* Wv = (const float*)d_in[7];
    const float* bv = (const float*)d_in[8];
    float* out = (float*)d_out;

    dim3 g1(8, 16, 3);
    k_proj<<<g1, 256>>>(hidden, Wq, bq, Wk, bk, Wv, bv);

    dim3 g2(8, 4, 32);
    k_scores<<<g2, 256>>>();

    cudaFuncSetAttribute(k_fused, cudaFuncAttributeMaxDynamicSharedMemorySize, SMEM_FUSED);
    k_fused<<<2048, 256, SMEM_FUSED>>>(rels, heads, out);

    dim3 g4(8, 32);
    k_ctx<<<g4, 256>>>(out);
}

// round 4
// speedup vs baseline: 1.0012x; 1.0012x over previous
#include <cuda_runtime.h>
#include <cstddef>

#define B_ 4
#define L_ 512
#define HID_ 512
#define H_ 8
#define DH_ 64

// ---------------- scratch (device globals; no allocations allowed) ----------
__device__ float g_q[B_ * L_ * HID_];
__device__ float g_k[B_ * L_ * HID_];
__device__ float g_v[B_ * L_ * HID_];
__device__ float g_sc[B_ * H_ * L_ * L_];   // scores, then probs (in place)

// ---------------- packed f32x2 FMA ------------------------------------------
__device__ __forceinline__ void ffma2(float2& d, const float2 a, const float2 b) {
    asm("fma.rn.f32x2 %0, %1, %2, %0;"
        : "+l"(reinterpret_cast<unsigned long long&>(d))
        : "l"(reinterpret_cast<const unsigned long long&>(a)),
          "l"(reinterpret_cast<const unsigned long long&>(b)));
}
__device__ __forceinline__ float2 fdup(float a) { return make_float2(a, a); }

// ---------------- cp.async helpers ------------------------------------------
__device__ __forceinline__ void cp_async16(void* smem, const void* gmem) {
    unsigned s = (unsigned)__cvta_generic_to_shared(smem);
    asm volatile("cp.async.cg.shared.global [%0], [%1], 16;\n" :: "r"(s), "l"(gmem));
}
__device__ __forceinline__ void cp_commit() {
    asm volatile("cp.async.commit_group;\n");
}
template <int N>
__device__ __forceinline__ void cp_wait() {
    asm volatile("cp.async.wait_group %0;\n" :: "n"(N));
}

// =============================================================================
// K1: QKV projection (known-good R2 version).
// BM=128, BN=64, BK=16, 256 threads, micro 8x4. grid (8, 16, 3).
// =============================================================================
__global__ __launch_bounds__(256) void k_proj(
    const float* __restrict__ X,
    const float* __restrict__ Wq, const float* __restrict__ bq,
    const float* __restrict__ Wk, const float* __restrict__ bk,
    const float* __restrict__ Wv, const float* __restrict__ bv)
{
    __shared__ float As[16][132];
    __shared__ float Bs[16][68];

    const float* W; const float* bias; float* C;
    if (blockIdx.z == 0)      { W = Wq; bias = bq; C = g_q; }
    else if (blockIdx.z == 1) { W = Wk; bias = bk; C = g_k; }
    else                      { W = Wv; bias = bv; C = g_v; }

    const int m0 = blockIdx.y * 128;
    const int n0 = blockIdx.x * 64;
    const int tid = threadIdx.x;
    const int tx = tid & 15, ty = tid >> 4;
    const int lrow = tid >> 2;
    const int lf   = tid & 3;

    float2 acc[4][4];
#pragma unroll
    for (int i = 0; i < 4; i++)
#pragma unroll
        for (int j = 0; j < 4; j++) acc[i][j] = make_float2(0.f, 0.f);

    for (int k0 = 0; k0 < 512; k0 += 16) {
#pragma unroll
        for (int r = 0; r < 2; r++) {
            int row = lrow + r * 64;
            float4 a4 = *(const float4*)&X[(size_t)(m0 + row) * 512 + k0 + lf * 4];
            As[lf * 4 + 0][row] = a4.x; As[lf * 4 + 1][row] = a4.y;
            As[lf * 4 + 2][row] = a4.z; As[lf * 4 + 3][row] = a4.w;
        }
        {
            float4 b4 = *(const float4*)&W[(size_t)(n0 + lrow) * 512 + k0 + lf * 4];
            Bs[lf * 4 + 0][lrow] = b4.x; Bs[lf * 4 + 1][lrow] = b4.y;
            Bs[lf * 4 + 2][lrow] = b4.z; Bs[lf * 4 + 3][lrow] = b4.w;
        }
        __syncthreads();
#pragma unroll
        for (int kk = 0; kk < 16; kk++) {
            float4 a0 = *(const float4*)&As[kk][ty * 8];
            float4 a1 = *(const float4*)&As[kk][ty * 8 + 4];
            float4 b4 = *(const float4*)&Bs[kk][tx * 4];
            float2 a2[4] = { make_float2(a0.x, a0.y), make_float2(a0.z, a0.w),
                             make_float2(a1.x, a1.y), make_float2(a1.z, a1.w) };
            float bj[4] = { b4.x, b4.y, b4.z, b4.w };
#pragma unroll
            for (int j = 0; j < 4; j++) {
                float2 bd = fdup(bj[j]);
#pragma unroll
                for (int i = 0; i < 4; i++) ffma2(acc[i][j], a2[i], bd);
            }
        }
        __syncthreads();
    }

    float bvv[4];
#pragma unroll
    for (int j = 0; j < 4; j++) bvv[j] = bias[n0 + tx * 4 + j];

#pragma unroll
    for (int i = 0; i < 4; i++) {
        int m = m0 + ty * 8 + 2 * i;
        *(float4*)&C[(size_t)m * 512 + n0 + tx * 4] =
            make_float4(acc[i][0].x + bvv[0], acc[i][1].x + bvv[1],
                        acc[i][2].x + bvv[2], acc[i][3].x + bvv[3]);
        *(float4*)&C[(size_t)(m + 1) * 512 + n0 + tx * 4] =
            make_float4(acc[i][0].y + bvv[0], acc[i][1].y + bvv[1],
                        acc[i][2].y + bvv[2], acc[i][3].y + bvv[3]);
    }
}

// =============================================================================
// K2: scores = q . k^T per (b,h) (known-good R2 version).
// BM=128(q), BN=64(k), K=64, BK=16. grid (8, 4, 32).
// =============================================================================
__global__ __launch_bounds__(256) void k_scores()
{
    __shared__ float As[16][132];
    __shared__ float Bs[16][68];

    const int bh = blockIdx.z;
    const int b = bh >> 3, h = bh & 7;
    const int m0 = blockIdx.y * 128;
    const int n0 = blockIdx.x * 64;
    const float* A  = g_q + (size_t)b * L_ * HID_ + h * DH_;
    const float* Bm = g_k + (size_t)b * L_ * HID_ + h * DH_;
    float* C = g_sc + (size_t)bh * L_ * L_;

    const int tid = threadIdx.x;
    const int tx = tid & 15, ty = tid >> 4;
    const int lrow = tid >> 2;
    const int lf   = tid & 3;

    float2 acc[4][4];
#pragma unroll
    for (int i = 0; i < 4; i++)
#pragma unroll
        for (int j = 0; j < 4; j++) acc[i][j] = make_float2(0.f, 0.f);

    for (int k0 = 0; k0 < 64; k0 += 16) {
#pragma unroll
        for (int r = 0; r < 2; r++) {
            int row = lrow + r * 64;
            float4 a4 = *(const float4*)&A[(size_t)(m0 + row) * 512 + k0 + lf * 4];
            As[lf * 4 + 0][row] = a4.x; As[lf * 4 + 1][row] = a4.y;
            As[lf * 4 + 2][row] = a4.z; As[lf * 4 + 3][row] = a4.w;
        }
        {
            float4 b4 = *(const float4*)&Bm[(size_t)(n0 + lrow) * 512 + k0 + lf * 4];
            Bs[lf * 4 + 0][lrow] = b4.x; Bs[lf * 4 + 1][lrow] = b4.y;
            Bs[lf * 4 + 2][lrow] = b4.z; Bs[lf * 4 + 3][lrow] = b4.w;
        }
        __syncthreads();
#pragma unroll
        for (int kk = 0; kk < 16; kk++) {
            float4 a0 = *(const float4*)&As[kk][ty * 8];
            float4 a1 = *(const float4*)&As[kk][ty * 8 + 4];
            float4 b4 = *(const float4*)&Bs[kk][tx * 4];
            float2 a2[4] = { make_float2(a0.x, a0.y), make_float2(a0.z, a0.w),
                             make_float2(a1.x, a1.y), make_float2(a1.z, a1.w) };
            float bj[4] = { b4.x, b4.y, b4.z, b4.w };
#pragma unroll
            for (int j = 0; j < 4; j++) {
                float2 bd = fdup(bj[j]);
#pragma unroll
                for (int i = 0; i < 4; i++) ffma2(acc[i][j], a2[i], bd);
            }
        }
        __syncthreads();
    }

#pragma unroll
    for (int i = 0; i < 4; i++) {
        int m = m0 + ty * 8 + 2 * i;
        *(float4*)&C[(size_t)m * 512 + n0 + tx * 4] =
            make_float4(acc[i][0].x, acc[i][1].x, acc[i][2].x, acc[i][3].x);
        *(float4*)&C[(size_t)(m + 1) * 512 + n0 + tx * 4] =
            make_float4(acc[i][0].y, acc[i][1].y, acc[i][2].y, acc[i][3].y);
    }
}

// =============================================================================
// K3: fused per-(b,q), 512 THREADS (16 warps -> 4/SMSP latency hiding).
// rels XOR-swizzled in smem via 4 cp.async groups of 128 rows.
// Stage B: work item = (row-in-group, head-pair) = 512 items.
// Stage D: 4-way k-split + smem partial reduce.
// smem: rels 512x64 (128KB) + sc_s 8x516 + q_s 512 + red 1536
// =============================================================================
#define SMEM_FUSED ((512 * 64 + 8 * 516 + 512 + 1536) * 4)

__global__ __launch_bounds__(512) void k_fused(
    const float* __restrict__ rels,
    const float* __restrict__ heads,
    float* __restrict__ out)
{
    extern __shared__ float sm[];
    float4* rv   = (float4*)sm;             // 512 rows x 16 float4 (swizzled)
    float* sc_s  = sm + 512 * 64;           // 8 * 516
    float* q_s   = sc_s + 8 * 516;          // 512: q pairs
    float* red_s = q_s + 512;               // 1536: stage-D partials

    const int bq = blockIdx.x;
    const int b = bq >> 9, q = bq & 511;
    const int tid = threadIdx.x;
    const int lane = tid & 31, w = tid >> 5;

    const float* rg = rels + (size_t)bq * (512 * 64);

    float4 qv;
    if (tid < 128)
        qv = *(const float4*)&g_q[((size_t)b * L_ + q) * HID_ + tid * 4];

    // ---- issue 4 cp.async groups: group g = rels rows [128g, 128g+128) ----
#pragma unroll
    for (int g = 0; g < 4; g++) {
#pragma unroll
        for (int i = 0; i < 4; i++) {
            int flat = g * 2048 + i * 512 + tid;   // float4 index
            int row = flat >> 4, d4 = flat & 15;
            cp_async16(&rv[row * 16 + (d4 ^ (row & 15))], rg + (size_t)flat * 4);
        }
        cp_commit();
    }

    // q_pair layout: q_s[p*128 + d*2 + comp] = q[head 2p+comp][d]
    if (tid < 128) {
        int e = tid * 4;
#pragma unroll
        for (int i = 0; i < 4; i++) {
            int d = (e + i) & 63, h = (e + i) >> 6;
            float val = (i == 0) ? qv.x : (i == 1) ? qv.y : (i == 2) ? qv.z : qv.w;
            q_s[(h >> 1) * 128 + d * 2 + (h & 1)] = val;
        }
    }

    const int kl = tid >> 2;       // 0..127 row within group
    const int p  = tid & 3;        // head pair
    const size_t hoff   = ((size_t)b * 512 + q) * 512;
    const size_t scoff0 = (((size_t)(b * 8 + 2 * p)) * 512 + q) * 512;
    const size_t scoff1 = scoff0 + (size_t)512 * 512;

#define GROUP_BODY(G, NWAIT)                                                   \
    do {                                                                       \
        cp_wait<NWAIT>();                                                      \
        __syncthreads();                                                       \
        const int k = (G) * 128 + kl;                                          \
        float hv = heads[hoff + k];                                            \
        float s0 = g_sc[scoff0 + k];                                           \
        float s1 = g_sc[scoff1 + k];                                           \
        float2 aA = make_float2(0.f, 0.f), aB = aA, aC = aA, aD = aA;          \
        _Pragma("unroll")                                                      \
        for (int d4 = 0; d4 < 16; d4++) {                                      \
            float4 r4  = rv[k * 16 + (d4 ^ (k & 15))];                         \
            float4 qp0 = *(const float4*)&q_s[p * 128 + d4 * 8];               \
            float4 qp1 = *(const float4*)&q_s[p * 128 + d4 * 8 + 4];           \
            ffma2(aA, fdup(r4.x), make_float2(qp0.x, qp0.y));                  \
            ffma2(aB, fdup(r4.y), make_float2(qp0.z, qp0.w));                  \
            ffma2(aC, fdup(r4.z), make_float2(qp1.x, qp1.y));                  \
            ffma2(aD, fdup(r4.w), make_float2(qp1.z, qp1.w));                  \
        }                                                                      \
        float2 acc = make_float2(aA.x + aB.x + aC.x + aD.x,                    \
                                 aA.y + aB.y + aC.y + aD.y);                   \
        sc_s[(2 * p) * 516 + k]     = (acc.x + s0) * 0.125f + hv;              \
        sc_s[(2 * p + 1) * 516 + k] = (acc.y + s1) * 0.125f + hv;              \
    } while (0)

    GROUP_BODY(0, 3); GROUP_BODY(1, 2); GROUP_BODY(2, 1); GROUP_BODY(3, 0);
#undef GROUP_BODY
    __syncthreads();

    // ---- stage C: softmax, warps 0..7 handle head w ----
    if (w < 8) {
        float* row = sc_s + w * 516;
        float vals[16];
        float mx = -1e30f;
#pragma unroll
        for (int i = 0; i < 16; i++) { vals[i] = row[i * 32 + lane]; mx = fmaxf(mx, vals[i]); }
#pragma unroll
        for (int o = 16; o; o >>= 1) mx = fmaxf(mx, __shfl_xor_sync(0xffffffffu, mx, o));
        float s = 0.f;
#pragma unroll
        for (int i = 0; i < 16; i++) { vals[i] = __expf(vals[i] - mx); s += vals[i]; }
#pragma unroll
        for (int o = 16; o; o >>= 1) s += __shfl_xor_sync(0xffffffffu, s, o);
        float inv = 1.f / s;
        float* pg = g_sc + (((size_t)(b * 8 + w)) * 512 + q) * 512;
#pragma unroll
        for (int i = 0; i < 16; i++) {
            float pv = vals[i] * inv;
            row[i * 32 + lane] = pv;
            pg[i * 32 + lane] = pv;
        }
    }
    __syncthreads();

    // ---- stage D: rel-ctx = probs . rels, 4-way k-split ----
    {
        const int ks = tid >> 7;        // 0..3
        const int r  = tid & 127;
        const int h  = r >> 4;
        const int dq = r & 15;
        float2 c0[2] = { make_float2(0.f, 0.f), make_float2(0.f, 0.f) };
        float2 c1[2] = { make_float2(0.f, 0.f), make_float2(0.f, 0.f) };
        const float* prow = sc_s + h * 516;
        const int kbeg = ks * 128;
#pragma unroll 8
        for (int k = kbeg; k < kbeg + 128; k += 4) {
            float4 p4 = *(const float4*)&prow[k];
            float pj[4] = { p4.x, p4.y, p4.z, p4.w };
#pragma unroll
            for (int j = 0; j < 4; j++) {
                float4 r4 = rv[(k + j) * 16 + (dq ^ ((k + j) & 15))];
                float2 pd = fdup(pj[j]);
                ffma2(c0[j & 1], pd, make_float2(r4.x, r4.y));
                ffma2(c1[j & 1], pd, make_float2(r4.z, r4.w));
            }
        }
        float2 c0f = make_float2(c0[0].x + c0[1].x, c0[0].y + c0[1].y);
        float2 c1f = make_float2(c1[0].x + c1[1].x, c1[0].y + c1[1].y);
        if (ks > 0) {
            *(float4*)&red_s[(ks - 1) * 512 + r * 4] =
                make_float4(c0f.x, c0f.y, c1f.x, c1f.y);
        }
        __syncthreads();
        if (ks == 0) {
            float4 t0 = *(const float4*)&red_s[r * 4];
            float4 t1 = *(const float4*)&red_s[512 + r * 4];
            float4 t2 = *(const float4*)&red_s[1024 + r * 4];
            float4 o = make_float4(c0f.x + t0.x + t1.x + t2.x,
                                   c0f.y + t0.y + t1.y + t2.y,
                                   c1f.x + t0.z + t1.z + t2.z,
                                   c1f.y + t0.w + t1.w + t2.w);
            *(float4*)&out[(size_t)bq * 512 + h * 64 + dq * 4] = o;
        }
    }
}

// =============================================================================
// K4: ctx += probs @ v per (b,h), k-split x2, atomicAdd epilogue.
// BM=64, BN=64, BK=16, double-buffered. grid (8, 32, 2) = 512 CTAs.
// =============================================================================
__global__ __launch_bounds__(256) void k_ctx(float* __restrict__ out)
{
    __shared__ float As[2][16][68];
    __shared__ float Bs[2][16][68];

    const int bh = blockIdx.y;
    const int b = bh >> 3, h = bh & 7;
    const int m0 = blockIdx.x * 64;
    const int kbase = blockIdx.z * 256;
    const float* P = g_sc + (size_t)bh * L_ * L_;
    const float* V = g_v + (size_t)b * L_ * HID_ + h * DH_;

    const int tid = threadIdx.x;
    const int tx = tid & 15, ty = tid >> 4;
    const int lrow = tid >> 2;
    const int lf   = tid & 3;
    const int vrow = tid >> 4;
    const int vc   = tid & 15;

    float2 acc[2][4];
#pragma unroll
    for (int i = 0; i < 2; i++)
#pragma unroll
        for (int j = 0; j < 4; j++) acc[i][j] = make_float2(0.f, 0.f);

    float4 a4r = *(const float4*)&P[(size_t)(m0 + lrow) * 512 + kbase + lf * 4];
    float4 b4r = *(const float4*)&V[(size_t)(kbase + vrow) * 512 + vc * 4];

#pragma unroll 1
    for (int t = 0; t < 16; t++) {
        const int cur = t & 1;
        As[cur][lf * 4 + 0][lrow] = a4r.x; As[cur][lf * 4 + 1][lrow] = a4r.y;
        As[cur][lf * 4 + 2][lrow] = a4r.z; As[cur][lf * 4 + 3][lrow] = a4r.w;
        *(float4*)&Bs[cur][vrow][vc * 4] = b4r;
        __syncthreads();

        if (t < 15) {
            int k0 = kbase + (t + 1) * 16;
            a4r = *(const float4*)&P[(size_t)(m0 + lrow) * 512 + k0 + lf * 4];
            b4r = *(const float4*)&V[(size_t)(k0 + vrow) * 512 + vc * 4];
        }

#pragma unroll
        for (int kk = 0; kk < 16; kk++) {
            float4 a4 = *(const float4*)&As[cur][kk][ty * 4];
            float4 b4 = *(const float4*)&Bs[cur][kk][tx * 4];
            float2 a2[2] = { make_float2(a4.x, a4.y), make_float2(a4.z, a4.w) };
            float bj[4] = { b4.x, b4.y, b4.z, b4.w };
#pragma unroll
            for (int j = 0; j < 4; j++) {
                float2 bd = fdup(bj[j]);
#pragma unroll
                for (int i = 0; i < 2; i++) ffma2(acc[i][j], a2[i], bd);
            }
        }
        if (t < 15) __syncthreads();
    }

#pragma unroll
    for (int i = 0; i < 2; i++) {
        int m = m0 + ty * 4 + 2 * i;
        float* p0 = &out[((size_t)b * 512 + m) * 512 + h * 64 + tx * 4];
        atomicAdd(p0 + 0, acc[i][0].x);
        atomicAdd(p0 + 1, acc[i][1].x);
        atomicAdd(p0 + 2, acc[i][2].x);
        atomicAdd(p0 + 3, acc[i][3].x);
        float* p1 = &out[((size_t)b * 512 + m + 1) * 512 + h * 64 + tx * 4];
        atomicAdd(p1 + 0, acc[i][0].y);
        atomicAdd(p1 + 1, acc[i][1].y);
        atomicAdd(p1 + 2, acc[i][2].y);
        atomicAdd(p1 + 3, acc[i][3].y);
    }
}

// =============================================================================
extern "C" void kernel_launch(void* const* d_in, const int* in_sizes, int n_in,
                              void* d_out, int out_size)
{
    const float* hidden = (const float*)d_in[0];
    const float* heads  = (const float*)d_in[1];
    const float* rels   = (const float*)d_in[2];
    const float* Wq = (const float*)d_in[3];
    const float* bq = (const float*)d_in[4];
    const float* Wk = (const float*)d_in[5];
    const float* bk = (const float*)d_in[6];
    const float* Wv = (const float*)d_in[7];
    const float* bv = (const float*)d_in[8];
    float* out = (float*)d_out;

    dim3 g1(8, 16, 3);
    k_proj<<<g1, 256>>>(hidden, Wq, bq, Wk, bk, Wv, bv);

    dim3 g2(8, 4, 32);
    k_scores<<<g2, 256>>>();

    cudaFuncSetAttribute(k_fused, cudaFuncAttributeMaxDynamicSharedMemorySize, SMEM_FUSED);
    k_fused<<<2048, 512, SMEM_FUSED>>>(rels, heads, out);

    dim3 g4(8, 32, 2);
    k_ctx<<<g4, 256>>>(out);
}

// round 5
// speedup vs baseline: 1.1458x; 1.1444x over previous
#include <cuda_runtime.h>
#include <cstddef>

#define B_ 4
#define L_ 512
#define HID_ 512
#define H_ 8
#define DH_ 64

// ---------------- scratch (device globals; no allocations allowed) ----------
__device__ float g_q[B_ * L_ * HID_];
__device__ float g_k[B_ * L_ * HID_];
__device__ float g_v[B_ * L_ * HID_];
__device__ float g_sc[B_ * H_ * L_ * L_];   // scores, then probs (in place)

// ---------------- packed f32x2 FMA ------------------------------------------
__device__ __forceinline__ void ffma2(float2& d, const float2 a, const float2 b) {
    asm("fma.rn.f32x2 %0, %1, %2, %0;"
        : "+l"(reinterpret_cast<unsigned long long&>(d))
        : "l"(reinterpret_cast<const unsigned long long&>(a)),
          "l"(reinterpret_cast<const unsigned long long&>(b)));
}
__device__ __forceinline__ float2 fdup(float a) { return make_float2(a, a); }

// ---------------- cp.async helpers ------------------------------------------
__device__ __forceinline__ void cp_async16(void* smem, const void* gmem) {
    unsigned s = (unsigned)__cvta_generic_to_shared(smem);
    asm volatile("cp.async.cg.shared.global [%0], [%1], 16;\n" :: "r"(s), "l"(gmem));
}
__device__ __forceinline__ void cp_commit() {
    asm volatile("cp.async.commit_group;\n");
}
template <int N>
__device__ __forceinline__ void cp_wait() {
    asm volatile("cp.async.wait_group %0;\n" :: "n"(N));
}

// =============================================================================
// K1: QKV projection (exact 391us version).
// BM=128, BN=64, BK=16, 256 threads, micro 8x4. grid (8, 16, 3).
// =============================================================================
__global__ __launch_bounds__(256) void k_proj(
    const float* __restrict__ X,
    const float* __restrict__ Wq, const float* __restrict__ bq,
    const float* __restrict__ Wk, const float* __restrict__ bk,
    const float* __restrict__ Wv, const float* __restrict__ bv)
{
    __shared__ float As[16][132];
    __shared__ float Bs[16][68];

    const float* W; const float* bias; float* C;
    if (blockIdx.z == 0)      { W = Wq; bias = bq; C = g_q; }
    else if (blockIdx.z == 1) { W = Wk; bias = bk; C = g_k; }
    else                      { W = Wv; bias = bv; C = g_v; }

    const int m0 = blockIdx.y * 128;
    const int n0 = blockIdx.x * 64;
    const int tid = threadIdx.x;
    const int tx = tid & 15, ty = tid >> 4;
    const int lrow = tid >> 2;
    const int lf   = tid & 3;

    float2 acc[4][4];
#pragma unroll
    for (int i = 0; i < 4; i++)
#pragma unroll
        for (int j = 0; j < 4; j++) acc[i][j] = make_float2(0.f, 0.f);

    for (int k0 = 0; k0 < 512; k0 += 16) {
#pragma unroll
        for (int r = 0; r < 2; r++) {
            int row = lrow + r * 64;
            float4 a4 = *(const float4*)&X[(size_t)(m0 + row) * 512 + k0 + lf * 4];
            As[lf * 4 + 0][row] = a4.x; As[lf * 4 + 1][row] = a4.y;
            As[lf * 4 + 2][row] = a4.z; As[lf * 4 + 3][row] = a4.w;
        }
        {
            float4 b4 = *(const float4*)&W[(size_t)(n0 + lrow) * 512 + k0 + lf * 4];
            Bs[lf * 4 + 0][lrow] = b4.x; Bs[lf * 4 + 1][lrow] = b4.y;
            Bs[lf * 4 + 2][lrow] = b4.z; Bs[lf * 4 + 3][lrow] = b4.w;
        }
        __syncthreads();
#pragma unroll
        for (int kk = 0; kk < 16; kk++) {
            float4 a0 = *(const float4*)&As[kk][ty * 8];
            float4 a1 = *(const float4*)&As[kk][ty * 8 + 4];
            float4 b4 = *(const float4*)&Bs[kk][tx * 4];
            float2 a2[4] = { make_float2(a0.x, a0.y), make_float2(a0.z, a0.w),
                             make_float2(a1.x, a1.y), make_float2(a1.z, a1.w) };
            float bj[4] = { b4.x, b4.y, b4.z, b4.w };
#pragma unroll
            for (int j = 0; j < 4; j++) {
                float2 bd = fdup(bj[j]);
#pragma unroll
                for (int i = 0; i < 4; i++) ffma2(acc[i][j], a2[i], bd);
            }
        }
        __syncthreads();
    }

    float bvv[4];
#pragma unroll
    for (int j = 0; j < 4; j++) bvv[j] = bias[n0 + tx * 4 + j];

#pragma unroll
    for (int i = 0; i < 4; i++) {
        int m = m0 + ty * 8 + 2 * i;
        *(float4*)&C[(size_t)m * 512 + n0 + tx * 4] =
            make_float4(acc[i][0].x + bvv[0], acc[i][1].x + bvv[1],
                        acc[i][2].x + bvv[2], acc[i][3].x + bvv[3]);
        *(float4*)&C[(size_t)(m + 1) * 512 + n0 + tx * 4] =
            make_float4(acc[i][0].y + bvv[0], acc[i][1].y + bvv[1],
                        acc[i][2].y + bvv[2], acc[i][3].y + bvv[3]);
    }
}

// =============================================================================
// K2: scores = q . k^T per (b,h) (exact 391us version).
// BM=128(q), BN=64(k), K=64, BK=16. grid (8, 4, 32).
// =============================================================================
__global__ __launch_bounds__(256) void k_scores()
{
    __shared__ float As[16][132];
    __shared__ float Bs[16][68];

    const int bh = blockIdx.z;
    const int b = bh >> 3, h = bh & 7;
    const int m0 = blockIdx.y * 128;
    const int n0 = blockIdx.x * 64;
    const float* A  = g_q + (size_t)b * L_ * HID_ + h * DH_;
    const float* Bm = g_k + (size_t)b * L_ * HID_ + h * DH_;
    float* C = g_sc + (size_t)bh * L_ * L_;

    const int tid = threadIdx.x;
    const int tx = tid & 15, ty = tid >> 4;
    const int lrow = tid >> 2;
    const int lf   = tid & 3;

    float2 acc[4][4];
#pragma unroll
    for (int i = 0; i < 4; i++)
#pragma unroll
        for (int j = 0; j < 4; j++) acc[i][j] = make_float2(0.f, 0.f);

    for (int k0 = 0; k0 < 64; k0 += 16) {
#pragma unroll
        for (int r = 0; r < 2; r++) {
            int row = lrow + r * 64;
            float4 a4 = *(const float4*)&A[(size_t)(m0 + row) * 512 + k0 + lf * 4];
            As[lf * 4 + 0][row] = a4.x; As[lf * 4 + 1][row] = a4.y;
            As[lf * 4 + 2][row] = a4.z; As[lf * 4 + 3][row] = a4.w;
        }
        {
            float4 b4 = *(const float4*)&Bm[(size_t)(n0 + lrow) * 512 + k0 + lf * 4];
            Bs[lf * 4 + 0][lrow] = b4.x; Bs[lf * 4 + 1][lrow] = b4.y;
            Bs[lf * 4 + 2][lrow] = b4.z; Bs[lf * 4 + 3][lrow] = b4.w;
        }
        __syncthreads();
#pragma unroll
        for (int kk = 0; kk < 16; kk++) {
            float4 a0 = *(const float4*)&As[kk][ty * 8];
            float4 a1 = *(const float4*)&As[kk][ty * 8 + 4];
            float4 b4 = *(const float4*)&Bs[kk][tx * 4];
            float2 a2[4] = { make_float2(a0.x, a0.y), make_float2(a0.z, a0.w),
                             make_float2(a1.x, a1.y), make_float2(a1.z, a1.w) };
            float bj[4] = { b4.x, b4.y, b4.z, b4.w };
#pragma unroll
            for (int j = 0; j < 4; j++) {
                float2 bd = fdup(bj[j]);
#pragma unroll
                for (int i = 0; i < 4; i++) ffma2(acc[i][j], a2[i], bd);
            }
        }
        __syncthreads();
    }

#pragma unroll
    for (int i = 0; i < 4; i++) {
        int m = m0 + ty * 8 + 2 * i;
        *(float4*)&C[(size_t)m * 512 + n0 + tx * 4] =
            make_float4(acc[i][0].x, acc[i][1].x, acc[i][2].x, acc[i][3].x);
        *(float4*)&C[(size_t)(m + 1) * 512 + n0 + tx * 4] =
            make_float4(acc[i][0].y, acc[i][1].y, acc[i][2].y, acc[i][3].y);
    }
}

// =============================================================================
// K3: fused per-(b,q) — 391us version + ONLY a 2-accumulator chain split.
// Conflict-free q layout q_s[d*8+h] kept.  256 threads, 8 cp.async groups.
// smem: rels 512x64 (swizzled, 128KB), sc_s[8][516], q_s[512]
// =============================================================================
#define SMEM_FUSED ((512 * 64 + 8 * 516 + 512) * 4)

__global__ __launch_bounds__(256) void k_fused(
    const float* __restrict__ rels,
    const float* __restrict__ heads,
    float* __restrict__ out)
{
    extern __shared__ float sm[];
    float4* rv  = (float4*)sm;          // 512 rows x 16 float4 (swizzled)
    float* sc_s = sm + 512 * 64;        // 8 * 516
    float* q_s  = sc_s + 8 * 516;       // 512 (q transposed; later reduce buf)

    const int bq = blockIdx.x;
    const int b = bq >> 9, q = bq & 511;
    const int tid = threadIdx.x;
    const int lane = tid & 31, w = tid >> 5;

    const float* rg = rels + (size_t)bq * (512 * 64);

    float4 qv;
    if (tid < 128)
        qv = *(const float4*)&g_q[((size_t)b * L_ + q) * HID_ + tid * 4];

    // ---- issue 8 cp.async groups: group g = rels rows [64g, 64g+64) ----
#pragma unroll
    for (int g = 0; g < 8; g++) {
#pragma unroll
        for (int i = 0; i < 4; i++) {
            int flat = g * 1024 + i * 256 + tid;   // float4 index
            int row = flat >> 4, d4 = flat & 15;
            cp_async16(&rv[row * 16 + (d4 ^ (row & 15))], rg + (size_t)flat * 4);
        }
        cp_commit();
    }

    // q layout: q_s[d*8 + h]  (conflict-free in stage B)
    if (tid < 128) {
        int e = tid * 4;
        q_s[((e + 0) & 63) * 8 + ((e + 0) >> 6)] = qv.x;
        q_s[((e + 1) & 63) * 8 + ((e + 1) >> 6)] = qv.y;
        q_s[((e + 2) & 63) * 8 + ((e + 2) >> 6)] = qv.z;
        q_s[((e + 3) & 63) * 8 + ((e + 3) >> 6)] = qv.w;
    }

    // ---- stage B per group: thread -> (k = g*64 + tid>>2, head pair tid&3)
    const int kl = tid >> 2;
    const int p  = tid & 3;
    const size_t hoff   = ((size_t)b * 512 + q) * 512;
    const size_t scoff0 = (((size_t)(b * 8 + 2 * p)) * 512 + q) * 512;
    const size_t scoff1 = scoff0 + (size_t)512 * 512;

#define GROUP_BODY(G, NWAIT)                                                   \
    do {                                                                       \
        cp_wait<NWAIT>();                                                      \
        __syncthreads();                                                       \
        const int k = (G) * 64 + kl;                                           \
        float2 aE = make_float2(0.f, 0.f), aO = make_float2(0.f, 0.f);         \
        _Pragma("unroll")                                                      \
        for (int d4 = 0; d4 < 16; d4++) {                                      \
            float4 r4 = rv[k * 16 + (d4 ^ (k & 15))];                          \
            ffma2(aE, fdup(r4.x), *(const float2*)&q_s[(d4 * 4 + 0) * 8 + 2 * p]); \
            ffma2(aO, fdup(r4.y), *(const float2*)&q_s[(d4 * 4 + 1) * 8 + 2 * p]); \
            ffma2(aE, fdup(r4.z), *(const float2*)&q_s[(d4 * 4 + 2) * 8 + 2 * p]); \
            ffma2(aO, fdup(r4.w), *(const float2*)&q_s[(d4 * 4 + 3) * 8 + 2 * p]); \
        }                                                                      \
        float2 acc = make_float2(aE.x + aO.x, aE.y + aO.y);                    \
        float hv = heads[hoff + k];                                            \
        float s0 = g_sc[scoff0 + k];                                           \
        float s1 = g_sc[scoff1 + k];                                           \
        sc_s[(2 * p) * 516 + k]     = (acc.x + s0) * 0.125f + hv;              \
        sc_s[(2 * p + 1) * 516 + k] = (acc.y + s1) * 0.125f + hv;              \
    } while (0)

    GROUP_BODY(0, 7); GROUP_BODY(1, 6); GROUP_BODY(2, 5); GROUP_BODY(3, 4);
    GROUP_BODY(4, 3); GROUP_BODY(5, 2); GROUP_BODY(6, 1); GROUP_BODY(7, 0);
#undef GROUP_BODY
    __syncthreads();

    // ---- stage C: softmax, warp w == head w ----
    {
        float* row = sc_s + w * 516;
        float vals[16];
        float mx = -1e30f;
#pragma unroll
        for (int i = 0; i < 16; i++) { vals[i] = row[i * 32 + lane]; mx = fmaxf(mx, vals[i]); }
#pragma unroll
        for (int o = 16; o; o >>= 1) mx = fmaxf(mx, __shfl_xor_sync(0xffffffffu, mx, o));
        float s = 0.f;
#pragma unroll
        for (int i = 0; i < 16; i++) { vals[i] = __expf(vals[i] - mx); s += vals[i]; }
#pragma unroll
        for (int o = 16; o; o >>= 1) s += __shfl_xor_sync(0xffffffffu, s, o);
        float inv = 1.f / s;
        float* pg = g_sc + (((size_t)(b * 8 + w)) * 512 + q) * 512;
#pragma unroll
        for (int i = 0; i < 16; i++) {
            float pv = vals[i] * inv;
            row[i * 32 + lane] = pv;
            pg[i * 32 + lane] = pv;
        }
    }
    __syncthreads();

    // ---- stage D: rel-ctx = probs . rels (k-split by 2, j-parity accs) ----
    {
        const int ks = tid >> 7;
        const int r  = tid & 127;
        const int h  = r >> 4;
        const int dq = r & 15;          // float4 column
        float2 c0[2] = { make_float2(0.f, 0.f), make_float2(0.f, 0.f) };
        float2 c1[2] = { make_float2(0.f, 0.f), make_float2(0.f, 0.f) };
        const float* prow = sc_s + h * 516;
        const int kbeg = ks * 256;
#pragma unroll 8
        for (int k = kbeg; k < kbeg + 256; k += 4) {
            float4 p4 = *(const float4*)&prow[k];
            float pj[4] = { p4.x, p4.y, p4.z, p4.w };
#pragma unroll
            for (int j = 0; j < 4; j++) {
                float4 r4 = rv[(k + j) * 16 + (dq ^ ((k + j) & 15))];
                float2 pd = fdup(pj[j]);
                ffma2(c0[j & 1], pd, make_float2(r4.x, r4.y));
                ffma2(c1[j & 1], pd, make_float2(r4.z, r4.w));
            }
        }
        float2 c0f = make_float2(c0[0].x + c0[1].x, c0[0].y + c0[1].y);
        float2 c1f = make_float2(c1[0].x + c1[1].x, c1[0].y + c1[1].y);
        if (ks == 1) {
            *(float4*)&q_s[r * 4] = make_float4(c0f.x, c0f.y, c1f.x, c1f.y);
        }
        __syncthreads();
        if (ks == 0) {
            float4 t = *(const float4*)&q_s[r * 4];
            float4 o = make_float4(c0f.x + t.x, c0f.y + t.y, c1f.x + t.z, c1f.y + t.w);
            *(float4*)&out[(size_t)bq * 512 + h * 64 + dq * 4] = o;
        }
    }
}

// =============================================================================
// K4: ctx += probs @ v per (b,h), k-split x2, atomicAdd epilogue (R4, 40us).
// BM=64, BN=64, BK=16, double-buffered. grid (8, 32, 2) = 512 CTAs.
// =============================================================================
__global__ __launch_bounds__(256) void k_ctx(float* __restrict__ out)
{
    __shared__ float As[2][16][68];
    __shared__ float Bs[2][16][68];

    const int bh = blockIdx.y;
    const int b = bh >> 3, h = bh & 7;
    const int m0 = blockIdx.x * 64;
    const int kbase = blockIdx.z * 256;
    const float* P = g_sc + (size_t)bh * L_ * L_;
    const float* V = g_v + (size_t)b * L_ * HID_ + h * DH_;

    const int tid = threadIdx.x;
    const int tx = tid & 15, ty = tid >> 4;
    const int lrow = tid >> 2;
    const int lf   = tid & 3;
    const int vrow = tid >> 4;
    const int vc   = tid & 15;

    float2 acc[2][4];
#pragma unroll
    for (int i = 0; i < 2; i++)
#pragma unroll
        for (int j = 0; j < 4; j++) acc[i][j] = make_float2(0.f, 0.f);

    float4 a4r = *(const float4*)&P[(size_t)(m0 + lrow) * 512 + kbase + lf * 4];
    float4 b4r = *(const float4*)&V[(size_t)(kbase + vrow) * 512 + vc * 4];

#pragma unroll 1
    for (int t = 0; t < 16; t++) {
        const int cur = t & 1;
        As[cur][lf * 4 + 0][lrow] = a4r.x; As[cur][lf * 4 + 1][lrow] = a4r.y;
        As[cur][lf * 4 + 2][lrow] = a4r.z; As[cur][lf * 4 + 3][lrow] = a4r.w;
        *(float4*)&Bs[cur][vrow][vc * 4] = b4r;
        __syncthreads();

        if (t < 15) {
            int k0 = kbase + (t + 1) * 16;
            a4r = *(const float4*)&P[(size_t)(m0 + lrow) * 512 + k0 + lf * 4];
            b4r = *(const float4*)&V[(size_t)(k0 + vrow) * 512 + vc * 4];
        }

#pragma unroll
        for (int kk = 0; kk < 16; kk++) {
            float4 a4 = *(const float4*)&As[cur][kk][ty * 4];
            float4 b4 = *(const float4*)&Bs[cur][kk][tx * 4];
            float2 a2[2] = { make_float2(a4.x, a4.y), make_float2(a4.z, a4.w) };
            float bj[4] = { b4.x, b4.y, b4.z, b4.w };
#pragma unroll
            for (int j = 0; j < 4; j++) {
                float2 bd = fdup(bj[j]);
#pragma unroll
                for (int i = 0; i < 2; i++) ffma2(acc[i][j], a2[i], bd);
            }
        }
        if (t < 15) __syncthreads();
    }

#pragma unroll
    for (int i = 0; i < 2; i++) {
        int m = m0 + ty * 4 + 2 * i;
        float* p0 = &out[((size_t)b * 512 + m) * 512 + h * 64 + tx * 4];
        atomicAdd(p0 + 0, acc[i][0].x);
        atomicAdd(p0 + 1, acc[i][1].x);
        atomicAdd(p0 + 2, acc[i][2].x);
        atomicAdd(p0 + 3, acc[i][3].x);
        float* p1 = &out[((size_t)b * 512 + m + 1) * 512 + h * 64 + tx * 4];
        atomicAdd(p1 + 0, acc[i][0].y);
        atomicAdd(p1 + 1, acc[i][1].y);
        atomicAdd(p1 + 2, acc[i][2].y);
        atomicAdd(p1 + 3, acc[i][3].y);
    }
}

// =============================================================================
extern "C" void kernel_launch(void* const* d_in, const int* in_sizes, int n_in,
                              void* d_out, int out_size)
{
    const float* hidden = (const float*)d_in[0];
    const float* heads  = (const float*)d_in[1];
    const float* rels   = (const float*)d_in[2];
    const float* Wq = (const float*)d_in[3];
    const float* bq = (const float*)d_in[4];
    const float* Wk = (const float*)d_in[5];
    const float* bk = (const float*)d_in[6];
    const float* Wv = (const float*)d_in[7];
    const float* bv = (const float*)d_in[8];
    float* out = (float*)d_out;

    dim3 g1(8, 16, 3);
    k_proj<<<g1, 256>>>(hidden, Wq, bq, Wk, bk, Wv, bv);

    dim3 g2(8, 4, 32);
    k_scores<<<g2, 256>>>();

    cudaFuncSetAttribute(k_fused, cudaFuncAttributeMaxDynamicSharedMemorySize, SMEM_FUSED);
    k_fused<<<2048, 256, SMEM_FUSED>>>(rels, heads, out);

    dim3 g4(8, 32, 2);
    k_ctx<<<g4, 256>>>(out);
}

// round 7
// speedup vs baseline: 1.3823x; 1.2065x over previous
#include <cuda_runtime.h>
#include <cuda_bf16.h>
#include <cstdint>
#include <cstddef>

#define B_ 4
#define L_ 512
#define HID_ 512
#define H_ 8
#define DH_ 64

// ---------------- scratch (device globals; no allocations allowed) ----------
__device__ float g_q[B_ * L_ * HID_];
__device__ float g_k[B_ * L_ * HID_];
__device__ float g_v[B_ * L_ * HID_];
__device__ float g_sc[B_ * H_ * L_ * L_];           // scores, then probs
// split-precision operands, K = 1536: A = [xh | xl | xh], B = [wh | wh | wl]
__device__ __nv_bfloat16 g_Xs[2048 * 1536];
__device__ __nv_bfloat16 g_Ws[3 * 512 * 1536];

// ---------------- packed f32x2 FMA ------------------------------------------
__device__ __forceinline__ void ffma2(float2& d, const float2 a, const float2 b) {
    asm("fma.rn.f32x2 %0, %1, %2, %0;"
        : "+l"(reinterpret_cast<unsigned long long&>(d))
        : "l"(reinterpret_cast<const unsigned long long&>(a)),
          "l"(reinterpret_cast<const unsigned long long&>(b)));
}
__device__ __forceinline__ float2 fdup(float a) { return make_float2(a, a); }

// ---------------- cp.async helpers ------------------------------------------
__device__ __forceinline__ void cp_async16(void* smem, const void* gmem) {
    unsigned s = (unsigned)__cvta_generic_to_shared(smem);
    asm volatile("cp.async.cg.shared.global [%0], [%1], 16;\n" :: "r"(s), "l"(gmem));
}
__device__ __forceinline__ void cp_commit() {
    asm volatile("cp.async.commit_group;\n");
}
template <int N>
__device__ __forceinline__ void cp_wait() {
    asm volatile("cp.async.wait_group %0;\n" :: "n"(N));
}

// ---------------- warp mma (sm_80+ HMMA, no 'a' feature needed) --------------
__device__ __forceinline__ void mma_bf16(float& c0, float& c1, float& c2, float& c3,
                                         uint32_t a0, uint32_t a1, uint32_t a2, uint32_t a3,
                                         uint32_t b0, uint32_t b1) {
    asm volatile(
        "mma.sync.aligned.m16n8k16.row.col.f32.bf16.bf16.f32 "
        "{%0,%1,%2,%3}, {%4,%5,%6,%7}, {%8,%9}, {%0,%1,%2,%3};"
        : "+f"(c0), "+f"(c1), "+f"(c2), "+f"(c3)
        : "r"(a0), "r"(a1), "r"(a2), "r"(a3), "r"(b0), "r"(b1));
}

// =============================================================================
// K0: build split-bf16 operands, K=1536.
//   g_Xs[m][0:512)=xh, [512:1024)=xl, [1024:1536)=xh
//   g_Ws[z][n][0:512)=wh, [512:1024)=wh, [1024:1536)=wl
// =============================================================================
__global__ __launch_bounds__(256) void k_prep(
    const float* __restrict__ X,
    const float* __restrict__ Wq, const float* __restrict__ Wk,
    const float* __restrict__ Wv)
{
    const int stride = gridDim.x * blockDim.x;
    for (int i = blockIdx.x * blockDim.x + threadIdx.x; i < 2048 * 512; i += stride) {
        int m = i >> 9, k = i & 511;
        float x = X[i];
        __nv_bfloat16 hi = __float2bfloat16(x);
        __nv_bfloat16 lo = __float2bfloat16(x - __bfloat162float(hi));
        __nv_bfloat16* row = g_Xs + (size_t)m * 1536;
        row[k] = hi; row[512 + k] = lo; row[1024 + k] = hi;
    }
    for (int i = blockIdx.x * blockDim.x + threadIdx.x; i < 3 * 512 * 512; i += stride) {
        int z = i >> 18;
        int r = i & 262143;
        const float* W = (z == 0) ? Wq : (z == 1) ? Wk : Wv;
        int n = r >> 9, k = r & 511;
        float x = W[r];
        __nv_bfloat16 hi = __float2bfloat16(x);
        __nv_bfloat16 lo = __float2bfloat16(x - __bfloat162float(hi));
        __nv_bfloat16* row = g_Ws + (size_t)z * 512 * 1536 + (size_t)n * 1536;
        row[k] = hi; row[512 + k] = hi; row[1024 + k] = lo;
    }
}

// =============================================================================
// K1: QKV projection via mma.sync bf16.  C = Xs @ Ws^T + bias.
// BM=128, BN=64, BK=64, K=1536 (24 iters), 256 threads = 8 warps (4m x 2n),
// warp tile 32x32 (2x4 m16n8k16), cp.async double-buffered, pad-72 smem.
// grid (8, 16, 3) = 384 CTAs.
// =============================================================================
#define PADK 72
#define A_BUF_ELE (128 * PADK)
#define B_BUF_ELE (64 * PADK)
#define SMEM_PROJ ((2 * A_BUF_ELE + 2 * B_BUF_ELE) * 2 + 64 * 4)

__global__ __launch_bounds__(256) void k_proj_mma(
    const float* __restrict__ bq, const float* __restrict__ bk,
    const float* __restrict__ bv)
{
    extern __shared__ char smp[];
    __nv_bfloat16* As = (__nv_bfloat16*)smp;                       // 2 bufs
    __nv_bfloat16* Bs = As + 2 * A_BUF_ELE;                        // 2 bufs
    float* biasS = (float*)(Bs + 2 * B_BUF_ELE);

    const int n0 = blockIdx.x * 64;
    const int m0 = blockIdx.y * 128;
    const int z  = blockIdx.z;
    const float* bias = (z == 0) ? bq : (z == 1) ? bk : bv;
    float* C = (z == 0) ? g_q : (z == 1) ? g_k : g_v;
    const __nv_bfloat16* Wz = g_Ws + (size_t)z * 512 * 1536;

    const int tid = threadIdx.x;
    const int wid = tid >> 5, lane = tid & 31;
    const int wm = wid >> 1, wn = wid & 1;
    const int g  = lane >> 2, tg = lane & 3;

    if (tid < 64) biasS[tid] = bias[n0 + tid];

    float acc[2][4][4];
#pragma unroll
    for (int mt = 0; mt < 2; mt++)
#pragma unroll
        for (int nt = 0; nt < 4; nt++)
#pragma unroll
            for (int e = 0; e < 4; e++) acc[mt][nt][e] = 0.f;

    auto load_chunk = [&](int c, int buf) {
        __nv_bfloat16* Ad = As + buf * A_BUF_ELE;
        __nv_bfloat16* Bd = Bs + buf * B_BUF_ELE;
#pragma unroll
        for (int i = 0; i < 4; i++) {                 // A: 128 rows x 8 segs
            int flat = i * 256 + tid;
            int row = flat >> 3, seg = flat & 7;
            cp_async16(Ad + row * PADK + seg * 8,
                       g_Xs + (size_t)(m0 + row) * 1536 + c * 64 + seg * 8);
        }
#pragma unroll
        for (int i = 0; i < 2; i++) {                 // B: 64 rows x 8 segs
            int flat = i * 256 + tid;
            int row = flat >> 3, seg = flat & 7;
            cp_async16(Bd + row * PADK + seg * 8,
                       Wz + (size_t)(n0 + row) * 1536 + c * 64 + seg * 8);
        }
        cp_commit();
    };

    load_chunk(0, 0);

#pragma unroll 1
    for (int t = 0; t < 24; t++) {
        if (t < 23) load_chunk(t + 1, (t + 1) & 1);
        if (t < 23) cp_wait<1>(); else cp_wait<0>();
        __syncthreads();

        const __nv_bfloat16* Ab = As + (t & 1) * A_BUF_ELE;
        const __nv_bfloat16* Bb = Bs + (t & 1) * B_BUF_ELE;

#pragma unroll
        for (int ks = 0; ks < 4; ks++) {
            const int kb = ks * 16;
            uint32_t af[2][4], bf[4][2];
#pragma unroll
            for (int mt = 0; mt < 2; mt++) {
                int r0 = wm * 32 + mt * 16 + g;
                af[mt][0] = *(const uint32_t*)&Ab[(r0)      * PADK + kb + tg * 2];
                af[mt][1] = *(const uint32_t*)&Ab[(r0 + 8)  * PADK + kb + tg * 2];
                af[mt][2] = *(const uint32_t*)&Ab[(r0)      * PADK + kb + tg * 2 + 8];
                af[mt][3] = *(const uint32_t*)&Ab[(r0 + 8)  * PADK + kb + tg * 2 + 8];
            }
#pragma unroll
            for (int nt = 0; nt < 4; nt++) {
                int nr = wn * 32 + nt * 8 + g;
                bf[nt][0] = *(const uint32_t*)&Bb[nr * PADK + kb + tg * 2];
                bf[nt][1] = *(const uint32_t*)&Bb[nr * PADK + kb + tg * 2 + 8];
            }
#pragma unroll
            for (int mt = 0; mt < 2; mt++)
#pragma unroll
                for (int nt = 0; nt < 4; nt++)
                    mma_bf16(acc[mt][nt][0], acc[mt][nt][1], acc[mt][nt][2], acc[mt][nt][3],
                             af[mt][0], af[mt][1], af[mt][2], af[mt][3],
                             bf[nt][0], bf[nt][1]);
        }
        __syncthreads();
    }

    // epilogue: c0,c1 = row g, cols tg*2,tg*2+1 ; c2,c3 = row g+8
#pragma unroll
    for (int mt = 0; mt < 2; mt++) {
        int r0 = m0 + wm * 32 + mt * 16 + g;
#pragma unroll
        for (int nt = 0; nt < 4; nt++) {
            int cl = wn * 32 + nt * 8 + tg * 2;       // local col in [0,64)
            float2 v0 = make_float2(acc[mt][nt][0] + biasS[cl],
                                    acc[mt][nt][1] + biasS[cl + 1]);
            float2 v1 = make_float2(acc[mt][nt][2] + biasS[cl],
                                    acc[mt][nt][3] + biasS[cl + 1]);
            *(float2*)&C[(size_t)r0 * 512 + n0 + cl] = v0;
            *(float2*)&C[(size_t)(r0 + 8) * 512 + n0 + cl] = v1;
        }
    }
}

// =============================================================================
// K2: scores = q . k^T per (b,h) (exact 391us version).
// =============================================================================
__global__ __launch_bounds__(256) void k_scores()
{
    __shared__ float As[16][132];
    __shared__ float Bs[16][68];

    const int bh = blockIdx.z;
    const int b = bh >> 3, h = bh & 7;
    const int m0 = blockIdx.y * 128;
    const int n0 = blockIdx.x * 64;
    const float* A  = g_q + (size_t)b * L_ * HID_ + h * DH_;
    const float* Bm = g_k + (size_t)b * L_ * HID_ + h * DH_;
    float* C = g_sc + (size_t)bh * L_ * L_;

    const int tid = threadIdx.x;
    const int tx = tid & 15, ty = tid >> 4;
    const int lrow = tid >> 2;
    const int lf   = tid & 3;

    float2 acc[4][4];
#pragma unroll
    for (int i = 0; i < 4; i++)
#pragma unroll
        for (int j = 0; j < 4; j++) acc[i][j] = make_float2(0.f, 0.f);

    for (int k0 = 0; k0 < 64; k0 += 16) {
#pragma unroll
        for (int r = 0; r < 2; r++) {
            int row = lrow + r * 64;
            float4 a4 = *(const float4*)&A[(size_t)(m0 + row) * 512 + k0 + lf * 4];
            As[lf * 4 + 0][row] = a4.x; As[lf * 4 + 1][row] = a4.y;
            As[lf * 4 + 2][row] = a4.z; As[lf * 4 + 3][row] = a4.w;
        }
        {
            float4 b4 = *(const float4*)&Bm[(size_t)(n0 + lrow) * 512 + k0 + lf * 4];
            Bs[lf * 4 + 0][lrow] = b4.x; Bs[lf * 4 + 1][lrow] = b4.y;
            Bs[lf * 4 + 2][lrow] = b4.z; Bs[lf * 4 + 3][lrow] = b4.w;
        }
        __syncthreads();
#pragma unroll
        for (int kk = 0; kk < 16; kk++) {
            float4 a0 = *(const float4*)&As[kk][ty * 8];
            float4 a1 = *(const float4*)&As[kk][ty * 8 + 4];
            float4 b4 = *(const float4*)&Bs[kk][tx * 4];
            float2 a2[4] = { make_float2(a0.x, a0.y), make_float2(a0.z, a0.w),
                             make_float2(a1.x, a1.y), make_float2(a1.z, a1.w) };
            float bj[4] = { b4.x, b4.y, b4.z, b4.w };
#pragma unroll
            for (int j = 0; j < 4; j++) {
                float2 bd = fdup(bj[j]);
#pragma unroll
                for (int i = 0; i < 4; i++) ffma2(acc[i][j], a2[i], bd);
            }
        }
        __syncthreads();
    }

#pragma unroll
    for (int i = 0; i < 4; i++) {
        int m = m0 + ty * 8 + 2 * i;
        *(float4*)&C[(size_t)m * 512 + n0 + tx * 4] =
            make_float4(acc[i][0].x, acc[i][1].x, acc[i][2].x, acc[i][3].x);
        *(float4*)&C[(size_t)(m + 1) * 512 + n0 + tx * 4] =
            make_float4(acc[i][0].y, acc[i][1].y, acc[i][2].y, acc[i][3].y);
    }
}

// =============================================================================
// K3: fused per-(b,q) (exact 391us version).
// =============================================================================
#define SMEM_FUSED ((512 * 64 + 8 * 516 + 512) * 4)

__global__ __launch_bounds__(256) void k_fused(
    const float* __restrict__ rels,
    const float* __restrict__ heads,
    float* __restrict__ out)
{
    extern __shared__ float sm[];
    float4* rv  = (float4*)sm;
    float* sc_s = sm + 512 * 64;
    float* q_s  = sc_s + 8 * 516;

    const int bq = blockIdx.x;
    const int b = bq >> 9, q = bq & 511;
    const int tid = threadIdx.x;
    const int lane = tid & 31, w = tid >> 5;

    const float* rg = rels + (size_t)bq * (512 * 64);

    float4 qv;
    if (tid < 128)
        qv = *(const float4*)&g_q[((size_t)b * L_ + q) * HID_ + tid * 4];

#pragma unroll
    for (int g = 0; g < 8; g++) {
#pragma unroll
        for (int i = 0; i < 4; i++) {
            int flat = g * 1024 + i * 256 + tid;
            int row = flat >> 4, d4 = flat & 15;
            cp_async16(&rv[row * 16 + (d4 ^ (row & 15))], rg + (size_t)flat * 4);
        }
        cp_commit();
    }

    if (tid < 128) {
        int e = tid * 4;
        q_s[((e + 0) & 63) * 8 + ((e + 0) >> 6)] = qv.x;
        q_s[((e + 1) & 63) * 8 + ((e + 1) >> 6)] = qv.y;
        q_s[((e + 2) & 63) * 8 + ((e + 2) >> 6)] = qv.z;
        q_s[((e + 3) & 63) * 8 + ((e + 3) >> 6)] = qv.w;
    }

    const int kl = tid >> 2;
    const int p  = tid & 3;
    const size_t hoff   = ((size_t)b * 512 + q) * 512;
    const size_t scoff0 = (((size_t)(b * 8 + 2 * p)) * 512 + q) * 512;
    const size_t scoff1 = scoff0 + (size_t)512 * 512;

#define GROUP_BODY(G, NWAIT)                                                   \
    do {                                                                       \
        cp_wait<NWAIT>();                                                      \
        __syncthreads();                                                       \
        const int k = (G) * 64 + kl;                                           \
        float2 acc = make_float2(0.f, 0.f);                                    \
        _Pragma("unroll")                                                      \
        for (int d4 = 0; d4 < 16; d4++) {                                      \
            float4 r4 = rv[k * 16 + (d4 ^ (k & 15))];                          \
            ffma2(acc, fdup(r4.x), *(const float2*)&q_s[(d4 * 4 + 0) * 8 + 2 * p]); \
            ffma2(acc, fdup(r4.y), *(const float2*)&q_s[(d4 * 4 + 1) * 8 + 2 * p]); \
            ffma2(acc, fdup(r4.z), *(const float2*)&q_s[(d4 * 4 + 2) * 8 + 2 * p]); \
            ffma2(acc, fdup(r4.w), *(const float2*)&q_s[(d4 * 4 + 3) * 8 + 2 * p]); \
        }                                                                      \
        float hv = heads[hoff + k];                                            \
        float s0 = g_sc[scoff0 + k];                                           \
        float s1 = g_sc[scoff1 + k];                                           \
        sc_s[(2 * p) * 516 + k]     = (acc.x + s0) * 0.125f + hv;              \
        sc_s[(2 * p + 1) * 516 + k] = (acc.y + s1) * 0.125f + hv;              \
    } while (0)

    GROUP_BODY(0, 7); GROUP_BODY(1, 6); GROUP_BODY(2, 5); GROUP_BODY(3, 4);
    GROUP_BODY(4, 3); GROUP_BODY(5, 2); GROUP_BODY(6, 1); GROUP_BODY(7, 0);
#undef GROUP_BODY
    __syncthreads();

    {
        float* row = sc_s + w * 516;
        float vals[16];
        float mx = -1e30f;
#pragma unroll
        for (int i = 0; i < 16; i++) { vals[i] = row[i * 32 + lane]; mx = fmaxf(mx, vals[i]); }
#pragma unroll
        for (int o = 16; o; o >>= 1) mx = fmaxf(mx, __shfl_xor_sync(0xffffffffu, mx, o));
        float s = 0.f;
#pragma unroll
        for (int i = 0; i < 16; i++) { vals[i] = __expf(vals[i] - mx); s += vals[i]; }
#pragma unroll
        for (int o = 16; o; o >>= 1) s += __shfl_xor_sync(0xffffffffu, s, o);
        float inv = 1.f / s;
        float* pg = g_sc + (((size_t)(b * 8 + w)) * 512 + q) * 512;
#pragma unroll
        for (int i = 0; i < 16; i++) {
            float pv = vals[i] * inv;
            row[i * 32 + lane] = pv;
            pg[i * 32 + lane] = pv;
        }
    }
    __syncthreads();

    {
        const int ks = tid >> 7;
        const int r  = tid & 127;
        const int h  = r >> 4;
        const int dq = r & 15;
        float2 c0 = make_float2(0.f, 0.f), c1 = make_float2(0.f, 0.f);
        const float* prow = sc_s + h * 516;
        const int kbeg = ks * 256;
#pragma unroll 8
        for (int k = kbeg; k < kbeg + 256; k += 4) {
            float4 p4 = *(const float4*)&prow[k];
            float pj[4] = { p4.x, p4.y, p4.z, p4.w };
#pragma unroll
            for (int j = 0; j < 4; j++) {
                float4 r4 = rv[(k + j) * 16 + (dq ^ ((k + j) & 15))];
                float2 pd = fdup(pj[j]);
                ffma2(c0, pd, make_float2(r4.x, r4.y));
                ffma2(c1, pd, make_float2(r4.z, r4.w));
            }
        }
        if (ks == 1) {
            *(float4*)&q_s[r * 4] = make_float4(c0.x, c0.y, c1.x, c1.y);
        }
        __syncthreads();
        if (ks == 0) {
            float4 t = *(const float4*)&q_s[r * 4];
            float4 o = make_float4(c0.x + t.x, c0.y + t.y, c1.x + t.z, c1.y + t.w);
            *(float4*)&out[(size_t)bq * 512 + h * 64 + dq * 4] = o;
        }
    }
}

// =============================================================================
// K4: ctx += probs @ v per (b,h), k-split x2, atomicAdd epilogue (R4).
// =============================================================================
__global__ __launch_bounds__(256) void k_ctx(float* __restrict__ out)
{
    __shared__ float As[2][16][68];
    __shared__ float Bs[2][16][68];

    const int bh = blockIdx.y;
    const int b = bh >> 3, h = bh & 7;
    const int m0 = blockIdx.x * 64;
    const int kbase = blockIdx.z * 256;
    const float* P = g_sc + (size_t)bh * L_ * L_;
    const float* V = g_v + (size_t)b * L_ * HID_ + h * DH_;

    const int tid = threadIdx.x;
    const int tx = tid & 15, ty = tid >> 4;
    const int lrow = tid >> 2;
    const int lf   = tid & 3;
    const int vrow = tid >> 4;
    const int vc   = tid & 15;

    float2 acc[2][4];
#pragma unroll
    for (int i = 0; i < 2; i++)
#pragma unroll
        for (int j = 0; j < 4; j++) acc[i][j] = make_float2(0.f, 0.f);

    float4 a4r = *(const float4*)&P[(size_t)(m0 + lrow) * 512 + kbase + lf * 4];
    float4 b4r = *(const float4*)&V[(size_t)(kbase + vrow) * 512 + vc * 4];

#pragma unroll 1
    for (int t = 0; t < 16; t++) {
        const int cur = t & 1;
        As[cur][lf * 4 + 0][lrow] = a4r.x; As[cur][lf * 4 + 1][lrow] = a4r.y;
        As[cur][lf * 4 + 2][lrow] = a4r.z; As[cur][lf * 4 + 3][lrow] = a4r.w;
        *(float4*)&Bs[cur][vrow][vc * 4] = b4r;
        __syncthreads();

        if (t < 15) {
            int k0 = kbase + (t + 1) * 16;
            a4r = *(const float4*)&P[(size_t)(m0 + lrow) * 512 + k0 + lf * 4];
            b4r = *(const float4*)&V[(size_t)(k0 + vrow) * 512 + vc * 4];
        }

#pragma unroll
        for (int kk = 0; kk < 16; kk++) {
            float4 a4 = *(const float4*)&As[cur][kk][ty * 4];
            float4 b4 = *(const float4*)&Bs[cur][kk][tx * 4];
            float2 a2[2] = { make_float2(a4.x, a4.y), make_float2(a4.z, a4.w) };
            float bj[4] = { b4.x, b4.y, b4.z, b4.w };
#pragma unroll
            for (int j = 0; j < 4; j++) {
                float2 bd = fdup(bj[j]);
#pragma unroll
                for (int i = 0; i < 2; i++) ffma2(acc[i][j], a2[i], bd);
            }
        }
        if (t < 15) __syncthreads();
    }

#pragma unroll
    for (int i = 0; i < 2; i++) {
        int m = m0 + ty * 4 + 2 * i;
        float* p0 = &out[((size_t)b * 512 + m) * 512 + h * 64 + tx * 4];
        atomicAdd(p0 + 0, acc[i][0].x);
        atomicAdd(p0 + 1, acc[i][1].x);
        atomicAdd(p0 + 2, acc[i][2].x);
        atomicAdd(p0 + 3, acc[i][3].x);
        float* p1 = &out[((size_t)b * 512 + m + 1) * 512 + h * 64 + tx * 4];
        atomicAdd(p1 + 0, acc[i][0].y);
        atomicAdd(p1 + 1, acc[i][1].y);
        atomicAdd(p1 + 2, acc[i][2].y);
        atomicAdd(p1 + 3, acc[i][3].y);
    }
}

// =============================================================================
extern "C" void kernel_launch(void* const* d_in, const int* in_sizes, int n_in,
                              void* d_out, int out_size)
{
    const float* hidden = (const float*)d_in[0];
    const float* heads  = (const float*)d_in[1];
    const float* rels   = (const float*)d_in[2];
    const float* Wq = (const float*)d_in[3];
    const float* bq = (const float*)d_in[4];
    const float* Wk = (const float*)d_in[5];
    const float* bk = (const float*)d_in[6];
    const float* Wv = (const float*)d_in[7];
    const float* bv = (const float*)d_in[8];
    float* out = (float*)d_out;

    k_prep<<<1024, 256>>>(hidden, Wq, Wk, Wv);

    cudaFuncSetAttribute(k_proj_mma, cudaFuncAttributeMaxDynamicSharedMemorySize, SMEM_PROJ);
    dim3 g1(8, 16, 3);
    k_proj_mma<<<g1, 256, SMEM_PROJ>>>(bq, bk, bv);

    dim3 g2(8, 4, 32);
    k_scores<<<g2, 256>>>();

    cudaFuncSetAttribute(k_fused, cudaFuncAttributeMaxDynamicSharedMemorySize, SMEM_FUSED);
    k_fused<<<2048, 256, SMEM_FUSED>>>(rels, heads, out);

    dim3 g4(8, 32, 2);
    k_ctx<<<g4, 256>>>(out);
}

// round 8
// speedup vs baseline: 1.4756x; 1.0675x over previous
#include <cuda_runtime.h>
#include <cuda_bf16.h>
#include <cstdint>
#include <cstddef>

#define B_ 4
#define L_ 512
#define HID_ 512
#define H_ 8
#define DH_ 64

// ---------------- scratch (device globals; no allocations allowed) ----------
__device__ float g_q[B_ * L_ * HID_];
__device__ float g_k[B_ * L_ * HID_];
__device__ float g_v[B_ * L_ * HID_];
__device__ float g_sc[B_ * H_ * L_ * L_];           // scores, then probs
// split-precision operands, K = 1536: A = [xh | xl | xh], B = [wh | wh | wl]
__device__ __nv_bfloat16 g_Xs[2048 * 1536];
__device__ __nv_bfloat16 g_Ws[3 * 512 * 1536];

// ---------------- packed f32x2 FMA ------------------------------------------
__device__ __forceinline__ void ffma2(float2& d, const float2 a, const float2 b) {
    asm("fma.rn.f32x2 %0, %1, %2, %0;"
        : "+l"(reinterpret_cast<unsigned long long&>(d))
        : "l"(reinterpret_cast<const unsigned long long&>(a)),
          "l"(reinterpret_cast<const unsigned long long&>(b)));
}
__device__ __forceinline__ float2 fdup(float a) { return make_float2(a, a); }

// ---------------- cp.async helpers ------------------------------------------
__device__ __forceinline__ void cp_async16(void* smem, const void* gmem) {
    unsigned s = (unsigned)__cvta_generic_to_shared(smem);
    asm volatile("cp.async.cg.shared.global [%0], [%1], 16;\n" :: "r"(s), "l"(gmem));
}
__device__ __forceinline__ void cp_commit() {
    asm volatile("cp.async.commit_group;\n");
}
template <int N>
__device__ __forceinline__ void cp_wait() {
    asm volatile("cp.async.wait_group %0;\n" :: "n"(N));
}

// ---------------- warp mma / ldmatrix (sm_80+, no 'a' feature) ---------------
__device__ __forceinline__ void mma_bf16(float& c0, float& c1, float& c2, float& c3,
                                         uint32_t a0, uint32_t a1, uint32_t a2, uint32_t a3,
                                         uint32_t b0, uint32_t b1) {
    asm volatile(
        "mma.sync.aligned.m16n8k16.row.col.f32.bf16.bf16.f32 "
        "{%0,%1,%2,%3}, {%4,%5,%6,%7}, {%8,%9}, {%0,%1,%2,%3};"
        : "+f"(c0), "+f"(c1), "+f"(c2), "+f"(c3)
        : "r"(a0), "r"(a1), "r"(a2), "r"(a3), "r"(b0), "r"(b1));
}
__device__ __forceinline__ void ldm_x4(uint32_t* r, uint32_t addr) {
    asm volatile("ldmatrix.sync.aligned.m8n8.x4.shared.b16 {%0,%1,%2,%3}, [%4];"
                 : "=r"(r[0]), "=r"(r[1]), "=r"(r[2]), "=r"(r[3]) : "r"(addr));
}
__device__ __forceinline__ void ldm_x2(uint32_t& r0, uint32_t& r1, uint32_t addr) {
    asm volatile("ldmatrix.sync.aligned.m8n8.x2.shared.b16 {%0,%1}, [%2];"
                 : "=r"(r0), "=r"(r1) : "r"(addr));
}
__device__ __forceinline__ void ldm_x2_trans(uint32_t& r0, uint32_t& r1, uint32_t addr) {
    asm volatile("ldmatrix.sync.aligned.m8n8.x2.trans.shared.b16 {%0,%1}, [%2];"
                 : "=r"(r0), "=r"(r1) : "r"(addr));
}

// =============================================================================
// K0: build split-bf16 operands for the projection, K=1536.
// =============================================================================
__global__ __launch_bounds__(256) void k_prep(
    const float* __restrict__ X,
    const float* __restrict__ Wq, const float* __restrict__ Wk,
    const float* __restrict__ Wv)
{
    const int stride = gridDim.x * blockDim.x;
    for (int i = blockIdx.x * blockDim.x + threadIdx.x; i < 2048 * 512; i += stride) {
        int m = i >> 9, k = i & 511;
        float x = X[i];
        __nv_bfloat16 hi = __float2bfloat16(x);
        __nv_bfloat16 lo = __float2bfloat16(x - __bfloat162float(hi));
        __nv_bfloat16* row = g_Xs + (size_t)m * 1536;
        row[k] = hi; row[512 + k] = lo; row[1024 + k] = hi;
    }
    for (int i = blockIdx.x * blockDim.x + threadIdx.x; i < 3 * 512 * 512; i += stride) {
        int z = i >> 18;
        int r = i & 262143;
        const float* W = (z == 0) ? Wq : (z == 1) ? Wk : Wv;
        int n = r >> 9, k = r & 511;
        float x = W[r];
        __nv_bfloat16 hi = __float2bfloat16(x);
        __nv_bfloat16 lo = __float2bfloat16(x - __bfloat162float(hi));
        __nv_bfloat16* row = g_Ws + (size_t)z * 512 * 1536 + (size_t)n * 1536;
        row[k] = hi; row[512 + k] = hi; row[1024 + k] = lo;
    }
}

// =============================================================================
// K1: QKV projection via mma.sync bf16 (unchanged from R7, 361us config).
// =============================================================================
#define PADK 72
#define A_BUF_ELE (128 * PADK)
#define B_BUF_ELE (64 * PADK)
#define SMEM_PROJ ((2 * A_BUF_ELE + 2 * B_BUF_ELE) * 2 + 64 * 4)

__global__ __launch_bounds__(256) void k_proj_mma(
    const float* __restrict__ bq, const float* __restrict__ bk,
    const float* __restrict__ bv)
{
    extern __shared__ char smp[];
    __nv_bfloat16* As = (__nv_bfloat16*)smp;
    __nv_bfloat16* Bs = As + 2 * A_BUF_ELE;
    float* biasS = (float*)(Bs + 2 * B_BUF_ELE);

    const int n0 = blockIdx.x * 64;
    const int m0 = blockIdx.y * 128;
    const int z  = blockIdx.z;
    const float* bias = (z == 0) ? bq : (z == 1) ? bk : bv;
    float* C = (z == 0) ? g_q : (z == 1) ? g_k : g_v;
    const __nv_bfloat16* Wz = g_Ws + (size_t)z * 512 * 1536;

    const int tid = threadIdx.x;
    const int wid = tid >> 5, lane = tid & 31;
    const int wm = wid >> 1, wn = wid & 1;
    const int g  = lane >> 2, tg = lane & 3;

    if (tid < 64) biasS[tid] = bias[n0 + tid];

    float acc[2][4][4];
#pragma unroll
    for (int mt = 0; mt < 2; mt++)
#pragma unroll
        for (int nt = 0; nt < 4; nt++)
#pragma unroll
            for (int e = 0; e < 4; e++) acc[mt][nt][e] = 0.f;

    auto load_chunk = [&](int c, int buf) {
        __nv_bfloat16* Ad = As + buf * A_BUF_ELE;
        __nv_bfloat16* Bd = Bs + buf * B_BUF_ELE;
#pragma unroll
        for (int i = 0; i < 4; i++) {
            int flat = i * 256 + tid;
            int row = flat >> 3, seg = flat & 7;
            cp_async16(Ad + row * PADK + seg * 8,
                       g_Xs + (size_t)(m0 + row) * 1536 + c * 64 + seg * 8);
        }
#pragma unroll
        for (int i = 0; i < 2; i++) {
            int flat = i * 256 + tid;
            int row = flat >> 3, seg = flat & 7;
            cp_async16(Bd + row * PADK + seg * 8,
                       Wz + (size_t)(n0 + row) * 1536 + c * 64 + seg * 8);
        }
        cp_commit();
    };

    load_chunk(0, 0);

#pragma unroll 1
    for (int t = 0; t < 24; t++) {
        if (t < 23) load_chunk(t + 1, (t + 1) & 1);
        if (t < 23) cp_wait<1>(); else cp_wait<0>();
        __syncthreads();

        const __nv_bfloat16* Ab = As + (t & 1) * A_BUF_ELE;
        const __nv_bfloat16* Bb = Bs + (t & 1) * B_BUF_ELE;

#pragma unroll
        for (int ks = 0; ks < 4; ks++) {
            const int kb = ks * 16;
            uint32_t af[2][4], bf[4][2];
#pragma unroll
            for (int mt = 0; mt < 2; mt++) {
                int r0 = wm * 32 + mt * 16 + g;
                af[mt][0] = *(const uint32_t*)&Ab[(r0)      * PADK + kb + tg * 2];
                af[mt][1] = *(const uint32_t*)&Ab[(r0 + 8)  * PADK + kb + tg * 2];
                af[mt][2] = *(const uint32_t*)&Ab[(r0)      * PADK + kb + tg * 2 + 8];
                af[mt][3] = *(const uint32_t*)&Ab[(r0 + 8)  * PADK + kb + tg * 2 + 8];
            }
#pragma unroll
            for (int nt = 0; nt < 4; nt++) {
                int nr = wn * 32 + nt * 8 + g;
                bf[nt][0] = *(const uint32_t*)&Bb[nr * PADK + kb + tg * 2];
                bf[nt][1] = *(const uint32_t*)&Bb[nr * PADK + kb + tg * 2 + 8];
            }
#pragma unroll
            for (int mt = 0; mt < 2; mt++)
#pragma unroll
                for (int nt = 0; nt < 4; nt++)
                    mma_bf16(acc[mt][nt][0], acc[mt][nt][1], acc[mt][nt][2], acc[mt][nt][3],
                             af[mt][0], af[mt][1], af[mt][2], af[mt][3],
                             bf[nt][0], bf[nt][1]);
        }
        __syncthreads();
    }

#pragma unroll
    for (int mt = 0; mt < 2; mt++) {
        int r0 = m0 + wm * 32 + mt * 16 + g;
#pragma unroll
        for (int nt = 0; nt < 4; nt++) {
            int cl = wn * 32 + nt * 8 + tg * 2;
            float2 v0 = make_float2(acc[mt][nt][0] + biasS[cl],
                                    acc[mt][nt][1] + biasS[cl + 1]);
            float2 v1 = make_float2(acc[mt][nt][2] + biasS[cl],
                                    acc[mt][nt][3] + biasS[cl + 1]);
            *(float2*)&C[(size_t)r0 * 512 + n0 + cl] = v0;
            *(float2*)&C[(size_t)(r0 + 8) * 512 + n0 + cl] = v1;
        }
    }
}

// =============================================================================
// K2: scores = q . k^T per (b,h) (exact 391us version).
// =============================================================================
__global__ __launch_bounds__(256) void k_scores()
{
    __shared__ float As[16][132];
    __shared__ float Bs[16][68];

    const int bh = blockIdx.z;
    const int b = bh >> 3, h = bh & 7;
    const int m0 = blockIdx.y * 128;
    const int n0 = blockIdx.x * 64;
    const float* A  = g_q + (size_t)b * L_ * HID_ + h * DH_;
    const float* Bm = g_k + (size_t)b * L_ * HID_ + h * DH_;
    float* C = g_sc + (size_t)bh * L_ * L_;

    const int tid = threadIdx.x;
    const int tx = tid & 15, ty = tid >> 4;
    const int lrow = tid >> 2;
    const int lf   = tid & 3;

    float2 acc[4][4];
#pragma unroll
    for (int i = 0; i < 4; i++)
#pragma unroll
        for (int j = 0; j < 4; j++) acc[i][j] = make_float2(0.f, 0.f);

    for (int k0 = 0; k0 < 64; k0 += 16) {
#pragma unroll
        for (int r = 0; r < 2; r++) {
            int row = lrow + r * 64;
            float4 a4 = *(const float4*)&A[(size_t)(m0 + row) * 512 + k0 + lf * 4];
            As[lf * 4 + 0][row] = a4.x; As[lf * 4 + 1][row] = a4.y;
            As[lf * 4 + 2][row] = a4.z; As[lf * 4 + 3][row] = a4.w;
        }
        {
            float4 b4 = *(const float4*)&Bm[(size_t)(n0 + lrow) * 512 + k0 + lf * 4];
            Bs[lf * 4 + 0][lrow] = b4.x; Bs[lf * 4 + 1][lrow] = b4.y;
            Bs[lf * 4 + 2][lrow] = b4.z; Bs[lf * 4 + 3][lrow] = b4.w;
        }
        __syncthreads();
#pragma unroll
        for (int kk = 0; kk < 16; kk++) {
            float4 a0 = *(const float4*)&As[kk][ty * 8];
            float4 a1 = *(const float4*)&As[kk][ty * 8 + 4];
            float4 b4 = *(const float4*)&Bs[kk][tx * 4];
            float2 a2[4] = { make_float2(a0.x, a0.y), make_float2(a0.z, a0.w),
                             make_float2(a1.x, a1.y), make_float2(a1.z, a1.w) };
            float bj[4] = { b4.x, b4.y, b4.z, b4.w };
#pragma unroll
            for (int j = 0; j < 4; j++) {
                float2 bd = fdup(bj[j]);
#pragma unroll
                for (int i = 0; i < 4; i++) ffma2(acc[i][j], a2[i], bd);
            }
        }
        __syncthreads();
    }

#pragma unroll
    for (int i = 0; i < 4; i++) {
        int m = m0 + ty * 8 + 2 * i;
        *(float4*)&C[(size_t)m * 512 + n0 + tx * 4] =
            make_float4(acc[i][0].x, acc[i][1].x, acc[i][2].x, acc[i][3].x);
        *(float4*)&C[(size_t)(m + 1) * 512 + n0 + tx * 4] =
            make_float4(acc[i][0].y, acc[i][1].y, acc[i][2].y, acc[i][3].y);
    }
}

// =============================================================================
// K3: fused per-(b,q) — TENSOR-CORE version.
// rels LDG->split bf16 (hi/lo) into swizzled smem; stage B and stage D run on
// mma.sync.m16n8k16 with split-bf16 (error ~2^-16).
// Stage B: scores[16(h),512(k)] = QS[16,64x3] @ rels[k][d] (B natural layout)
// Stage D: ctx[16(h),64(d)]     = PS[16,512x3] @ rels^T   (B via ldmatrix.trans)
// =============================================================================
#define F_RH 0
#define F_RL 65536
#define F_SC 131072                 // float [8][516]
#define F_QS 147584                 // bf16  [16][136]  ([qh|ql] cols 0..127)
#define F_PS 151936                 // bf16  [16][1032] ([ph|pl] cols 0..1023)
#define F_RED 184960                // float [4][8][32][4]
#define SMEM_FUSED (184960 + 16384) // 201344 bytes

__global__ __launch_bounds__(256) void k_fused(
    const float* __restrict__ rels,
    const float* __restrict__ heads,
    float* __restrict__ out)
{
    extern __shared__ char smf[];
    const uint32_t sbase = (uint32_t)__cvta_generic_to_shared(smf);
    float* sc_s = (float*)(smf + F_SC);
    __nv_bfloat16* QS = (__nv_bfloat16*)(smf + F_QS);
    __nv_bfloat16* PS = (__nv_bfloat16*)(smf + F_PS);
    float* red = (float*)(smf + F_RED);

    const int bq = blockIdx.x;
    const int b = bq >> 9, q = bq & 511;
    const int tid = threadIdx.x;
    const int lane = tid & 31, w = tid >> 5;

    const float* rg = rels + (size_t)bq * (512 * 64);
    const size_t hoff = ((size_t)b * 512 + q) * 512;
    const size_t scbase = (size_t)b * 2097152 + (size_t)q * 512;

    // ---- issue q LDG + rels group-0 LDG first (latency) ----
    float4 qv = make_float4(0.f, 0.f, 0.f, 0.f);
    if (tid < 128)
        qv = *(const float4*)&g_q[((size_t)b * L_ + q) * HID_ + tid * 4];

    float4 stg[2][4];
    {
        int r = (tid >> 2), dseg = (tid & 3) * 16;
        const float* src = rg + (size_t)r * 64 + dseg;
#pragma unroll
        for (int j = 0; j < 4; j++) stg[0][j] = ((const float4*)src)[j];
    }

    // ---- zero QS rows 8-15 and PS rows 8-15 ----
    for (int i = tid; i < 544; i += 256)
        ((uint32_t*)(smf + F_QS + 8 * 272))[i] = 0;
    for (int i = tid; i < 4128; i += 256)
        ((uint32_t*)(smf + F_PS + 8 * 2064))[i] = 0;

    // ---- build QS [qh|ql]: QS[h][d], QS[h][64+d] ----
    if (tid < 128) {
        int h = tid >> 4, d = (tid & 15) * 4;
        float xs[4] = { qv.x, qv.y, qv.z, qv.w };
#pragma unroll
        for (int j = 0; j < 4; j++) {
            __nv_bfloat16 hb = __float2bfloat16(xs[j]);
            QS[h * 136 + d + j] = hb;
            QS[h * 136 + 64 + d + j] = __float2bfloat16(xs[j] - __bfloat162float(hb));
        }
    }
    __syncthreads();

    // ---- load q A-fragments once: afr[s][dstep][4] ----
    uint32_t afr[2][4][4];
#pragma unroll
    for (int s = 0; s < 2; s++)
#pragma unroll
        for (int ds = 0; ds < 4; ds++) {
            uint32_t addr = sbase + F_QS + (lane & 15) * 272
                          + (s * 64 + ds * 16 + ((lane >> 4) << 3)) * 2;
            ldm_x4(afr[s][ds], addr);
        }

    // ---- rels conversion helpers ----
    auto ldg_group = [&](int g, float4* dst) {
        int r = g * 64 + (tid >> 2), dseg = (tid & 3) * 16;
        const float* src = rg + (size_t)r * 64 + dseg;
#pragma unroll
        for (int j = 0; j < 4; j++) dst[j] = ((const float4*)src)[j];
    };
    auto sts_group = [&](int g, const float4* st) {
        int rr = tid >> 2;
        int r = g * 64 + rr;
        int c0 = (tid & 3) * 2;
        const float* xs = (const float*)st;
        union { __nv_bfloat16 bb[8]; uint4 u; } h0, h1, l0, l1;
#pragma unroll
        for (int j = 0; j < 8; j++) {
            float x = xs[j];
            __nv_bfloat16 hb = __float2bfloat16(x);
            h0.bb[j] = hb; l0.bb[j] = __float2bfloat16(x - __bfloat162float(hb));
        }
#pragma unroll
        for (int j = 0; j < 8; j++) {
            float x = xs[8 + j];
            __nv_bfloat16 hb = __float2bfloat16(x);
            h1.bb[j] = hb; l1.bb[j] = __float2bfloat16(x - __bfloat162float(hb));
        }
        char* rhrow = smf + F_RH + r * 128;
        char* rlrow = smf + F_RL + r * 128;
        int s7 = rr & 7;
        *(uint4*)(rhrow + (((c0)     ^ s7) << 4)) = h0.u;
        *(uint4*)(rhrow + (((c0 + 1) ^ s7) << 4)) = h1.u;
        *(uint4*)(rlrow + (((c0)     ^ s7) << 4)) = l0.u;
        *(uint4*)(rlrow + (((c0 + 1) ^ s7) << 4)) = l1.u;
    };

    // ---- stage B per group: warp w handles n-tile k in [g*64+w*8, +8) ----
    auto stageB = [&](int g) {
        const int k0 = g * 64 + w * 8;
        float a0 = 0.f, a1 = 0.f, a2 = 0.f, a3 = 0.f;
        const int row = k0 + (lane & 7);
        const int s7 = row & 7;
        const int csel = (lane >> 3) & 1;
#pragma unroll
        for (int pass = 0; pass < 3; pass++) {
            const uint32_t rb = sbase + ((pass < 2) ? F_RH : F_RL);
            const int s = (pass == 1) ? 1 : 0;
#pragma unroll
            for (int ds = 0; ds < 4; ds++) {
                int chunk = ds * 2 + csel;
                uint32_t addr = rb + row * 128 + ((chunk ^ s7) << 4);
                uint32_t b0, b1;
                ldm_x2(b0, b1, addr);
                mma_bf16(a0, a1, a2, a3,
                         afr[s][ds][0], afr[s][ds][1], afr[s][ds][2], afr[s][ds][3],
                         b0, b1);
            }
        }
        int h = lane >> 2, kk = k0 + (lane & 3) * 2;
        float2 qk = *(const float2*)&g_sc[scbase + (size_t)h * 262144 + kk];
        float2 hv = *(const float2*)&heads[hoff + kk];
        sc_s[h * 516 + kk]     = (a0 + qk.x) * 0.125f + hv.x;
        sc_s[h * 516 + kk + 1] = (a1 + qk.y) * 0.125f + hv.y;
    };

    // ---- group loop: convert + stage B, pipelined ----
#pragma unroll 1
    for (int g = 0; g < 8; g++) {
        sts_group(g, stg[g & 1]);
        __syncthreads();
        if (g < 7) ldg_group(g + 1, stg[(g + 1) & 1]);
        stageB(g);
    }
    __syncthreads();

    // ---- softmax (warp w == head w) + build PS [ph|pl] ----
    {
        float* row = sc_s + w * 516;
        float vals[16];
        float mx = -1e30f;
#pragma unroll
        for (int i = 0; i < 16; i++) { vals[i] = row[i * 32 + lane]; mx = fmaxf(mx, vals[i]); }
#pragma unroll
        for (int o = 16; o; o >>= 1) mx = fmaxf(mx, __shfl_xor_sync(0xffffffffu, mx, o));
        float s = 0.f;
#pragma unroll
        for (int i = 0; i < 16; i++) { vals[i] = __expf(vals[i] - mx); s += vals[i]; }
#pragma unroll
        for (int o = 16; o; o >>= 1) s += __shfl_xor_sync(0xffffffffu, s, o);
        float inv = 1.f / s;
        float* pg = g_sc + (((size_t)(b * 8 + w)) * 512 + q) * 512;
#pragma unroll
        for (int i = 0; i < 16; i++) {
            float pv = vals[i] * inv;
            int kk = i * 32 + lane;
            pg[kk] = pv;
            __nv_bfloat16 ph = __float2bfloat16(pv);
            PS[w * 1032 + kk] = ph;
            PS[w * 1032 + 512 + kk] = __float2bfloat16(pv - __bfloat162float(ph));
        }
    }
    __syncthreads();

    // ---- stage D: warp (kg = w>>1, ng = w&1), 4 n-tiles each ----
    {
        const int kg = w >> 1, ng = w & 1;
        float aD[4][4];
#pragma unroll
        for (int i = 0; i < 4; i++)
#pragma unroll
            for (int j = 0; j < 4; j++) aD[i][j] = 0.f;

#pragma unroll
        for (int pass = 0; pass < 3; pass++) {
            const uint32_t rb = sbase + ((pass < 2) ? F_RH : F_RL);
            const int acol = (pass == 1) ? 512 : 0;
#pragma unroll
            for (int ks = 0; ks < 8; ks++) {
                const int k0 = kg * 128 + ks * 16;
                uint32_t af[4];
                uint32_t aaddr = sbase + F_PS + (lane & 15) * 2064
                               + (acol + k0 + ((lane >> 4) << 3)) * 2;
                ldm_x4(af, aaddr);
                const int row = k0 + (lane & 7) + (((lane >> 3) & 1) << 3);
                const int s7 = row & 7;
#pragma unroll
                for (int ntl = 0; ntl < 4; ntl++) {
                    int d0 = (ng * 4 + ntl) * 8;
                    uint32_t baddr = rb + row * 128 + (((d0 >> 3) ^ s7) << 4);
                    uint32_t b0, b1;
                    ldm_x2_trans(b0, b1, baddr);
                    mma_bf16(aD[ntl][0], aD[ntl][1], aD[ntl][2], aD[ntl][3],
                             af[0], af[1], af[2], af[3], b0, b1);
                }
            }
        }
#pragma unroll
        for (int ntl = 0; ntl < 4; ntl++) {
            int slot = kg * 8 + ng * 4 + ntl;
            *(float4*)&red[(slot * 32 + lane) * 4] =
                make_float4(aD[ntl][0], aD[ntl][1], aD[ntl][2], aD[ntl][3]);
        }
    }
    __syncthreads();

    // ---- reduce 4 kg partials; warp w owns n-tile w; write out ----
    {
        float4 s0 = *(const float4*)&red[((0 * 8 + w) * 32 + lane) * 4];
        float4 s1 = *(const float4*)&red[((1 * 8 + w) * 32 + lane) * 4];
        float4 s2 = *(const float4*)&red[((2 * 8 + w) * 32 + lane) * 4];
        float4 s3 = *(const float4*)&red[((3 * 8 + w) * 32 + lane) * 4];
        float rx = s0.x + s1.x + s2.x + s3.x;
        float ry = s0.y + s1.y + s2.y + s3.y;
        int h = lane >> 2, d = w * 8 + (lane & 3) * 2;
        *(float2*)&out[(size_t)bq * 512 + h * 64 + d] = make_float2(rx, ry);
    }
}

// =============================================================================
// K4: ctx += probs @ v per (b,h), k-split x2, atomicAdd epilogue (R4/R7).
// =============================================================================
__global__ __launch_bounds__(256) void k_ctx(float* __restrict__ out)
{
    __shared__ float As[2][16][68];
    __shared__ float Bs[2][16][68];

    const int bh = blockIdx.y;
    const int b = bh >> 3, h = bh & 7;
    const int m0 = blockIdx.x * 64;
    const int kbase = blockIdx.z * 256;
    const float* P = g_sc + (size_t)bh * L_ * L_;
    const float* V = g_v + (size_t)b * L_ * HID_ + h * DH_;

    const int tid = threadIdx.x;
    const int tx = tid & 15, ty = tid >> 4;
    const int lrow = tid >> 2;
    const int lf   = tid & 3;
    const int vrow = tid >> 4;
    const int vc   = tid & 15;

    float2 acc[2][4];
#pragma unroll
    for (int i = 0; i < 2; i++)
#pragma unroll
        for (int j = 0; j < 4; j++) acc[i][j] = make_float2(0.f, 0.f);

    float4 a4r = *(const float4*)&P[(size_t)(m0 + lrow) * 512 + kbase + lf * 4];
    float4 b4r = *(const float4*)&V[(size_t)(kbase + vrow) * 512 + vc * 4];

#pragma unroll 1
    for (int t = 0; t < 16; t++) {
        const int cur = t & 1;
        As[cur][lf * 4 + 0][lrow] = a4r.x; As[cur][lf * 4 + 1][lrow] = a4r.y;
        As[cur][lf * 4 + 2][lrow] = a4r.z; As[cur][lf * 4 + 3][lrow] = a4r.w;
        *(float4*)&Bs[cur][vrow][vc * 4] = b4r;
        __syncthreads();

        if (t < 15) {
            int k0 = kbase + (t + 1) * 16;
            a4r = *(const float4*)&P[(size_t)(m0 + lrow) * 512 + k0 + lf * 4];
            b4r = *(const float4*)&V[(size_t)(k0 + vrow) * 512 + vc * 4];
        }

#pragma unroll
        for (int kk = 0; kk < 16; kk++) {
            float4 a4 = *(const float4*)&As[cur][kk][ty * 4];
            float4 b4 = *(const float4*)&Bs[cur][kk][tx * 4];
            float2 a2[2] = { make_float2(a4.x, a4.y), make_float2(a4.z, a4.w) };
            float bj[4] = { b4.x, b4.y, b4.z, b4.w };
#pragma unroll
            for (int j = 0; j < 4; j++) {
                float2 bd = fdup(bj[j]);
#pragma unroll
                for (int i = 0; i < 2; i++) ffma2(acc[i][j], a2[i], bd);
            }
        }
        if (t < 15) __syncthreads();
    }

#pragma unroll
    for (int i = 0; i < 2; i++) {
        int m = m0 + ty * 4 + 2 * i;
        float* p0 = &out[((size_t)b * 512 + m) * 512 + h * 64 + tx * 4];
        atomicAdd(p0 + 0, acc[i][0].x);
        atomicAdd(p0 + 1, acc[i][1].x);
        atomicAdd(p0 + 2, acc[i][2].x);
        atomicAdd(p0 + 3, acc[i][3].x);
        float* p1 = &out[((size_t)b * 512 + m + 1) * 512 + h * 64 + tx * 4];
        atomicAdd(p1 + 0, acc[i][0].y);
        atomicAdd(p1 + 1, acc[i][1].y);
        atomicAdd(p1 + 2, acc[i][2].y);
        atomicAdd(p1 + 3, acc[i][3].y);
    }
}

// =============================================================================
extern "C" void kernel_launch(void* const* d_in, const int* in_sizes, int n_in,
                              void* d_out, int out_size)
{
    const float* hidden = (const float*)d_in[0];
    const float* heads  = (const float*)d_in[1];
    const float* rels   = (const float*)d_in[2];
    const float* Wq = (const float*)d_in[3];
    const float* bq = (const float*)d_in[4];
    const float* Wk = (const float*)d_in[5];
    const float* bk = (const float*)d_in[6];
    const float* Wv = (const float*)d_in[7];
    const float* bv = (const float*)d_in[8];
    float* out = (float*)d_out;

    k_prep<<<1024, 256>>>(hidden, Wq, Wk, Wv);

    cudaFuncSetAttribute(k_proj_mma, cudaFuncAttributeMaxDynamicSharedMemorySize, SMEM_PROJ);
    dim3 g1(8, 16, 3);
    k_proj_mma<<<g1, 256, SMEM_PROJ>>>(bq, bk, bv);

    dim3 g2(8, 4, 32);
    k_scores<<<g2, 256>>>();

    cudaFuncSetAttribute(k_fused, cudaFuncAttributeMaxDynamicSharedMemorySize, SMEM_FUSED);
    k_fused<<<2048, 256, SMEM_FUSED>>>(rels, heads, out);

    dim3 g4(8, 32, 2);
    k_ctx<<<g4, 256>>>(out);
}

// round 9
// speedup vs baseline: 1.5687x; 1.0631x over previous
#include <cuda_runtime.h>
#include <cuda_bf16.h>
#include <cstdint>
#include <cstddef>

#define B_ 4
#define L_ 512
#define HID_ 512
#define H_ 8
#define DH_ 64

// ---------------- scratch (device globals; no allocations allowed) ----------
__device__ float g_q[B_ * L_ * HID_];
__device__ float g_k[B_ * L_ * HID_];
__device__ float g_v[B_ * L_ * HID_];
__device__ float g_sc[B_ * H_ * L_ * L_];           // scores, then probs
// split-precision operands, K = 1536: A = [xh | xl | xh], B = [wh | wh | wl]
__device__ __nv_bfloat16 g_Xs[2048 * 1536];
__device__ __nv_bfloat16 g_Ws[3 * 512 * 1536];

// ---------------- packed f32x2 FMA ------------------------------------------
__device__ __forceinline__ void ffma2(float2& d, const float2 a, const float2 b) {
    asm("fma.rn.f32x2 %0, %1, %2, %0;"
        : "+l"(reinterpret_cast<unsigned long long&>(d))
        : "l"(reinterpret_cast<const unsigned long long&>(a)),
          "l"(reinterpret_cast<const unsigned long long&>(b)));
}
__device__ __forceinline__ float2 fdup(float a) { return make_float2(a, a); }

// ---------------- cp.async helpers ------------------------------------------
__device__ __forceinline__ void cp_async16(void* smem, const void* gmem) {
    unsigned s = (unsigned)__cvta_generic_to_shared(smem);
    asm volatile("cp.async.cg.shared.global [%0], [%1], 16;\n" :: "r"(s), "l"(gmem));
}
__device__ __forceinline__ void cp_commit() {
    asm volatile("cp.async.commit_group;\n");
}
template <int N>
__device__ __forceinline__ void cp_wait() {
    asm volatile("cp.async.wait_group %0;\n" :: "n"(N));
}

// ---------------- warp mma / ldmatrix (sm_80+, no 'a' feature) ---------------
__device__ __forceinline__ void mma_bf16(float& c0, float& c1, float& c2, float& c3,
                                         uint32_t a0, uint32_t a1, uint32_t a2, uint32_t a3,
                                         uint32_t b0, uint32_t b1) {
    asm volatile(
        "mma.sync.aligned.m16n8k16.row.col.f32.bf16.bf16.f32 "
        "{%0,%1,%2,%3}, {%4,%5,%6,%7}, {%8,%9}, {%0,%1,%2,%3};"
        : "+f"(c0), "+f"(c1), "+f"(c2), "+f"(c3)
        : "r"(a0), "r"(a1), "r"(a2), "r"(a3), "r"(b0), "r"(b1));
}
__device__ __forceinline__ void ldm_x4(uint32_t* r, uint32_t addr) {
    asm volatile("ldmatrix.sync.aligned.m8n8.x4.shared.b16 {%0,%1,%2,%3}, [%4];"
                 : "=r"(r[0]), "=r"(r[1]), "=r"(r[2]), "=r"(r[3]) : "r"(addr));
}
__device__ __forceinline__ void ldm_x2(uint32_t& r0, uint32_t& r1, uint32_t addr) {
    asm volatile("ldmatrix.sync.aligned.m8n8.x2.shared.b16 {%0,%1}, [%2];"
                 : "=r"(r0), "=r"(r1) : "r"(addr));
}
__device__ __forceinline__ void ldm_x2_trans(uint32_t& r0, uint32_t& r1, uint32_t addr) {
    asm volatile("ldmatrix.sync.aligned.m8n8.x2.trans.shared.b16 {%0,%1}, [%2];"
                 : "=r"(r0), "=r"(r1) : "r"(addr));
}

// =============================================================================
// K0: build split-bf16 operands for the projection, K=1536.
// =============================================================================
__global__ __launch_bounds__(256) void k_prep(
    const float* __restrict__ X,
    const float* __restrict__ Wq, const float* __restrict__ Wk,
    const float* __restrict__ Wv)
{
    const int stride = gridDim.x * blockDim.x;
    for (int i = blockIdx.x * blockDim.x + threadIdx.x; i < 2048 * 512; i += stride) {
        int m = i >> 9, k = i & 511;
        float x = X[i];
        __nv_bfloat16 hi = __float2bfloat16(x);
        __nv_bfloat16 lo = __float2bfloat16(x - __bfloat162float(hi));
        __nv_bfloat16* row = g_Xs + (size_t)m * 1536;
        row[k] = hi; row[512 + k] = lo; row[1024 + k] = hi;
    }
    for (int i = blockIdx.x * blockDim.x + threadIdx.x; i < 3 * 512 * 512; i += stride) {
        int z = i >> 18;
        int r = i & 262143;
        const float* W = (z == 0) ? Wq : (z == 1) ? Wk : Wv;
        int n = r >> 9, k = r & 511;
        float x = W[r];
        __nv_bfloat16 hi = __float2bfloat16(x);
        __nv_bfloat16 lo = __float2bfloat16(x - __bfloat162float(hi));
        __nv_bfloat16* row = g_Ws + (size_t)z * 512 * 1536 + (size_t)n * 1536;
        row[k] = hi; row[512 + k] = hi; row[1024 + k] = lo;
    }
}

// =============================================================================
// K1: QKV projection via mma.sync bf16 (unchanged).
// =============================================================================
#define PADK 72
#define A_BUF_ELE (128 * PADK)
#define B_BUF_ELE (64 * PADK)
#define SMEM_PROJ ((2 * A_BUF_ELE + 2 * B_BUF_ELE) * 2 + 64 * 4)

__global__ __launch_bounds__(256) void k_proj_mma(
    const float* __restrict__ bq, const float* __restrict__ bk,
    const float* __restrict__ bv)
{
    extern __shared__ char smp[];
    __nv_bfloat16* As = (__nv_bfloat16*)smp;
    __nv_bfloat16* Bs = As + 2 * A_BUF_ELE;
    float* biasS = (float*)(Bs + 2 * B_BUF_ELE);

    const int n0 = blockIdx.x * 64;
    const int m0 = blockIdx.y * 128;
    const int z  = blockIdx.z;
    const float* bias = (z == 0) ? bq : (z == 1) ? bk : bv;
    float* C = (z == 0) ? g_q : (z == 1) ? g_k : g_v;
    const __nv_bfloat16* Wz = g_Ws + (size_t)z * 512 * 1536;

    const int tid = threadIdx.x;
    const int wid = tid >> 5, lane = tid & 31;
    const int wm = wid >> 1, wn = wid & 1;
    const int g  = lane >> 2, tg = lane & 3;

    if (tid < 64) biasS[tid] = bias[n0 + tid];

    float acc[2][4][4];
#pragma unroll
    for (int mt = 0; mt < 2; mt++)
#pragma unroll
        for (int nt = 0; nt < 4; nt++)
#pragma unroll
            for (int e = 0; e < 4; e++) acc[mt][nt][e] = 0.f;

    auto load_chunk = [&](int c, int buf) {
        __nv_bfloat16* Ad = As + buf * A_BUF_ELE;
        __nv_bfloat16* Bd = Bs + buf * B_BUF_ELE;
#pragma unroll
        for (int i = 0; i < 4; i++) {
            int flat = i * 256 + tid;
            int row = flat >> 3, seg = flat & 7;
            cp_async16(Ad + row * PADK + seg * 8,
                       g_Xs + (size_t)(m0 + row) * 1536 + c * 64 + seg * 8);
        }
#pragma unroll
        for (int i = 0; i < 2; i++) {
            int flat = i * 256 + tid;
            int row = flat >> 3, seg = flat & 7;
            cp_async16(Bd + row * PADK + seg * 8,
                       Wz + (size_t)(n0 + row) * 1536 + c * 64 + seg * 8);
        }
        cp_commit();
    };

    load_chunk(0, 0);

#pragma unroll 1
    for (int t = 0; t < 24; t++) {
        if (t < 23) load_chunk(t + 1, (t + 1) & 1);
        if (t < 23) cp_wait<1>(); else cp_wait<0>();
        __syncthreads();

        const __nv_bfloat16* Ab = As + (t & 1) * A_BUF_ELE;
        const __nv_bfloat16* Bb = Bs + (t & 1) * B_BUF_ELE;

#pragma unroll
        for (int ks = 0; ks < 4; ks++) {
            const int kb = ks * 16;
            uint32_t af[2][4], bf[4][2];
#pragma unroll
            for (int mt = 0; mt < 2; mt++) {
                int r0 = wm * 32 + mt * 16 + g;
                af[mt][0] = *(const uint32_t*)&Ab[(r0)      * PADK + kb + tg * 2];
                af[mt][1] = *(const uint32_t*)&Ab[(r0 + 8)  * PADK + kb + tg * 2];
                af[mt][2] = *(const uint32_t*)&Ab[(r0)      * PADK + kb + tg * 2 + 8];
                af[mt][3] = *(const uint32_t*)&Ab[(r0 + 8)  * PADK + kb + tg * 2 + 8];
            }
#pragma unroll
            for (int nt = 0; nt < 4; nt++) {
                int nr = wn * 32 + nt * 8 + g;
                bf[nt][0] = *(const uint32_t*)&Bb[nr * PADK + kb + tg * 2];
                bf[nt][1] = *(const uint32_t*)&Bb[nr * PADK + kb + tg * 2 + 8];
            }
#pragma unroll
            for (int mt = 0; mt < 2; mt++)
#pragma unroll
                for (int nt = 0; nt < 4; nt++)
                    mma_bf16(acc[mt][nt][0], acc[mt][nt][1], acc[mt][nt][2], acc[mt][nt][3],
                             af[mt][0], af[mt][1], af[mt][2], af[mt][3],
                             bf[nt][0], bf[nt][1]);
        }
        __syncthreads();
    }

#pragma unroll
    for (int mt = 0; mt < 2; mt++) {
        int r0 = m0 + wm * 32 + mt * 16 + g;
#pragma unroll
        for (int nt = 0; nt < 4; nt++) {
            int cl = wn * 32 + nt * 8 + tg * 2;
            float2 v0 = make_float2(acc[mt][nt][0] + biasS[cl],
                                    acc[mt][nt][1] + biasS[cl + 1]);
            float2 v1 = make_float2(acc[mt][nt][2] + biasS[cl],
                                    acc[mt][nt][3] + biasS[cl + 1]);
            *(float2*)&C[(size_t)r0 * 512 + n0 + cl] = v0;
            *(float2*)&C[(size_t)(r0 + 8) * 512 + n0 + cl] = v1;
        }
    }
}

// =============================================================================
// K2: scores = q . k^T per (b,h) (unchanged).
// =============================================================================
__global__ __launch_bounds__(256) void k_scores()
{
    __shared__ float As[16][132];
    __shared__ float Bs[16][68];

    const int bh = blockIdx.z;
    const int b = bh >> 3, h = bh & 7;
    const int m0 = blockIdx.y * 128;
    const int n0 = blockIdx.x * 64;
    const float* A  = g_q + (size_t)b * L_ * HID_ + h * DH_;
    const float* Bm = g_k + (size_t)b * L_ * HID_ + h * DH_;
    float* C = g_sc + (size_t)bh * L_ * L_;

    const int tid = threadIdx.x;
    const int tx = tid & 15, ty = tid >> 4;
    const int lrow = tid >> 2;
    const int lf   = tid & 3;

    float2 acc[4][4];
#pragma unroll
    for (int i = 0; i < 4; i++)
#pragma unroll
        for (int j = 0; j < 4; j++) acc[i][j] = make_float2(0.f, 0.f);

    for (int k0 = 0; k0 < 64; k0 += 16) {
#pragma unroll
        for (int r = 0; r < 2; r++) {
            int row = lrow + r * 64;
            float4 a4 = *(const float4*)&A[(size_t)(m0 + row) * 512 + k0 + lf * 4];
            As[lf * 4 + 0][row] = a4.x; As[lf * 4 + 1][row] = a4.y;
            As[lf * 4 + 2][row] = a4.z; As[lf * 4 + 3][row] = a4.w;
        }
        {
            float4 b4 = *(const float4*)&Bm[(size_t)(n0 + lrow) * 512 + k0 + lf * 4];
            Bs[lf * 4 + 0][lrow] = b4.x; Bs[lf * 4 + 1][lrow] = b4.y;
            Bs[lf * 4 + 2][lrow] = b4.z; Bs[lf * 4 + 3][lrow] = b4.w;
        }
        __syncthreads();
#pragma unroll
        for (int kk = 0; kk < 16; kk++) {
            float4 a0 = *(const float4*)&As[kk][ty * 8];
            float4 a1 = *(const float4*)&As[kk][ty * 8 + 4];
            float4 b4 = *(const float4*)&Bs[kk][tx * 4];
            float2 a2[4] = { make_float2(a0.x, a0.y), make_float2(a0.z, a0.w),
                             make_float2(a1.x, a1.y), make_float2(a1.z, a1.w) };
            float bj[4] = { b4.x, b4.y, b4.z, b4.w };
#pragma unroll
            for (int j = 0; j < 4; j++) {
                float2 bd = fdup(bj[j]);
#pragma unroll
                for (int i = 0; i < 4; i++) ffma2(acc[i][j], a2[i], bd);
            }
        }
        __syncthreads();
    }

#pragma unroll
    for (int i = 0; i < 4; i++) {
        int m = m0 + ty * 8 + 2 * i;
        *(float4*)&C[(size_t)m * 512 + n0 + tx * 4] =
            make_float4(acc[i][0].x, acc[i][1].x, acc[i][2].x, acc[i][3].x);
        *(float4*)&C[(size_t)(m + 1) * 512 + n0 + tx * 4] =
            make_float4(acc[i][0].y, acc[i][1].y, acc[i][2].y, acc[i][3].y);
    }
}

// =============================================================================
// K3: fused per-(b,q) — tensor-core, 512 THREADS (16 warps), 4 super-groups
// of 128 rows, LDG of next super-group issued before convert+MMA of current.
// =============================================================================
#define F_RH 0
#define F_RL 65536
#define F_SC 131072                 // float [8][516]
#define F_QS 147584                 // bf16  [16][136]
#define F_PS 151936                 // bf16  [16][1032]
#define F_RED 184960                // float [64][32][4] = 32KB
#define SMEM_FUSED (184960 + 32768) // 217728 bytes

__global__ __launch_bounds__(512) void k_fused(
    const float* __restrict__ rels,
    const float* __restrict__ heads,
    float* __restrict__ out)
{
    extern __shared__ char smf[];
    const uint32_t sbase = (uint32_t)__cvta_generic_to_shared(smf);
    float* sc_s = (float*)(smf + F_SC);
    __nv_bfloat16* QS = (__nv_bfloat16*)(smf + F_QS);
    __nv_bfloat16* PS = (__nv_bfloat16*)(smf + F_PS);
    float* red = (float*)(smf + F_RED);

    const int bq = blockIdx.x;
    const int b = bq >> 9, q = bq & 511;
    const int tid = threadIdx.x;
    const int lane = tid & 31, w = tid >> 5;

    const float* rg = rels + (size_t)bq * (512 * 64);
    const size_t hoff = ((size_t)b * 512 + q) * 512;
    const size_t scbase = (size_t)b * 2097152 + (size_t)q * 512;

    // ---- q LDG + rels super-group 0 LDG first ----
    float4 qv = make_float4(0.f, 0.f, 0.f, 0.f);
    if (tid < 128)
        qv = *(const float4*)&g_q[((size_t)b * L_ + q) * HID_ + tid * 4];

    float4 stg[2][4];
    {
        int r = tid >> 2, dseg = (tid & 3) * 16;
        const float* src = rg + (size_t)r * 64 + dseg;
#pragma unroll
        for (int j = 0; j < 4; j++) stg[0][j] = ((const float4*)src)[j];
    }

    // ---- zero QS rows 8-15 and PS rows 8-15 ----
    for (int i = tid; i < 544; i += 512)
        ((uint32_t*)(smf + F_QS + 8 * 272))[i] = 0;
    for (int i = tid; i < 4128; i += 512)
        ((uint32_t*)(smf + F_PS + 8 * 2064))[i] = 0;

    // ---- build QS [qh|ql] ----
    if (tid < 128) {
        int h = tid >> 4, d = (tid & 15) * 4;
        float xs[4] = { qv.x, qv.y, qv.z, qv.w };
#pragma unroll
        for (int j = 0; j < 4; j++) {
            __nv_bfloat16 hb = __float2bfloat16(xs[j]);
            QS[h * 136 + d + j] = hb;
            QS[h * 136 + 64 + d + j] = __float2bfloat16(xs[j] - __bfloat162float(hb));
        }
    }
    __syncthreads();

    // ---- load q A-fragments once ----
    uint32_t afr[2][4][4];
#pragma unroll
    for (int s = 0; s < 2; s++)
#pragma unroll
        for (int ds = 0; ds < 4; ds++) {
            uint32_t addr = sbase + F_QS + (lane & 15) * 272
                          + (s * 64 + ds * 16 + ((lane >> 4) << 3)) * 2;
            ldm_x4(afr[s][ds], addr);
        }

    auto ldg_group = [&](int sg, float4* dst) {
        int r = sg * 128 + (tid >> 2), dseg = (tid & 3) * 16;
        const float* src = rg + (size_t)r * 64 + dseg;
#pragma unroll
        for (int j = 0; j < 4; j++) dst[j] = ((const float4*)src)[j];
    };
    auto sts_group = [&](int sg, const float4* st) {
        int rr = tid >> 2;
        int r = sg * 128 + rr;
        int c0 = (tid & 3) * 2;
        const float* xs = (const float*)st;
        union { __nv_bfloat16 bb[8]; uint4 u; } h0, h1, l0, l1;
#pragma unroll
        for (int j = 0; j < 8; j++) {
            float x = xs[j];
            __nv_bfloat16 hb = __float2bfloat16(x);
            h0.bb[j] = hb; l0.bb[j] = __float2bfloat16(x - __bfloat162float(hb));
        }
#pragma unroll
        for (int j = 0; j < 8; j++) {
            float x = xs[8 + j];
            __nv_bfloat16 hb = __float2bfloat16(x);
            h1.bb[j] = hb; l1.bb[j] = __float2bfloat16(x - __bfloat162float(hb));
        }
        char* rhrow = smf + F_RH + r * 128;
        char* rlrow = smf + F_RL + r * 128;
        int s7 = rr & 7;
        *(uint4*)(rhrow + (((c0)     ^ s7) << 4)) = h0.u;
        *(uint4*)(rhrow + (((c0 + 1) ^ s7) << 4)) = h1.u;
        *(uint4*)(rlrow + (((c0)     ^ s7) << 4)) = l0.u;
        *(uint4*)(rlrow + (((c0 + 1) ^ s7) << 4)) = l1.u;
    };

    // ---- stage B: warp w owns n-tile w of the 128-row super-group ----
    auto stageB = [&](int sg) {
        const int k0 = sg * 128 + w * 8;
        float a0 = 0.f, a1 = 0.f, a2 = 0.f, a3 = 0.f;
        const int row = k0 + (lane & 7);
        const int s7 = row & 7;
        const int csel = (lane >> 3) & 1;
#pragma unroll
        for (int pass = 0; pass < 3; pass++) {
            const uint32_t rb = sbase + ((pass < 2) ? F_RH : F_RL);
            const int s = (pass == 1) ? 1 : 0;
#pragma unroll
            for (int ds = 0; ds < 4; ds++) {
                int chunk = ds * 2 + csel;
                uint32_t addr = rb + row * 128 + ((chunk ^ s7) << 4);
                uint32_t b0, b1;
                ldm_x2(b0, b1, addr);
                mma_bf16(a0, a1, a2, a3,
                         afr[s][ds][0], afr[s][ds][1], afr[s][ds][2], afr[s][ds][3],
                         b0, b1);
            }
        }
        int h = lane >> 2, kk = k0 + (lane & 3) * 2;
        float2 qk = *(const float2*)&g_sc[scbase + (size_t)h * 262144 + kk];
        float2 hv = *(const float2*)&heads[hoff + kk];
        sc_s[h * 516 + kk]     = (a0 + qk.x) * 0.125f + hv.x;
        sc_s[h * 516 + kk + 1] = (a1 + qk.y) * 0.125f + hv.y;
    };

    // ---- super-group loop: LDG(sg+1) -> STS(sg) -> sync -> MMA(sg) ----
#pragma unroll 1
    for (int sg = 0; sg < 4; sg++) {
        if (sg < 3) ldg_group(sg + 1, stg[(sg + 1) & 1]);
        sts_group(sg, stg[sg & 1]);
        __syncthreads();
        stageB(sg);
    }
    __syncthreads();

    // ---- softmax (warps 0..7, head w) + build PS ----
    if (w < 8) {
        float* row = sc_s + w * 516;
        float vals[16];
        float mx = -1e30f;
#pragma unroll
        for (int i = 0; i < 16; i++) { vals[i] = row[i * 32 + lane]; mx = fmaxf(mx, vals[i]); }
#pragma unroll
        for (int o = 16; o; o >>= 1) mx = fmaxf(mx, __shfl_xor_sync(0xffffffffu, mx, o));
        float s = 0.f;
#pragma unroll
        for (int i = 0; i < 16; i++) { vals[i] = __expf(vals[i] - mx); s += vals[i]; }
#pragma unroll
        for (int o = 16; o; o >>= 1) s += __shfl_xor_sync(0xffffffffu, s, o);
        float inv = 1.f / s;
        float* pg = g_sc + (((size_t)(b * 8 + w)) * 512 + q) * 512;
#pragma unroll
        for (int i = 0; i < 16; i++) {
            float pv = vals[i] * inv;
            int kk = i * 32 + lane;
            pg[kk] = pv;
            __nv_bfloat16 ph = __float2bfloat16(pv);
            PS[w * 1032 + kk] = ph;
            PS[w * 1032 + 512 + kk] = __float2bfloat16(pv - __bfloat162float(ph));
        }
    }
    __syncthreads();

    // ---- stage D: warp (kg = w>>1 of 8, ng = w&1), 4 n-tiles each ----
    {
        const int kg = w >> 1, ng = w & 1;
        float aD[4][4];
#pragma unroll
        for (int i = 0; i < 4; i++)
#pragma unroll
            for (int j = 0; j < 4; j++) aD[i][j] = 0.f;

#pragma unroll
        for (int pass = 0; pass < 3; pass++) {
            const uint32_t rb = sbase + ((pass < 2) ? F_RH : F_RL);
            const int acol = (pass == 1) ? 512 : 0;
#pragma unroll
            for (int ks = 0; ks < 4; ks++) {
                const int k0 = kg * 64 + ks * 16;
                uint32_t af[4];
                uint32_t aaddr = sbase + F_PS + (lane & 15) * 2064
                               + (acol + k0 + ((lane >> 4) << 3)) * 2;
                ldm_x4(af, aaddr);
                const int row = k0 + (lane & 7) + (((lane >> 3) & 1) << 3);
                const int s7 = row & 7;
#pragma unroll
                for (int ntl = 0; ntl < 4; ntl++) {
                    int d0 = (ng * 4 + ntl) * 8;
                    uint32_t baddr = rb + row * 128 + (((d0 >> 3) ^ s7) << 4);
                    uint32_t b0, b1;
                    ldm_x2_trans(b0, b1, baddr);
                    mma_bf16(aD[ntl][0], aD[ntl][1], aD[ntl][2], aD[ntl][3],
                             af[0], af[1], af[2], af[3], b0, b1);
                }
            }
        }
#pragma unroll
        for (int ntl = 0; ntl < 4; ntl++) {
            int slot = kg * 8 + ng * 4 + ntl;
            *(float4*)&red[(slot * 32 + lane) * 4] =
                make_float4(aD[ntl][0], aD[ntl][1], aD[ntl][2], aD[ntl][3]);
        }
    }
    __syncthreads();

    // ---- reduce 8 kg partials; warps 0..7 own d-tile w ----
    if (w < 8) {
        float rx = 0.f, ry = 0.f;
#pragma unroll
        for (int kg = 0; kg < 8; kg++) {
            float4 s = *(const float4*)&red[((kg * 8 + w) * 32 + lane) * 4];
            rx += s.x; ry += s.y;
        }
        int h = lane >> 2, d = w * 8 + (lane & 3) * 2;
        *(float2*)&out[(size_t)bq * 512 + h * 64 + d] = make_float2(rx, ry);
    }
}

// =============================================================================
// K4: ctx += probs @ v per (b,h), k-split x2, atomicAdd epilogue (unchanged).
// =============================================================================
__global__ __launch_bounds__(256) void k_ctx(float* __restrict__ out)
{
    __shared__ float As[2][16][68];
    __shared__ float Bs[2][16][68];

    const int bh = blockIdx.y;
    const int b = bh >> 3, h = bh & 7;
    const int m0 = blockIdx.x * 64;
    const int kbase = blockIdx.z * 256;
    const float* P = g_sc + (size_t)bh * L_ * L_;
    const float* V = g_v + (size_t)b * L_ * HID_ + h * DH_;

    const int tid = threadIdx.x;
    const int tx = tid & 15, ty = tid >> 4;
    const int lrow = tid >> 2;
    const int lf   = tid & 3;
    const int vrow = tid >> 4;
    const int vc   = tid & 15;

    float2 acc[2][4];
#pragma unroll
    for (int i = 0; i < 2; i++)
#pragma unroll
        for (int j = 0; j < 4; j++) acc[i][j] = make_float2(0.f, 0.f);

    float4 a4r = *(const float4*)&P[(size_t)(m0 + lrow) * 512 + kbase + lf * 4];
    float4 b4r = *(const float4*)&V[(size_t)(kbase + vrow) * 512 + vc * 4];

#pragma unroll 1
    for (int t = 0; t < 16; t++) {
        const int cur = t & 1;
        As[cur][lf * 4 + 0][lrow] = a4r.x; As[cur][lf * 4 + 1][lrow] = a4r.y;
        As[cur][lf * 4 + 2][lrow] = a4r.z; As[cur][lf * 4 + 3][lrow] = a4r.w;
        *(float4*)&Bs[cur][vrow][vc * 4] = b4r;
        __syncthreads();

        if (t < 15) {
            int k0 = kbase + (t + 1) * 16;
            a4r = *(const float4*)&P[(size_t)(m0 + lrow) * 512 + k0 + lf * 4];
            b4r = *(const float4*)&V[(size_t)(k0 + vrow) * 512 + vc * 4];
        }

#pragma unroll
        for (int kk = 0; kk < 16; kk++) {
            float4 a4 = *(const float4*)&As[cur][kk][ty * 4];
            float4 b4 = *(const float4*)&Bs[cur][kk][tx * 4];
            float2 a2[2] = { make_float2(a4.x, a4.y), make_float2(a4.z, a4.w) };
            float bj[4] = { b4.x, b4.y, b4.z, b4.w };
#pragma unroll
            for (int j = 0; j < 4; j++) {
                float2 bd = fdup(bj[j]);
#pragma unroll
                for (int i = 0; i < 2; i++) ffma2(acc[i][j], a2[i], bd);
            }
        }
        if (t < 15) __syncthreads();
    }

#pragma unroll
    for (int i = 0; i < 2; i++) {
        int m = m0 + ty * 4 + 2 * i;
        float* p0 = &out[((size_t)b * 512 + m) * 512 + h * 64 + tx * 4];
        atomicAdd(p0 + 0, acc[i][0].x);
        atomicAdd(p0 + 1, acc[i][1].x);
        atomicAdd(p0 + 2, acc[i][2].x);
        atomicAdd(p0 + 3, acc[i][3].x);
        float* p1 = &out[((size_t)b * 512 + m + 1) * 512 + h * 64 + tx * 4];
        atomicAdd(p1 + 0, acc[i][0].y);
        atomicAdd(p1 + 1, acc[i][1].y);
        atomicAdd(p1 + 2, acc[i][2].y);
        atomicAdd(p1 + 3, acc[i][3].y);
    }
}

// =============================================================================
extern "C" void kernel_launch(void* const* d_in, const int* in_sizes, int n_in,
                              void* d_out, int out_size)
{
    const float* hidden = (const float*)d_in[0];
    const float* heads  = (const float*)d_in[1];
    const float* rels   = (const float*)d_in[2];
    const float* Wq = (const float*)d_in[3];
    const float* bq = (const float*)d_in[4];
    const float* Wk = (const float*)d_in[5];
    const float* bk = (const float*)d_in[6];
    const float* Wv = (const float*)d_in[7];
    const float* bv = (const float*)d_in[8];
    float* out = (float*)d_out;

    k_prep<<<1024, 256>>>(hidden, Wq, Wk, Wv);

    cudaFuncSetAttribute(k_proj_mma, cudaFuncAttributeMaxDynamicSharedMemorySize, SMEM_PROJ);
    dim3 g1(8, 16, 3);
    k_proj_mma<<<g1, 256, SMEM_PROJ>>>(bq, bk, bv);

    dim3 g2(8, 4, 32);
    k_scores<<<g2, 256>>>();

    cudaFuncSetAttribute(k_fused, cudaFuncAttributeMaxDynamicSharedMemorySize, SMEM_FUSED);
    k_fused<<<2048, 512, SMEM_FUSED>>>(rels, heads, out);

    dim3 g4(8, 32, 2);
    k_ctx<<<g4, 256>>>(out);
}

// round 10
// speedup vs baseline: 1.8013x; 1.1483x over previous
#include <cuda_runtime.h>
#include <cuda_bf16.h>
#include <cstdint>
#include <cstddef>

#define B_ 4
#define L_ 512
#define HID_ 512
#define H_ 8
#define DH_ 64

// ---------------- scratch (device globals; no allocations allowed) ----------
__device__ float g_q[B_ * L_ * HID_];
__device__ float g_k[B_ * L_ * HID_];
__device__ float g_v[B_ * L_ * HID_];
__device__ float g_sc[B_ * H_ * L_ * L_];            // qk scores (fp32)
__device__ __nv_bfloat16 g_Xs[2048 * 1536];          // proj A split
__device__ __nv_bfloat16 g_Ws[3 * 512 * 1536];       // proj B split
__device__ __nv_bfloat16 g_qs[32 * 512 * 128];       // q split [bh][l][qh|ql]
__device__ __nv_bfloat16 g_ks[32 * 512 * 128];       // k split [bh][l][kh|kl]
__device__ __nv_bfloat16 g_ps[32 * 512 * 1024];      // probs split [bh][q][ph|pl]
__device__ __nv_bfloat16 g_vT[32 * 64 * 1024];       // v^T split [bh][d][vh|vl]

// ---------------- cp.async helpers ------------------------------------------
__device__ __forceinline__ void cp_async16(void* smem, const void* gmem) {
    unsigned s = (unsigned)__cvta_generic_to_shared(smem);
    asm volatile("cp.async.cg.shared.global [%0], [%1], 16;\n" :: "r"(s), "l"(gmem));
}
__device__ __forceinline__ void cp_commit() {
    asm volatile("cp.async.commit_group;\n");
}
template <int N>
__device__ __forceinline__ void cp_wait() {
    asm volatile("cp.async.wait_group %0;\n" :: "n"(N));
}

// ---------------- warp mma / ldmatrix (sm_80+, no 'a' feature) ---------------
__device__ __forceinline__ void mma_bf16(float& c0, float& c1, float& c2, float& c3,
                                         uint32_t a0, uint32_t a1, uint32_t a2, uint32_t a3,
                                         uint32_t b0, uint32_t b1) {
    asm volatile(
        "mma.sync.aligned.m16n8k16.row.col.f32.bf16.bf16.f32 "
        "{%0,%1,%2,%3}, {%4,%5,%6,%7}, {%8,%9}, {%0,%1,%2,%3};"
        : "+f"(c0), "+f"(c1), "+f"(c2), "+f"(c3)
        : "r"(a0), "r"(a1), "r"(a2), "r"(a3), "r"(b0), "r"(b1));
}
__device__ __forceinline__ void ldm_x4(uint32_t* r, uint32_t addr) {
    asm volatile("ldmatrix.sync.aligned.m8n8.x4.shared.b16 {%0,%1,%2,%3}, [%4];"
                 : "=r"(r[0]), "=r"(r[1]), "=r"(r[2]), "=r"(r[3]) : "r"(addr));
}
__device__ __forceinline__ void ldm_x2(uint32_t& r0, uint32_t& r1, uint32_t addr) {
    asm volatile("ldmatrix.sync.aligned.m8n8.x2.shared.b16 {%0,%1}, [%2];"
                 : "=r"(r0), "=r"(r1) : "r"(addr));
}
__device__ __forceinline__ void ldm_x2_trans(uint32_t& r0, uint32_t& r1, uint32_t addr) {
    asm volatile("ldmatrix.sync.aligned.m8n8.x2.trans.shared.b16 {%0,%1}, [%2];"
                 : "=r"(r0), "=r"(r1) : "r"(addr));
}

// =============================================================================
// K0: build split-bf16 operands for the projection, K=1536.
// =============================================================================
__global__ __launch_bounds__(256) void k_prep(
    const float* __restrict__ X,
    const float* __restrict__ Wq, const float* __restrict__ Wk,
    const float* __restrict__ Wv)
{
    const int stride = gridDim.x * blockDim.x;
    for (int i = blockIdx.x * blockDim.x + threadIdx.x; i < 2048 * 512; i += stride) {
        int m = i >> 9, k = i & 511;
        float x = X[i];
        __nv_bfloat16 hi = __float2bfloat16(x);
        __nv_bfloat16 lo = __float2bfloat16(x - __bfloat162float(hi));
        __nv_bfloat16* row = g_Xs + (size_t)m * 1536;
        row[k] = hi; row[512 + k] = lo; row[1024 + k] = hi;
    }
    for (int i = blockIdx.x * blockDim.x + threadIdx.x; i < 3 * 512 * 512; i += stride) {
        int z = i >> 18;
        int r = i & 262143;
        const float* W = (z == 0) ? Wq : (z == 1) ? Wk : Wv;
        int n = r >> 9, k = r & 511;
        float x = W[r];
        __nv_bfloat16 hi = __float2bfloat16(x);
        __nv_bfloat16 lo = __float2bfloat16(x - __bfloat162float(hi));
        __nv_bfloat16* row = g_Ws + (size_t)z * 512 * 1536 + (size_t)n * 1536;
        row[k] = hi; row[512 + k] = hi; row[1024 + k] = lo;
    }
}

// =============================================================================
// K1: QKV projection via mma.sync bf16 (unchanged, proven).
// =============================================================================
#define PADK 72
#define A_BUF_ELE (128 * PADK)
#define B_BUF_ELE (64 * PADK)
#define SMEM_PROJ ((2 * A_BUF_ELE + 2 * B_BUF_ELE) * 2 + 64 * 4)

__global__ __launch_bounds__(256) void k_proj_mma(
    const float* __restrict__ bq, const float* __restrict__ bk,
    const float* __restrict__ bv)
{
    extern __shared__ char smp[];
    __nv_bfloat16* As = (__nv_bfloat16*)smp;
    __nv_bfloat16* Bs = As + 2 * A_BUF_ELE;
    float* biasS = (float*)(Bs + 2 * B_BUF_ELE);

    const int n0 = blockIdx.x * 64;
    const int m0 = blockIdx.y * 128;
    const int z  = blockIdx.z;
    const float* bias = (z == 0) ? bq : (z == 1) ? bk : bv;
    float* C = (z == 0) ? g_q : (z == 1) ? g_k : g_v;
    const __nv_bfloat16* Wz = g_Ws + (size_t)z * 512 * 1536;

    const int tid = threadIdx.x;
    const int wid = tid >> 5, lane = tid & 31;
    const int wm = wid >> 1, wn = wid & 1;
    const int g  = lane >> 2, tg = lane & 3;

    if (tid < 64) biasS[tid] = bias[n0 + tid];

    float acc[2][4][4];
#pragma unroll
    for (int mt = 0; mt < 2; mt++)
#pragma unroll
        for (int nt = 0; nt < 4; nt++)
#pragma unroll
            for (int e = 0; e < 4; e++) acc[mt][nt][e] = 0.f;

    auto load_chunk = [&](int c, int buf) {
        __nv_bfloat16* Ad = As + buf * A_BUF_ELE;
        __nv_bfloat16* Bd = Bs + buf * B_BUF_ELE;
#pragma unroll
        for (int i = 0; i < 4; i++) {
            int flat = i * 256 + tid;
            int row = flat >> 3, seg = flat & 7;
            cp_async16(Ad + row * PADK + seg * 8,
                       g_Xs + (size_t)(m0 + row) * 1536 + c * 64 + seg * 8);
        }
#pragma unroll
        for (int i = 0; i < 2; i++) {
            int flat = i * 256 + tid;
            int row = flat >> 3, seg = flat & 7;
            cp_async16(Bd + row * PADK + seg * 8,
                       Wz + (size_t)(n0 + row) * 1536 + c * 64 + seg * 8);
        }
        cp_commit();
    };

    load_chunk(0, 0);

#pragma unroll 1
    for (int t = 0; t < 24; t++) {
        if (t < 23) load_chunk(t + 1, (t + 1) & 1);
        if (t < 23) cp_wait<1>(); else cp_wait<0>();
        __syncthreads();

        const __nv_bfloat16* Ab = As + (t & 1) * A_BUF_ELE;
        const __nv_bfloat16* Bb = Bs + (t & 1) * B_BUF_ELE;

#pragma unroll
        for (int ks = 0; ks < 4; ks++) {
            const int kb = ks * 16;
            uint32_t af[2][4], bf[4][2];
#pragma unroll
            for (int mt = 0; mt < 2; mt++) {
                int r0 = wm * 32 + mt * 16 + g;
                af[mt][0] = *(const uint32_t*)&Ab[(r0)      * PADK + kb + tg * 2];
                af[mt][1] = *(const uint32_t*)&Ab[(r0 + 8)  * PADK + kb + tg * 2];
                af[mt][2] = *(const uint32_t*)&Ab[(r0)      * PADK + kb + tg * 2 + 8];
                af[mt][3] = *(const uint32_t*)&Ab[(r0 + 8)  * PADK + kb + tg * 2 + 8];
            }
#pragma unroll
            for (int nt = 0; nt < 4; nt++) {
                int nr = wn * 32 + nt * 8 + g;
                bf[nt][0] = *(const uint32_t*)&Bb[nr * PADK + kb + tg * 2];
                bf[nt][1] = *(const uint32_t*)&Bb[nr * PADK + kb + tg * 2 + 8];
            }
#pragma unroll
            for (int mt = 0; mt < 2; mt++)
#pragma unroll
                for (int nt = 0; nt < 4; nt++)
                    mma_bf16(acc[mt][nt][0], acc[mt][nt][1], acc[mt][nt][2], acc[mt][nt][3],
                             af[mt][0], af[mt][1], af[mt][2], af[mt][3],
                             bf[nt][0], bf[nt][1]);
        }
        __syncthreads();
    }

#pragma unroll
    for (int mt = 0; mt < 2; mt++) {
        int r0 = m0 + wm * 32 + mt * 16 + g;
#pragma unroll
        for (int nt = 0; nt < 4; nt++) {
            int cl = wn * 32 + nt * 8 + tg * 2;
            float2 v0 = make_float2(acc[mt][nt][0] + biasS[cl],
                                    acc[mt][nt][1] + biasS[cl + 1]);
            float2 v1 = make_float2(acc[mt][nt][2] + biasS[cl],
                                    acc[mt][nt][3] + biasS[cl + 1]);
            *(float2*)&C[(size_t)r0 * 512 + n0 + cl] = v0;
            *(float2*)&C[(size_t)(r0 + 8) * 512 + n0 + cl] = v1;
        }
    }
}

// =============================================================================
// K1b: split q,k into bf16 hi/lo [bh][l][128] for the scores GEMM.
// =============================================================================
__global__ __launch_bounds__(256) void k_split()
{
    const int stride = gridDim.x * blockDim.x;
    for (int i = blockIdx.x * blockDim.x + threadIdx.x; i < 2097152; i += stride) {
        int which = i >> 20;
        int r = i & 1048575;
        int m = r >> 9, n = r & 511;
        int h = n >> 6, d = n & 63;
        int b = m >> 9, l = m & 511;
        float x = (which ? g_k : g_q)[r];
        __nv_bfloat16 hi = __float2bfloat16(x);
        __nv_bfloat16 lo = __float2bfloat16(x - __bfloat162float(hi));
        __nv_bfloat16* dst = (which ? g_ks : g_qs)
                           + ((size_t)(b * 8 + h) * 512 + l) * 128 + d;
        dst[0] = hi; dst[64] = lo;
    }
}

// =============================================================================
// K1c: v -> v^T split bf16 [bh][d][vh(512)|vl(512)], smem-tiled transpose.
// grid (32 bh, 8 ktile), 256 threads.
// =============================================================================
__global__ __launch_bounds__(256) void k_vsplit()
{
    __shared__ float ts[64][65];
    const int bh = blockIdx.x;
    const int k0 = blockIdx.y * 64;
    const int b = bh >> 3, h = bh & 7;
    const int tid = threadIdx.x;

    {
        int kr = tid >> 2, ds = (tid & 3) * 16;
        const float* src = g_v + ((size_t)(b * 512) + k0 + kr) * 512 + h * 64 + ds;
#pragma unroll
        for (int j = 0; j < 4; j++) {
            float4 v4 = ((const float4*)src)[j];
            ts[kr][ds + j * 4 + 0] = v4.x; ts[kr][ds + j * 4 + 1] = v4.y;
            ts[kr][ds + j * 4 + 2] = v4.z; ts[kr][ds + j * 4 + 3] = v4.w;
        }
    }
    __syncthreads();
    {
        int d = tid >> 2, ks = (tid & 3) * 16;
        union { __nv_bfloat16 bb[8]; uint4 u; } h0, h1, l0, l1;
#pragma unroll
        for (int j = 0; j < 8; j++) {
            float x = ts[ks + j][d];
            __nv_bfloat16 hb = __float2bfloat16(x);
            h0.bb[j] = hb; l0.bb[j] = __float2bfloat16(x - __bfloat162float(hb));
        }
#pragma unroll
        for (int j = 0; j < 8; j++) {
            float x = ts[ks + 8 + j][d];
            __nv_bfloat16 hb = __float2bfloat16(x);
            h1.bb[j] = hb; l1.bb[j] = __float2bfloat16(x - __bfloat162float(hb));
        }
        __nv_bfloat16* dst = g_vT + ((size_t)bh * 64 + d) * 1024 + k0 + ks;
        *(uint4*)(dst)       = h0.u;
        *(uint4*)(dst + 8)   = h1.u;
        *(uint4*)(dst + 512) = l0.u;
        *(uint4*)(dst + 520) = l1.u;
    }
}

// =============================================================================
// K2: scores = q . k^T per (b,h) via mma.sync, K = 3x64 split chunks.
// grid (8, 4, 32), 256 threads, clone of k_proj_mma.
// =============================================================================
__global__ __launch_bounds__(256) void k_scores_mma()
{
    extern __shared__ char smp[];
    __nv_bfloat16* As = (__nv_bfloat16*)smp;
    __nv_bfloat16* Bs = As + 2 * A_BUF_ELE;

    const int n0 = blockIdx.x * 64;
    const int m0 = blockIdx.y * 128;
    const int bh = blockIdx.z;
    const __nv_bfloat16* Aq = g_qs + (size_t)bh * 512 * 128;
    const __nv_bfloat16* Bk = g_ks + (size_t)bh * 512 * 128;
    float* C = g_sc + (size_t)bh * 262144;

    const int tid = threadIdx.x;
    const int wid = tid >> 5, lane = tid & 31;
    const int wm = wid >> 1, wn = wid & 1;
    const int g  = lane >> 2, tg = lane & 3;

    const int Aoff[3] = { 0, 64, 0 };
    const int Boff[3] = { 0, 0, 64 };

    float acc[2][4][4];
#pragma unroll
    for (int mt = 0; mt < 2; mt++)
#pragma unroll
        for (int nt = 0; nt < 4; nt++)
#pragma unroll
            for (int e = 0; e < 4; e++) acc[mt][nt][e] = 0.f;

    auto load_chunk = [&](int c, int buf) {
        __nv_bfloat16* Ad = As + buf * A_BUF_ELE;
        __nv_bfloat16* Bd = Bs + buf * B_BUF_ELE;
#pragma unroll
        for (int i = 0; i < 4; i++) {
            int flat = i * 256 + tid;
            int row = flat >> 3, seg = flat & 7;
            cp_async16(Ad + row * PADK + seg * 8,
                       Aq + (size_t)(m0 + row) * 128 + Aoff[c] + seg * 8);
        }
#pragma unroll
        for (int i = 0; i < 2; i++) {
            int flat = i * 256 + tid;
            int row = flat >> 3, seg = flat & 7;
            cp_async16(Bd + row * PADK + seg * 8,
                       Bk + (size_t)(n0 + row) * 128 + Boff[c] + seg * 8);
        }
        cp_commit();
    };

    load_chunk(0, 0);

#pragma unroll 1
    for (int t = 0; t < 3; t++) {
        if (t < 2) load_chunk(t + 1, (t + 1) & 1);
        if (t < 2) cp_wait<1>(); else cp_wait<0>();
        __syncthreads();

        const __nv_bfloat16* Ab = As + (t & 1) * A_BUF_ELE;
        const __nv_bfloat16* Bb = Bs + (t & 1) * B_BUF_ELE;

#pragma unroll
        for (int ks = 0; ks < 4; ks++) {
            const int kb = ks * 16;
            uint32_t af[2][4], bf[4][2];
#pragma unroll
            for (int mt = 0; mt < 2; mt++) {
                int r0 = wm * 32 + mt * 16 + g;
                af[mt][0] = *(const uint32_t*)&Ab[(r0)      * PADK + kb + tg * 2];
                af[mt][1] = *(const uint32_t*)&Ab[(r0 + 8)  * PADK + kb + tg * 2];
                af[mt][2] = *(const uint32_t*)&Ab[(r0)      * PADK + kb + tg * 2 + 8];
                af[mt][3] = *(const uint32_t*)&Ab[(r0 + 8)  * PADK + kb + tg * 2 + 8];
            }
#pragma unroll
            for (int nt = 0; nt < 4; nt++) {
                int nr = wn * 32 + nt * 8 + g;
                bf[nt][0] = *(const uint32_t*)&Bb[nr * PADK + kb + tg * 2];
                bf[nt][1] = *(const uint32_t*)&Bb[nr * PADK + kb + tg * 2 + 8];
            }
#pragma unroll
            for (int mt = 0; mt < 2; mt++)
#pragma unroll
                for (int nt = 0; nt < 4; nt++)
                    mma_bf16(acc[mt][nt][0], acc[mt][nt][1], acc[mt][nt][2], acc[mt][nt][3],
                             af[mt][0], af[mt][1], af[mt][2], af[mt][3],
                             bf[nt][0], bf[nt][1]);
        }
        __syncthreads();
    }

#pragma unroll
    for (int mt = 0; mt < 2; mt++) {
        int r0 = m0 + wm * 32 + mt * 16 + g;
#pragma unroll
        for (int nt = 0; nt < 4; nt++) {
            int cl = wn * 32 + nt * 8 + tg * 2;
            *(float2*)&C[(size_t)r0 * 512 + n0 + cl] =
                make_float2(acc[mt][nt][0], acc[mt][nt][1]);
            *(float2*)&C[(size_t)(r0 + 8) * 512 + n0 + cl] =
                make_float2(acc[mt][nt][2], acc[mt][nt][3]);
        }
    }
}

// =============================================================================
// K3: fused per-(b,q) — tensor-core, 512 threads; R9 + qk/heads prefetch +
// dual-accumulator stage B; writes probs split bf16 to g_ps (no fp32 probs).
// =============================================================================
#define F_RH 0
#define F_RL 65536
#define F_SC 131072
#define F_QS 147584
#define F_PS 151936
#define F_RED 184960
#define SMEM_FUSED (184960 + 32768)

__global__ __launch_bounds__(512) void k_fused(
    const float* __restrict__ rels,
    const float* __restrict__ heads,
    float* __restrict__ out)
{
    extern __shared__ char smf[];
    const uint32_t sbase = (uint32_t)__cvta_generic_to_shared(smf);
    float* sc_s = (float*)(smf + F_SC);
    __nv_bfloat16* QS = (__nv_bfloat16*)(smf + F_QS);
    __nv_bfloat16* PS = (__nv_bfloat16*)(smf + F_PS);
    float* red = (float*)(smf + F_RED);

    const int bq = blockIdx.x;
    const int b = bq >> 9, q = bq & 511;
    const int tid = threadIdx.x;
    const int lane = tid & 31, w = tid >> 5;

    const float* rg = rels + (size_t)bq * (512 * 64);
    const size_t hoff = ((size_t)b * 512 + q) * 512;

    // ---- q LDG + rels super-group 0 LDG + qk/heads prefetch ----
    float4 qv = make_float4(0.f, 0.f, 0.f, 0.f);
    if (tid < 128)
        qv = *(const float4*)&g_q[((size_t)b * L_ + q) * HID_ + tid * 4];

    float4 stg[2][4];
    {
        int r = tid >> 2, dseg = (tid & 3) * 16;
        const float* src = rg + (size_t)r * 64 + dseg;
#pragma unroll
        for (int j = 0; j < 4; j++) stg[0][j] = ((const float4*)src)[j];
    }

    float2 qkPre[4], hvPre[4];
    {
        int hh = lane >> 2;
        int kkb = w * 8 + (lane & 3) * 2;
#pragma unroll
        for (int sg = 0; sg < 4; sg++) {
            int kk = sg * 128 + kkb;
            qkPre[sg] = *(const float2*)&g_sc[(size_t)(b * 8 + hh) * 262144
                                              + (size_t)q * 512 + kk];
            hvPre[sg] = *(const float2*)&heads[hoff + kk];
        }
    }

    // ---- zero QS rows 8-15 and PS rows 8-15 ----
    for (int i = tid; i < 544; i += 512)
        ((uint32_t*)(smf + F_QS + 8 * 272))[i] = 0;
    for (int i = tid; i < 4128; i += 512)
        ((uint32_t*)(smf + F_PS + 8 * 2064))[i] = 0;

    // ---- build QS [qh|ql] ----
    if (tid < 128) {
        int h = tid >> 4, d = (tid & 15) * 4;
        float xs[4] = { qv.x, qv.y, qv.z, qv.w };
#pragma unroll
        for (int j = 0; j < 4; j++) {
            __nv_bfloat16 hb = __float2bfloat16(xs[j]);
            QS[h * 136 + d + j] = hb;
            QS[h * 136 + 64 + d + j] = __float2bfloat16(xs[j] - __bfloat162float(hb));
        }
    }
    __syncthreads();

    // ---- load q A-fragments once ----
    uint32_t afr[2][4][4];
#pragma unroll
    for (int s = 0; s < 2; s++)
#pragma unroll
        for (int ds = 0; ds < 4; ds++) {
            uint32_t addr = sbase + F_QS + (lane & 15) * 272
                          + (s * 64 + ds * 16 + ((lane >> 4) << 3)) * 2;
            ldm_x4(afr[s][ds], addr);
        }

    auto ldg_group = [&](int sg, float4* dst) {
        int r = sg * 128 + (tid >> 2), dseg = (tid & 3) * 16;
        const float* src = rg + (size_t)r * 64 + dseg;
#pragma unroll
        for (int j = 0; j < 4; j++) dst[j] = ((const float4*)src)[j];
    };
    auto sts_group = [&](int sg, const float4* st) {
        int rr = tid >> 2;
        int r = sg * 128 + rr;
        int c0 = (tid & 3) * 2;
        const float* xs = (const float*)st;
        union { __nv_bfloat16 bb[8]; uint4 u; } h0, h1, l0, l1;
#pragma unroll
        for (int j = 0; j < 8; j++) {
            float x = xs[j];
            __nv_bfloat16 hb = __float2bfloat16(x);
            h0.bb[j] = hb; l0.bb[j] = __float2bfloat16(x - __bfloat162float(hb));
        }
#pragma unroll
        for (int j = 0; j < 8; j++) {
            float x = xs[8 + j];
            __nv_bfloat16 hb = __float2bfloat16(x);
            h1.bb[j] = hb; l1.bb[j] = __float2bfloat16(x - __bfloat162float(hb));
        }
        char* rhrow = smf + F_RH + r * 128;
        char* rlrow = smf + F_RL + r * 128;
        int s7 = rr & 7;
        *(uint4*)(rhrow + (((c0)     ^ s7) << 4)) = h0.u;
        *(uint4*)(rhrow + (((c0 + 1) ^ s7) << 4)) = h1.u;
        *(uint4*)(rlrow + (((c0)     ^ s7) << 4)) = l0.u;
        *(uint4*)(rlrow + (((c0 + 1) ^ s7) << 4)) = l1.u;
    };

    // ---- stage B: warp w owns n-tile w; dual accumulator chains ----
    auto stageB = [&](int sg) {
        const int k0 = sg * 128 + w * 8;
        float e0 = 0.f, e1 = 0.f, e2 = 0.f, e3 = 0.f;
        float o0 = 0.f, o1 = 0.f, o2 = 0.f, o3 = 0.f;
        const int row = k0 + (lane & 7);
        const int s7 = row & 7;
        const int csel = (lane >> 3) & 1;
#pragma unroll
        for (int pass = 0; pass < 3; pass++) {
            const uint32_t rb = sbase + ((pass < 2) ? F_RH : F_RL);
            const int s = (pass == 1) ? 1 : 0;
#pragma unroll
            for (int ds = 0; ds < 4; ds++) {
                int chunk = ds * 2 + csel;
                uint32_t addr = rb + row * 128 + ((chunk ^ s7) << 4);
                uint32_t b0, b1;
                ldm_x2(b0, b1, addr);
                if (ds & 1)
                    mma_bf16(o0, o1, o2, o3,
                             afr[s][ds][0], afr[s][ds][1], afr[s][ds][2], afr[s][ds][3],
                             b0, b1);
                else
                    mma_bf16(e0, e1, e2, e3,
                             afr[s][ds][0], afr[s][ds][1], afr[s][ds][2], afr[s][ds][3],
                             b0, b1);
            }
        }
        float a0 = e0 + o0, a1 = e1 + o1;
        int h = lane >> 2, kk = k0 + (lane & 3) * 2;
        sc_s[h * 516 + kk]     = (a0 + qkPre[sg].x) * 0.125f + hvPre[sg].x;
        sc_s[h * 516 + kk + 1] = (a1 + qkPre[sg].y) * 0.125f + hvPre[sg].y;
    };

#pragma unroll 1
    for (int sg = 0; sg < 4; sg++) {
        if (sg < 3) ldg_group(sg + 1, stg[(sg + 1) & 1]);
        sts_group(sg, stg[sg & 1]);
        __syncthreads();
        stageB(sg);
    }
    __syncthreads();

    // ---- softmax (warps 0..7) + PS smem + g_ps global (bf16 split) ----
    if (w < 8) {
        float* row = sc_s + w * 516;
        float vals[16];
        float mx = -1e30f;
#pragma unroll
        for (int i = 0; i < 16; i++) { vals[i] = row[i * 32 + lane]; mx = fmaxf(mx, vals[i]); }
#pragma unroll
        for (int o = 16; o; o >>= 1) mx = fmaxf(mx, __shfl_xor_sync(0xffffffffu, mx, o));
        float s = 0.f;
#pragma unroll
        for (int i = 0; i < 16; i++) { vals[i] = __expf(vals[i] - mx); s += vals[i]; }
#pragma unroll
        for (int o = 16; o; o >>= 1) s += __shfl_xor_sync(0xffffffffu, s, o);
        float inv = 1.f / s;
        __nv_bfloat16* pgp = g_ps + ((size_t)(b * 8 + w) * 512 + q) * 1024;
#pragma unroll
        for (int i = 0; i < 16; i++) {
            float pv = vals[i] * inv;
            int kk = i * 32 + lane;
            __nv_bfloat16 ph = __float2bfloat16(pv);
            __nv_bfloat16 pl = __float2bfloat16(pv - __bfloat162float(ph));
            PS[w * 1032 + kk] = ph;
            PS[w * 1032 + 512 + kk] = pl;
            pgp[kk] = ph;
            pgp[512 + kk] = pl;
        }
    }
    __syncthreads();

    // ---- stage D: warp (kg = w>>1 of 8, ng = w&1), 4 n-tiles each ----
    {
        const int kg = w >> 1, ng = w & 1;
        float aD[4][4];
#pragma unroll
        for (int i = 0; i < 4; i++)
#pragma unroll
            for (int j = 0; j < 4; j++) aD[i][j] = 0.f;

#pragma unroll
        for (int pass = 0; pass < 3; pass++) {
            const uint32_t rb = sbase + ((pass < 2) ? F_RH : F_RL);
            const int acol = (pass == 1) ? 512 : 0;
#pragma unroll
            for (int ks = 0; ks < 4; ks++) {
                const int k0 = kg * 64 + ks * 16;
                uint32_t af[4];
                uint32_t aaddr = sbase + F_PS + (lane & 15) * 2064
                               + (acol + k0 + ((lane >> 4) << 3)) * 2;
                ldm_x4(af, aaddr);
                const int row = k0 + (lane & 7) + (((lane >> 3) & 1) << 3);
                const int s7 = row & 7;
#pragma unroll
                for (int ntl = 0; ntl < 4; ntl++) {
                    int d0 = (ng * 4 + ntl) * 8;
                    uint32_t baddr = rb + row * 128 + (((d0 >> 3) ^ s7) << 4);
                    uint32_t b0, b1;
                    ldm_x2_trans(b0, b1, baddr);
                    mma_bf16(aD[ntl][0], aD[ntl][1], aD[ntl][2], aD[ntl][3],
                             af[0], af[1], af[2], af[3], b0, b1);
                }
            }
        }
#pragma unroll
        for (int ntl = 0; ntl < 4; ntl++) {
            int slot = kg * 8 + ng * 4 + ntl;
            *(float4*)&red[(slot * 32 + lane) * 4] =
                make_float4(aD[ntl][0], aD[ntl][1], aD[ntl][2], aD[ntl][3]);
        }
    }
    __syncthreads();

    if (w < 8) {
        float rx = 0.f, ry = 0.f;
#pragma unroll
        for (int kg = 0; kg < 8; kg++) {
            float4 s = *(const float4*)&red[((kg * 8 + w) * 32 + lane) * 4];
            rx += s.x; ry += s.y;
        }
        int h = lane >> 2, d = w * 8 + (lane & 3) * 2;
        *(float2*)&out[(size_t)bq * 512 + h * 64 + d] = make_float2(rx, ry);
    }
}

// =============================================================================
// K4: ctx += probs @ v via mma.sync, K = 24x64 chunks ([ph|pl|ph]·[vh|vh|vl]).
// grid (4 mtiles, 32 bh) = 128 CTAs; RMW epilogue (disjoint tiles).
// =============================================================================
__global__ __launch_bounds__(256) void k_ctx_mma(float* __restrict__ out)
{
    extern __shared__ char smp[];
    __nv_bfloat16* As = (__nv_bfloat16*)smp;
    __nv_bfloat16* Bs = As + 2 * A_BUF_ELE;

    const int m0 = blockIdx.x * 128;
    const int bh = blockIdx.y;
    const int b = bh >> 3, h = bh & 7;
    const __nv_bfloat16* Ap = g_ps + (size_t)bh * 512 * 1024;
    const __nv_bfloat16* Bv = g_vT + (size_t)bh * 64 * 1024;

    const int tid = threadIdx.x;
    const int wid = tid >> 5, lane = tid & 31;
    const int wm = wid >> 1, wn = wid & 1;
    const int g  = lane >> 2, tg = lane & 3;

    float acc[2][4][4];
#pragma unroll
    for (int mt = 0; mt < 2; mt++)
#pragma unroll
        for (int nt = 0; nt < 4; nt++)
#pragma unroll
            for (int e = 0; e < 4; e++) acc[mt][nt][e] = 0.f;

    auto aoff = [](int t) { return t < 8 ? t * 64 : t < 16 ? 512 + (t - 8) * 64 : (t - 16) * 64; };
    auto boff = [](int t) { return t < 8 ? t * 64 : t < 16 ? (t - 8) * 64 : 512 + (t - 16) * 64; };

    auto load_chunk = [&](int c, int buf) {
        __nv_bfloat16* Ad = As + buf * A_BUF_ELE;
        __nv_bfloat16* Bd = Bs + buf * B_BUF_ELE;
        int ao = aoff(c), bo = boff(c);
#pragma unroll
        for (int i = 0; i < 4; i++) {
            int flat = i * 256 + tid;
            int row = flat >> 3, seg = flat & 7;
            cp_async16(Ad + row * PADK + seg * 8,
                       Ap + (size_t)(m0 + row) * 1024 + ao + seg * 8);
        }
#pragma unroll
        for (int i = 0; i < 2; i++) {
            int flat = i * 256 + tid;
            int row = flat >> 3, seg = flat & 7;
            cp_async16(Bd + row * PADK + seg * 8,
                       Bv + (size_t)row * 1024 + bo + seg * 8);
        }
        cp_commit();
    };

    load_chunk(0, 0);

#pragma unroll 1
    for (int t = 0; t < 24; t++) {
        if (t < 23) load_chunk(t + 1, (t + 1) & 1);
        if (t < 23) cp_wait<1>(); else cp_wait<0>();
        __syncthreads();

        const __nv_bfloat16* Ab = As + (t & 1) * A_BUF_ELE;
        const __nv_bfloat16* Bb = Bs + (t & 1) * B_BUF_ELE;

#pragma unroll
        for (int ks = 0; ks < 4; ks++) {
            const int kb = ks * 16;
            uint32_t af[2][4], bf[4][2];
#pragma unroll
            for (int mt = 0; mt < 2; mt++) {
                int r0 = wm * 32 + mt * 16 + g;
                af[mt][0] = *(const uint32_t*)&Ab[(r0)      * PADK + kb + tg * 2];
                af[mt][1] = *(const uint32_t*)&Ab[(r0 + 8)  * PADK + kb + tg * 2];
                af[mt][2] = *(const uint32_t*)&Ab[(r0)      * PADK + kb + tg * 2 + 8];
                af[mt][3] = *(const uint32_t*)&Ab[(r0 + 8)  * PADK + kb + tg * 2 + 8];
            }
#pragma unroll
            for (int nt = 0; nt < 4; nt++) {
                int nr = wn * 32 + nt * 8 + g;
                bf[nt][0] = *(const uint32_t*)&Bb[nr * PADK + kb + tg * 2];
                bf[nt][1] = *(const uint32_t*)&Bb[nr * PADK + kb + tg * 2 + 8];
            }
#pragma unroll
            for (int mt = 0; mt < 2; mt++)
#pragma unroll
                for (int nt = 0; nt < 4; nt++)
                    mma_bf16(acc[mt][nt][0], acc[mt][nt][1], acc[mt][nt][2], acc[mt][nt][3],
                             af[mt][0], af[mt][1], af[mt][2], af[mt][3],
                             bf[nt][0], bf[nt][1]);
        }
        __syncthreads();
    }

#pragma unroll
    for (int mt = 0; mt < 2; mt++) {
        int r0 = m0 + wm * 32 + mt * 16 + g;
#pragma unroll
        for (int nt = 0; nt < 4; nt++) {
            int cl = wn * 32 + nt * 8 + tg * 2;
            float* p0 = &out[((size_t)(b * 512 + r0)) * 512 + h * 64 + cl];
            float2 c0 = *(float2*)p0;
            c0.x += acc[mt][nt][0]; c0.y += acc[mt][nt][1];
            *(float2*)p0 = c0;
            float* p1 = &out[((size_t)(b * 512 + r0 + 8)) * 512 + h * 64 + cl];
            float2 c1 = *(float2*)p1;
            c1.x += acc[mt][nt][2]; c1.y += acc[mt][nt][3];
            *(float2*)p1 = c1;
        }
    }
}

// =============================================================================
extern "C" void kernel_launch(void* const* d_in, const int* in_sizes, int n_in,
                              void* d_out, int out_size)
{
    const float* hidden = (const float*)d_in[0];
    const float* heads  = (const float*)d_in[1];
    const float* rels   = (const float*)d_in[2];
    const float* Wq = (const float*)d_in[3];
    const float* bq = (const float*)d_in[4];
    const float* Wk = (const float*)d_in[5];
    const float* bk = (const float*)d_in[6];
    const float* Wv = (const float*)d_in[7];
    const float* bv = (const float*)d_in[8];
    float* out = (float*)d_out;

    k_prep<<<1024, 256>>>(hidden, Wq, Wk, Wv);

    cudaFuncSetAttribute(k_proj_mma, cudaFuncAttributeMaxDynamicSharedMemorySize, SMEM_PROJ);
    dim3 g1(8, 16, 3);
    k_proj_mma<<<g1, 256, SMEM_PROJ>>>(bq, bk, bv);

    k_split<<<2048, 256>>>();
    dim3 gv(32, 8);
    k_vsplit<<<gv, 256>>>();

    cudaFuncSetAttribute(k_scores_mma, cudaFuncAttributeMaxDynamicSharedMemorySize, SMEM_PROJ);
    dim3 g2(8, 4, 32);
    k_scores_mma<<<g2, 256, SMEM_PROJ>>>();

    cudaFuncSetAttribute(k_fused, cudaFuncAttributeMaxDynamicSharedMemorySize, SMEM_FUSED);
    k_fused<<<2048, 512, SMEM_FUSED>>>(rels, heads, out);

    cudaFuncSetAttribute(k_ctx_mma, cudaFuncAttributeMaxDynamicSharedMemorySize, SMEM_PROJ);
    dim3 g4(4, 32);
    k_ctx_mma<<<g4, 256, SMEM_PROJ>>>(out);
}

// round 11
// speedup vs baseline: 1.9594x; 1.0877x over previous
#include <cuda_runtime.h>
#include <cuda_bf16.h>
#include <cstdint>
#include <cstddef>

#define B_ 4
#define L_ 512
#define HID_ 512
#define H_ 8
#define DH_ 64

// ---------------- scratch (device globals; no allocations allowed) ----------
__device__ float g_q[B_ * L_ * HID_];
__device__ float g_k[B_ * L_ * HID_];
__device__ float g_v[B_ * L_ * HID_];
__device__ float g_sc[B_ * H_ * L_ * L_];            // qk scores (fp32)
__device__ __nv_bfloat16 g_Xs[2048 * 1536];          // proj A split
__device__ __nv_bfloat16 g_Ws[3 * 512 * 1536];       // proj B split
__device__ __nv_bfloat16 g_qs[32 * 512 * 128];       // q split [bh][l][qh|ql]
__device__ __nv_bfloat16 g_ks[32 * 512 * 128];       // k split [bh][l][kh|kl]
__device__ __nv_bfloat16 g_ps[32 * 512 * 1024];      // probs split [bh][q][ph|pl]
__device__ __nv_bfloat16 g_vT[32 * 64 * 1024];       // v^T split [bh][d][vh|vl]

// ---------------- cp.async helpers ------------------------------------------
__device__ __forceinline__ void cp_async16(void* smem, const void* gmem) {
    unsigned s = (unsigned)__cvta_generic_to_shared(smem);
    asm volatile("cp.async.cg.shared.global [%0], [%1], 16;\n" :: "r"(s), "l"(gmem));
}
__device__ __forceinline__ void cp_commit() {
    asm volatile("cp.async.commit_group;\n");
}
template <int N>
__device__ __forceinline__ void cp_wait() {
    asm volatile("cp.async.wait_group %0;\n" :: "n"(N));
}

// ---------------- warp mma / ldmatrix (sm_80+, no 'a' feature) ---------------
__device__ __forceinline__ void mma_bf16(float& c0, float& c1, float& c2, float& c3,
                                         uint32_t a0, uint32_t a1, uint32_t a2, uint32_t a3,
                                         uint32_t b0, uint32_t b1) {
    asm volatile(
        "mma.sync.aligned.m16n8k16.row.col.f32.bf16.bf16.f32 "
        "{%0,%1,%2,%3}, {%4,%5,%6,%7}, {%8,%9}, {%0,%1,%2,%3};"
        : "+f"(c0), "+f"(c1), "+f"(c2), "+f"(c3)
        : "r"(a0), "r"(a1), "r"(a2), "r"(a3), "r"(b0), "r"(b1));
}
__device__ __forceinline__ void ldm_x4(uint32_t* r, uint32_t addr) {
    asm volatile("ldmatrix.sync.aligned.m8n8.x4.shared.b16 {%0,%1,%2,%3}, [%4];"
                 : "=r"(r[0]), "=r"(r[1]), "=r"(r[2]), "=r"(r[3]) : "r"(addr));
}
__device__ __forceinline__ void ldm_x2(uint32_t& r0, uint32_t& r1, uint32_t addr) {
    asm volatile("ldmatrix.sync.aligned.m8n8.x2.shared.b16 {%0,%1}, [%2];"
                 : "=r"(r0), "=r"(r1) : "r"(addr));
}
__device__ __forceinline__ void ldm_x2_trans(uint32_t& r0, uint32_t& r1, uint32_t addr) {
    asm volatile("ldmatrix.sync.aligned.m8n8.x2.trans.shared.b16 {%0,%1}, [%2];"
                 : "=r"(r0), "=r"(r1) : "r"(addr));
}
// pack bf16x2 with lower = a, upper = b
__device__ __forceinline__ uint32_t cvt_bf16x2(float a, float b) {
    uint32_t w;
    asm("cvt.rn.bf16x2.f32 %0, %1, %2;" : "=r"(w) : "f"(b), "f"(a));
    return w;
}

// =============================================================================
// K0: build split-bf16 operands for the projection, K=1536.
// =============================================================================
__global__ __launch_bounds__(256) void k_prep(
    const float* __restrict__ X,
    const float* __restrict__ Wq, const float* __restrict__ Wk,
    const float* __restrict__ Wv)
{
    const int stride = gridDim.x * blockDim.x;
    for (int i = blockIdx.x * blockDim.x + threadIdx.x; i < 2048 * 512; i += stride) {
        int m = i >> 9, k = i & 511;
        float x = X[i];
        __nv_bfloat16 hi = __float2bfloat16(x);
        __nv_bfloat16 lo = __float2bfloat16(x - __bfloat162float(hi));
        __nv_bfloat16* row = g_Xs + (size_t)m * 1536;
        row[k] = hi; row[512 + k] = lo; row[1024 + k] = hi;
    }
    for (int i = blockIdx.x * blockDim.x + threadIdx.x; i < 3 * 512 * 512; i += stride) {
        int z = i >> 18;
        int r = i & 262143;
        const float* W = (z == 0) ? Wq : (z == 1) ? Wk : Wv;
        int n = r >> 9, k = r & 511;
        float x = W[r];
        __nv_bfloat16 hi = __float2bfloat16(x);
        __nv_bfloat16 lo = __float2bfloat16(x - __bfloat162float(hi));
        __nv_bfloat16* row = g_Ws + (size_t)z * 512 * 1536 + (size_t)n * 1536;
        row[k] = hi; row[512 + k] = hi; row[1024 + k] = lo;
    }
}

// =============================================================================
// K1: QKV projection via mma.sync bf16 (unchanged, proven).
// =============================================================================
#define PADK 72
#define A_BUF_ELE (128 * PADK)
#define B_BUF_ELE (64 * PADK)
#define SMEM_PROJ ((2 * A_BUF_ELE + 2 * B_BUF_ELE) * 2 + 64 * 4)

__global__ __launch_bounds__(256) void k_proj_mma(
    const float* __restrict__ bq, const float* __restrict__ bk,
    const float* __restrict__ bv)
{
    extern __shared__ char smp[];
    __nv_bfloat16* As = (__nv_bfloat16*)smp;
    __nv_bfloat16* Bs = As + 2 * A_BUF_ELE;
    float* biasS = (float*)(Bs + 2 * B_BUF_ELE);

    const int n0 = blockIdx.x * 64;
    const int m0 = blockIdx.y * 128;
    const int z  = blockIdx.z;
    const float* bias = (z == 0) ? bq : (z == 1) ? bk : bv;
    float* C = (z == 0) ? g_q : (z == 1) ? g_k : g_v;
    const __nv_bfloat16* Wz = g_Ws + (size_t)z * 512 * 1536;

    const int tid = threadIdx.x;
    const int wid = tid >> 5, lane = tid & 31;
    const int wm = wid >> 1, wn = wid & 1;
    const int g  = lane >> 2, tg = lane & 3;

    if (tid < 64) biasS[tid] = bias[n0 + tid];

    float acc[2][4][4];
#pragma unroll
    for (int mt = 0; mt < 2; mt++)
#pragma unroll
        for (int nt = 0; nt < 4; nt++)
#pragma unroll
            for (int e = 0; e < 4; e++) acc[mt][nt][e] = 0.f;

    auto load_chunk = [&](int c, int buf) {
        __nv_bfloat16* Ad = As + buf * A_BUF_ELE;
        __nv_bfloat16* Bd = Bs + buf * B_BUF_ELE;
#pragma unroll
        for (int i = 0; i < 4; i++) {
            int flat = i * 256 + tid;
            int row = flat >> 3, seg = flat & 7;
            cp_async16(Ad + row * PADK + seg * 8,
                       g_Xs + (size_t)(m0 + row) * 1536 + c * 64 + seg * 8);
        }
#pragma unroll
        for (int i = 0; i < 2; i++) {
            int flat = i * 256 + tid;
            int row = flat >> 3, seg = flat & 7;
            cp_async16(Bd + row * PADK + seg * 8,
                       Wz + (size_t)(n0 + row) * 1536 + c * 64 + seg * 8);
        }
        cp_commit();
    };

    load_chunk(0, 0);

#pragma unroll 1
    for (int t = 0; t < 24; t++) {
        if (t < 23) load_chunk(t + 1, (t + 1) & 1);
        if (t < 23) cp_wait<1>(); else cp_wait<0>();
        __syncthreads();

        const __nv_bfloat16* Ab = As + (t & 1) * A_BUF_ELE;
        const __nv_bfloat16* Bb = Bs + (t & 1) * B_BUF_ELE;

#pragma unroll
        for (int ks = 0; ks < 4; ks++) {
            const int kb = ks * 16;
            uint32_t af[2][4], bf[4][2];
#pragma unroll
            for (int mt = 0; mt < 2; mt++) {
                int r0 = wm * 32 + mt * 16 + g;
                af[mt][0] = *(const uint32_t*)&Ab[(r0)      * PADK + kb + tg * 2];
                af[mt][1] = *(const uint32_t*)&Ab[(r0 + 8)  * PADK + kb + tg * 2];
                af[mt][2] = *(const uint32_t*)&Ab[(r0)      * PADK + kb + tg * 2 + 8];
                af[mt][3] = *(const uint32_t*)&Ab[(r0 + 8)  * PADK + kb + tg * 2 + 8];
            }
#pragma unroll
            for (int nt = 0; nt < 4; nt++) {
                int nr = wn * 32 + nt * 8 + g;
                bf[nt][0] = *(const uint32_t*)&Bb[nr * PADK + kb + tg * 2];
                bf[nt][1] = *(const uint32_t*)&Bb[nr * PADK + kb + tg * 2 + 8];
            }
#pragma unroll
            for (int mt = 0; mt < 2; mt++)
#pragma unroll
                for (int nt = 0; nt < 4; nt++)
                    mma_bf16(acc[mt][nt][0], acc[mt][nt][1], acc[mt][nt][2], acc[mt][nt][3],
                             af[mt][0], af[mt][1], af[mt][2], af[mt][3],
                             bf[nt][0], bf[nt][1]);
        }
        __syncthreads();
    }

#pragma unroll
    for (int mt = 0; mt < 2; mt++) {
        int r0 = m0 + wm * 32 + mt * 16 + g;
#pragma unroll
        for (int nt = 0; nt < 4; nt++) {
            int cl = wn * 32 + nt * 8 + tg * 2;
            float2 v0 = make_float2(acc[mt][nt][0] + biasS[cl],
                                    acc[mt][nt][1] + biasS[cl + 1]);
            float2 v1 = make_float2(acc[mt][nt][2] + biasS[cl],
                                    acc[mt][nt][3] + biasS[cl + 1]);
            *(float2*)&C[(size_t)r0 * 512 + n0 + cl] = v0;
            *(float2*)&C[(size_t)(r0 + 8) * 512 + n0 + cl] = v1;
        }
    }
}

// =============================================================================
// K1b: split q,k into bf16 hi/lo [bh][l][128] for the scores GEMM.
// =============================================================================
__global__ __launch_bounds__(256) void k_split()
{
    const int stride = gridDim.x * blockDim.x;
    for (int i = blockIdx.x * blockDim.x + threadIdx.x; i < 2097152; i += stride) {
        int which = i >> 20;
        int r = i & 1048575;
        int m = r >> 9, n = r & 511;
        int h = n >> 6, d = n & 63;
        int b = m >> 9, l = m & 511;
        float x = (which ? g_k : g_q)[r];
        __nv_bfloat16 hi = __float2bfloat16(x);
        __nv_bfloat16 lo = __float2bfloat16(x - __bfloat162float(hi));
        __nv_bfloat16* dst = (which ? g_ks : g_qs)
                           + ((size_t)(b * 8 + h) * 512 + l) * 128 + d;
        dst[0] = hi; dst[64] = lo;
    }
}

// =============================================================================
// K1c: v -> v^T split bf16 [bh][d][vh(512)|vl(512)], smem-tiled transpose.
// =============================================================================
__global__ __launch_bounds__(256) void k_vsplit()
{
    __shared__ float ts[64][65];
    const int bh = blockIdx.x;
    const int k0 = blockIdx.y * 64;
    const int b = bh >> 3, h = bh & 7;
    const int tid = threadIdx.x;

    {
        int kr = tid >> 2, ds = (tid & 3) * 16;
        const float* src = g_v + ((size_t)(b * 512) + k0 + kr) * 512 + h * 64 + ds;
#pragma unroll
        for (int j = 0; j < 4; j++) {
            float4 v4 = ((const float4*)src)[j];
            ts[kr][ds + j * 4 + 0] = v4.x; ts[kr][ds + j * 4 + 1] = v4.y;
            ts[kr][ds + j * 4 + 2] = v4.z; ts[kr][ds + j * 4 + 3] = v4.w;
        }
    }
    __syncthreads();
    {
        int d = tid >> 2, ks = (tid & 3) * 16;
        union { __nv_bfloat16 bb[8]; uint4 u; } h0, h1, l0, l1;
#pragma unroll
        for (int j = 0; j < 8; j++) {
            float x = ts[ks + j][d];
            __nv_bfloat16 hb = __float2bfloat16(x);
            h0.bb[j] = hb; l0.bb[j] = __float2bfloat16(x - __bfloat162float(hb));
        }
#pragma unroll
        for (int j = 0; j < 8; j++) {
            float x = ts[ks + 8 + j][d];
            __nv_bfloat16 hb = __float2bfloat16(x);
            h1.bb[j] = hb; l1.bb[j] = __float2bfloat16(x - __bfloat162float(hb));
        }
        __nv_bfloat16* dst = g_vT + ((size_t)bh * 64 + d) * 1024 + k0 + ks;
        *(uint4*)(dst)       = h0.u;
        *(uint4*)(dst + 8)   = h1.u;
        *(uint4*)(dst + 512) = l0.u;
        *(uint4*)(dst + 520) = l1.u;
    }
}

// =============================================================================
// K2: scores = q . k^T per (b,h) via mma.sync, K = 3x64 split chunks.
// =============================================================================
__global__ __launch_bounds__(256) void k_scores_mma()
{
    extern __shared__ char smp[];
    __nv_bfloat16* As = (__nv_bfloat16*)smp;
    __nv_bfloat16* Bs = As + 2 * A_BUF_ELE;

    const int n0 = blockIdx.x * 64;
    const int m0 = blockIdx.y * 128;
    const int bh = blockIdx.z;
    const __nv_bfloat16* Aq = g_qs + (size_t)bh * 512 * 128;
    const __nv_bfloat16* Bk = g_ks + (size_t)bh * 512 * 128;
    float* C = g_sc + (size_t)bh * 262144;

    const int tid = threadIdx.x;
    const int wid = tid >> 5, lane = tid & 31;
    const int wm = wid >> 1, wn = wid & 1;
    const int g  = lane >> 2, tg = lane & 3;

    const int Aoff[3] = { 0, 64, 0 };
    const int Boff[3] = { 0, 0, 64 };

    float acc[2][4][4];
#pragma unroll
    for (int mt = 0; mt < 2; mt++)
#pragma unroll
        for (int nt = 0; nt < 4; nt++)
#pragma unroll
            for (int e = 0; e < 4; e++) acc[mt][nt][e] = 0.f;

    auto load_chunk = [&](int c, int buf) {
        __nv_bfloat16* Ad = As + buf * A_BUF_ELE;
        __nv_bfloat16* Bd = Bs + buf * B_BUF_ELE;
#pragma unroll
        for (int i = 0; i < 4; i++) {
            int flat = i * 256 + tid;
            int row = flat >> 3, seg = flat & 7;
            cp_async16(Ad + row * PADK + seg * 8,
                       Aq + (size_t)(m0 + row) * 128 + Aoff[c] + seg * 8);
        }
#pragma unroll
        for (int i = 0; i < 2; i++) {
            int flat = i * 256 + tid;
            int row = flat >> 3, seg = flat & 7;
            cp_async16(Bd + row * PADK + seg * 8,
                       Bk + (size_t)(n0 + row) * 128 + Boff[c] + seg * 8);
        }
        cp_commit();
    };

    load_chunk(0, 0);

#pragma unroll 1
    for (int t = 0; t < 3; t++) {
        if (t < 2) load_chunk(t + 1, (t + 1) & 1);
        if (t < 2) cp_wait<1>(); else cp_wait<0>();
        __syncthreads();

        const __nv_bfloat16* Ab = As + (t & 1) * A_BUF_ELE;
        const __nv_bfloat16* Bb = Bs + (t & 1) * B_BUF_ELE;

#pragma unroll
        for (int ks = 0; ks < 4; ks++) {
            const int kb = ks * 16;
            uint32_t af[2][4], bf[4][2];
#pragma unroll
            for (int mt = 0; mt < 2; mt++) {
                int r0 = wm * 32 + mt * 16 + g;
                af[mt][0] = *(const uint32_t*)&Ab[(r0)      * PADK + kb + tg * 2];
                af[mt][1] = *(const uint32_t*)&Ab[(r0 + 8)  * PADK + kb + tg * 2];
                af[mt][2] = *(const uint32_t*)&Ab[(r0)      * PADK + kb + tg * 2 + 8];
                af[mt][3] = *(const uint32_t*)&Ab[(r0 + 8)  * PADK + kb + tg * 2 + 8];
            }
#pragma unroll
            for (int nt = 0; nt < 4; nt++) {
                int nr = wn * 32 + nt * 8 + g;
                bf[nt][0] = *(const uint32_t*)&Bb[nr * PADK + kb + tg * 2];
                bf[nt][1] = *(const uint32_t*)&Bb[nr * PADK + kb + tg * 2 + 8];
            }
#pragma unroll
            for (int mt = 0; mt < 2; mt++)
#pragma unroll
                for (int nt = 0; nt < 4; nt++)
                    mma_bf16(acc[mt][nt][0], acc[mt][nt][1], acc[mt][nt][2], acc[mt][nt][3],
                             af[mt][0], af[mt][1], af[mt][2], af[mt][3],
                             bf[nt][0], bf[nt][1]);
        }
        __syncthreads();
    }

#pragma unroll
    for (int mt = 0; mt < 2; mt++) {
        int r0 = m0 + wm * 32 + mt * 16 + g;
#pragma unroll
        for (int nt = 0; nt < 4; nt++) {
            int cl = wn * 32 + nt * 8 + tg * 2;
            *(float2*)&C[(size_t)r0 * 512 + n0 + cl] =
                make_float2(acc[mt][nt][0], acc[mt][nt][1]);
            *(float2*)&C[(size_t)(r0 + 8) * 512 + n0 + cl] =
                make_float2(acc[mt][nt][2], acc[mt][nt][3]);
        }
    }
}

// =============================================================================
// K3: fused per-(b,q) — tensor-core with [hi;lo] M-packing (2 passes, not 3).
// QS rows 0-7 = q_hi, rows 8-15 = q_lo.  PS rows 0-7 = p_hi, 8-15 = p_lo.
// score/ctx = (c0+c2, c1+c3).  512 threads.
// =============================================================================
#define F_RH 0
#define F_RL 65536
#define F_SC 131072                  // float [8][516] = 16512
#define F_QS 147584                  // bf16 [16][136] = 4352
#define F_PS 151936                  // bf16 [16][520] = 16640
#define F_RED 168576                 // float2 [64][32] = 16384
#define SMEM_FUSED 184960

__global__ __launch_bounds__(512) void k_fused(
    const float* __restrict__ rels,
    const float* __restrict__ heads,
    float* __restrict__ out)
{
    extern __shared__ char smf[];
    const uint32_t sbase = (uint32_t)__cvta_generic_to_shared(smf);
    float* sc_s = (float*)(smf + F_SC);
    __nv_bfloat16* QS = (__nv_bfloat16*)(smf + F_QS);
    __nv_bfloat16* PS = (__nv_bfloat16*)(smf + F_PS);
    float* red = (float*)(smf + F_RED);

    const int bq = blockIdx.x;
    const int b = bq >> 9, q = bq & 511;
    const int tid = threadIdx.x;
    const int lane = tid & 31, w = tid >> 5;

    const float* rg = rels + (size_t)bq * (512 * 64);
    const size_t hoff = ((size_t)b * 512 + q) * 512;

    // ---- q LDG + rels super-group 0 LDG + qk/heads prefetch ----
    float4 qv = make_float4(0.f, 0.f, 0.f, 0.f);
    if (tid < 128)
        qv = *(const float4*)&g_q[((size_t)b * L_ + q) * HID_ + tid * 4];

    float4 stg[2][4];
    {
        int r = tid >> 2, dseg = (tid & 3) * 16;
        const float* src = rg + (size_t)r * 64 + dseg;
#pragma unroll
        for (int j = 0; j < 4; j++) stg[0][j] = ((const float4*)src)[j];
    }

    float2 qkPre[4], hvPre[4];
    {
        int hh = lane >> 2;
        int kkb = w * 8 + (lane & 3) * 2;
#pragma unroll
        for (int sg = 0; sg < 4; sg++) {
            int kk = sg * 128 + kkb;
            qkPre[sg] = *(const float2*)&g_sc[(size_t)(b * 8 + hh) * 262144
                                              + (size_t)q * 512 + kk];
            hvPre[sg] = *(const float2*)&heads[hoff + kk];
        }
    }

    // ---- build QS: rows 0-7 = hi, rows 8-15 = lo ----
    if (tid < 128) {
        int h = tid >> 4, d = (tid & 15) * 4;
        float xs[4] = { qv.x, qv.y, qv.z, qv.w };
#pragma unroll
        for (int j = 0; j < 4; j++) {
            __nv_bfloat16 hb = __float2bfloat16(xs[j]);
            QS[h * 136 + d + j] = hb;
            QS[(h + 8) * 136 + d + j] = __float2bfloat16(xs[j] - __bfloat162float(hb));
        }
    }
    __syncthreads();

    // ---- load q A-fragments once (K=64 -> 4 fragments) ----
    uint32_t afr[4][4];
#pragma unroll
    for (int ds = 0; ds < 4; ds++) {
        uint32_t addr = sbase + F_QS + (lane & 15) * 272
                      + (ds * 16 + ((lane >> 4) << 3)) * 2;
        ldm_x4(afr[ds], addr);
    }

    auto ldg_group = [&](int sg, float4* dst) {
        int r = sg * 128 + (tid >> 2), dseg = (tid & 3) * 16;
        const float* src = rg + (size_t)r * 64 + dseg;
#pragma unroll
        for (int j = 0; j < 4; j++) dst[j] = ((const float4*)src)[j];
    };
    // PRMT-based split: hi = truncation (upper 16 bits), lo = exact remainder
    auto sts_group = [&](int sg, const float4* st) {
        int rr = tid >> 2;
        int r = sg * 128 + rr;
        int c0 = (tid & 3) * 2;
        const float* xs = (const float*)st;
        uint32_t hw[8], lw[8];
#pragma unroll
        for (int j = 0; j < 8; j++) {
            float x0 = xs[2 * j], x1 = xs[2 * j + 1];
            uint32_t u0 = __float_as_uint(x0), u1 = __float_as_uint(x1);
            hw[j] = __byte_perm(u0, u1, 0x7632);
            float h0f = __uint_as_float(u0 & 0xFFFF0000u);
            float h1f = __uint_as_float(u1 & 0xFFFF0000u);
            lw[j] = cvt_bf16x2(x0 - h0f, x1 - h1f);
        }
        char* rhrow = smf + F_RH + r * 128;
        char* rlrow = smf + F_RL + r * 128;
        int s7 = rr & 7;
        *(uint4*)(rhrow + (((c0)     ^ s7) << 4)) = make_uint4(hw[0], hw[1], hw[2], hw[3]);
        *(uint4*)(rhrow + (((c0 + 1) ^ s7) << 4)) = make_uint4(hw[4], hw[5], hw[6], hw[7]);
        *(uint4*)(rlrow + (((c0)     ^ s7) << 4)) = make_uint4(lw[0], lw[1], lw[2], lw[3]);
        *(uint4*)(rlrow + (((c0 + 1) ^ s7) << 4)) = make_uint4(lw[4], lw[5], lw[6], lw[7]);
    };

    // ---- stage B: warp w owns n-tile w; 2 passes (rh full, rl hi-only) ----
    auto stageB = [&](int sg) {
        const int k0 = sg * 128 + w * 8;
        float p0c0 = 0.f, p0c1 = 0.f, p0c2 = 0.f, p0c3 = 0.f;
        float p1c0 = 0.f, p1c1 = 0.f, p1c2 = 0.f, p1c3 = 0.f;
        const int row = k0 + (lane & 7);
        const int s7 = row & 7;
        const int csel = (lane >> 3) & 1;
#pragma unroll
        for (int ds = 0; ds < 4; ds++) {
            int chunk = ds * 2 + csel;
            uint32_t b0, b1;
            ldm_x2(b0, b1, sbase + F_RH + row * 128 + ((chunk ^ s7) << 4));
            mma_bf16(p0c0, p0c1, p0c2, p0c3,
                     afr[ds][0], afr[ds][1], afr[ds][2], afr[ds][3], b0, b1);
        }
#pragma unroll
        for (int ds = 0; ds < 4; ds++) {
            int chunk = ds * 2 + csel;
            uint32_t b0, b1;
            ldm_x2(b0, b1, sbase + F_RL + row * 128 + ((chunk ^ s7) << 4));
            mma_bf16(p1c0, p1c1, p1c2, p1c3,
                     afr[ds][0], 0u, afr[ds][2], 0u, b0, b1);
        }
        float a0 = p0c0 + p0c2 + p1c0;      // qh*rh + ql*rh + qh*rl
        float a1 = p0c1 + p0c3 + p1c1;
        int h = lane >> 2, kk = k0 + (lane & 3) * 2;
        sc_s[h * 516 + kk]     = (a0 + qkPre[sg].x) * 0.125f + hvPre[sg].x;
        sc_s[h * 516 + kk + 1] = (a1 + qkPre[sg].y) * 0.125f + hvPre[sg].y;
    };

#pragma unroll 1
    for (int sg = 0; sg < 4; sg++) {
        if (sg < 3) ldg_group(sg + 1, stg[(sg + 1) & 1]);
        sts_group(sg, stg[sg & 1]);
        __syncthreads();
        stageB(sg);
    }
    __syncthreads();

    // ---- softmax (warps 0..7) + PS rows [hi; lo] + g_ps global ----
    if (w < 8) {
        float* row = sc_s + w * 516;
        float vals[16];
        float mx = -1e30f;
#pragma unroll
        for (int i = 0; i < 16; i++) { vals[i] = row[i * 32 + lane]; mx = fmaxf(mx, vals[i]); }
#pragma unroll
        for (int o = 16; o; o >>= 1) mx = fmaxf(mx, __shfl_xor_sync(0xffffffffu, mx, o));
        float s = 0.f;
#pragma unroll
        for (int i = 0; i < 16; i++) { vals[i] = __expf(vals[i] - mx); s += vals[i]; }
#pragma unroll
        for (int o = 16; o; o >>= 1) s += __shfl_xor_sync(0xffffffffu, s, o);
        float inv = 1.f / s;
        __nv_bfloat16* pgp = g_ps + ((size_t)(b * 8 + w) * 512 + q) * 1024;
#pragma unroll
        for (int i = 0; i < 16; i++) {
            float pv = vals[i] * inv;
            int kk = i * 32 + lane;
            __nv_bfloat16 ph = __float2bfloat16(pv);
            __nv_bfloat16 pl = __float2bfloat16(pv - __bfloat162float(ph));
            PS[w * 520 + kk] = ph;
            PS[(w + 8) * 520 + kk] = pl;
            pgp[kk] = ph;
            pgp[512 + kk] = pl;
        }
    }
    __syncthreads();

    // ---- stage D: warp (kg = w>>1 of 8, ng = w&1), 4 n-tiles; 2 passes ----
    {
        const int kg = w >> 1, ng = w & 1;
        float aD[4][4];
#pragma unroll
        for (int i = 0; i < 4; i++)
#pragma unroll
            for (int j = 0; j < 4; j++) aD[i][j] = 0.f;

#pragma unroll
        for (int ks = 0; ks < 4; ks++) {
            const int k0 = kg * 64 + ks * 16;
            uint32_t af[4];
            uint32_t aaddr = sbase + F_PS + (lane & 15) * 1040
                           + (k0 + ((lane >> 4) << 3)) * 2;
            ldm_x4(af, aaddr);
            const int row = k0 + (lane & 7) + (((lane >> 3) & 1) << 3);
            const int s7 = row & 7;
#pragma unroll
            for (int ntl = 0; ntl < 4; ntl++) {
                int d0 = (ng * 4 + ntl) * 8;
                uint32_t b0, b1;
                ldm_x2_trans(b0, b1, sbase + F_RH + row * 128 + (((d0 >> 3) ^ s7) << 4));
                mma_bf16(aD[ntl][0], aD[ntl][1], aD[ntl][2], aD[ntl][3],
                         af[0], af[1], af[2], af[3], b0, b1);
            }
#pragma unroll
            for (int ntl = 0; ntl < 4; ntl++) {
                int d0 = (ng * 4 + ntl) * 8;
                uint32_t b0, b1;
                ldm_x2_trans(b0, b1, sbase + F_RL + row * 128 + (((d0 >> 3) ^ s7) << 4));
                mma_bf16(aD[ntl][0], aD[ntl][1], aD[ntl][2], aD[ntl][3],
                         af[0], 0u, af[2], 0u, b0, b1);
            }
        }
#pragma unroll
        for (int ntl = 0; ntl < 4; ntl++) {
            int slot = kg * 8 + ng * 4 + ntl;
            *(float2*)&red[(slot * 32 + lane) * 2] =
                make_float2(aD[ntl][0] + aD[ntl][2], aD[ntl][1] + aD[ntl][3]);
        }
    }
    __syncthreads();

    if (w < 8) {
        float rx = 0.f, ry = 0.f;
#pragma unroll
        for (int kg = 0; kg < 8; kg++) {
            float2 s = *(const float2*)&red[((kg * 8 + w) * 32 + lane) * 2];
            rx += s.x; ry += s.y;
        }
        int h = lane >> 2, d = w * 8 + (lane & 3) * 2;
        *(float2*)&out[(size_t)bq * 512 + h * 64 + d] = make_float2(rx, ry);
    }
}

// =============================================================================
// K4: ctx += probs @ v via mma.sync, K-split x2 (12 chunks each), atomicAdd.
// grid (4 mtiles, 32 bh, 2 ksplit) = 256 CTAs.
// =============================================================================
__global__ __launch_bounds__(256) void k_ctx_mma(float* __restrict__ out)
{
    extern __shared__ char smp[];
    __nv_bfloat16* As = (__nv_bfloat16*)smp;
    __nv_bfloat16* Bs = As + 2 * A_BUF_ELE;

    const int m0 = blockIdx.x * 128;
    const int bh = blockIdx.y;
    const int tbase = blockIdx.z * 12;
    const int b = bh >> 3, h = bh & 7;
    const __nv_bfloat16* Ap = g_ps + (size_t)bh * 512 * 1024;
    const __nv_bfloat16* Bv = g_vT + (size_t)bh * 64 * 1024;

    const int tid = threadIdx.x;
    const int wid = tid >> 5, lane = tid & 31;
    const int wm = wid >> 1, wn = wid & 1;
    const int g  = lane >> 2, tg = lane & 3;

    float acc[2][4][4];
#pragma unroll
    for (int mt = 0; mt < 2; mt++)
#pragma unroll
        for (int nt = 0; nt < 4; nt++)
#pragma unroll
            for (int e = 0; e < 4; e++) acc[mt][nt][e] = 0.f;

    auto aoff = [](int t) { return t < 8 ? t * 64 : t < 16 ? 512 + (t - 8) * 64 : (t - 16) * 64; };
    auto boff = [](int t) { return t < 8 ? t * 64 : t < 16 ? (t - 8) * 64 : 512 + (t - 16) * 64; };

    auto load_chunk = [&](int c, int buf) {
        __nv_bfloat16* Ad = As + buf * A_BUF_ELE;
        __nv_bfloat16* Bd = Bs + buf * B_BUF_ELE;
        int ao = aoff(c), bo = boff(c);
#pragma unroll
        for (int i = 0; i < 4; i++) {
            int flat = i * 256 + tid;
            int row = flat >> 3, seg = flat & 7;
            cp_async16(Ad + row * PADK + seg * 8,
                       Ap + (size_t)(m0 + row) * 1024 + ao + seg * 8);
        }
#pragma unroll
        for (int i = 0; i < 2; i++) {
            int flat = i * 256 + tid;
            int row = flat >> 3, seg = flat & 7;
            cp_async16(Bd + row * PADK + seg * 8,
                       Bv + (size_t)row * 1024 + bo + seg * 8);
        }
        cp_commit();
    };

    load_chunk(tbase, 0);

#pragma unroll 1
    for (int t = 0; t < 12; t++) {
        if (t < 11) load_chunk(tbase + t + 1, (t + 1) & 1);
        if (t < 11) cp_wait<1>(); else cp_wait<0>();
        __syncthreads();

        const __nv_bfloat16* Ab = As + (t & 1) * A_BUF_ELE;
        const __nv_bfloat16* Bb = Bs + (t & 1) * B_BUF_ELE;

#pragma unroll
        for (int ks = 0; ks < 4; ks++) {
            const int kb = ks * 16;
            uint32_t af[2][4], bf[4][2];
#pragma unroll
            for (int mt = 0; mt < 2; mt++) {
                int r0 = wm * 32 + mt * 16 + g;
                af[mt][0] = *(const uint32_t*)&Ab[(r0)      * PADK + kb + tg * 2];
                af[mt][1] = *(const uint32_t*)&Ab[(r0 + 8)  * PADK + kb + tg * 2];
                af[mt][2] = *(const uint32_t*)&Ab[(r0)      * PADK + kb + tg * 2 + 8];
                af[mt][3] = *(const uint32_t*)&Ab[(r0 + 8)  * PADK + kb + tg * 2 + 8];
            }
#pragma unroll
            for (int nt = 0; nt < 4; nt++) {
                int nr = wn * 32 + nt * 8 + g;
                bf[nt][0] = *(const uint32_t*)&Bb[nr * PADK + kb + tg * 2];
                bf[nt][1] = *(const uint32_t*)&Bb[nr * PADK + kb + tg * 2 + 8];
            }
#pragma unroll
            for (int mt = 0; mt < 2; mt++)
#pragma unroll
                for (int nt = 0; nt < 4; nt++)
                    mma_bf16(acc[mt][nt][0], acc[mt][nt][1], acc[mt][nt][2], acc[mt][nt][3],
                             af[mt][0], af[mt][1], af[mt][2], af[mt][3],
                             bf[nt][0], bf[nt][1]);
        }
        __syncthreads();
    }

#pragma unroll
    for (int mt = 0; mt < 2; mt++) {
        int r0 = m0 + wm * 32 + mt * 16 + g;
#pragma unroll
        for (int nt = 0; nt < 4; nt++) {
            int cl = wn * 32 + nt * 8 + tg * 2;
            float* p0 = &out[((size_t)(b * 512 + r0)) * 512 + h * 64 + cl];
            atomicAdd(p0 + 0, acc[mt][nt][0]);
            atomicAdd(p0 + 1, acc[mt][nt][1]);
            float* p1 = &out[((size_t)(b * 512 + r0 + 8)) * 512 + h * 64 + cl];
            atomicAdd(p1 + 0, acc[mt][nt][2]);
            atomicAdd(p1 + 1, acc[mt][nt][3]);
        }
    }
}

// =============================================================================
extern "C" void kernel_launch(void* const* d_in, const int* in_sizes, int n_in,
                              void* d_out, int out_size)
{
    const float* hidden = (const float*)d_in[0];
    const float* heads  = (const float*)d_in[1];
    const float* rels   = (const float*)d_in[2];
    const float* Wq = (const float*)d_in[3];
    const float* bq = (const float*)d_in[4];
    const float* Wk = (const float*)d_in[5];
    const float* bk = (const float*)d_in[6];
    const float* Wv = (const float*)d_in[7];
    const float* bv = (const float*)d_in[8];
    float* out = (float*)d_out;

    k_prep<<<1024, 256>>>(hidden, Wq, Wk, Wv);

    cudaFuncSetAttribute(k_proj_mma, cudaFuncAttributeMaxDynamicSharedMemorySize, SMEM_PROJ);
    dim3 g1(8, 16, 3);
    k_proj_mma<<<g1, 256, SMEM_PROJ>>>(bq, bk, bv);

    k_split<<<2048, 256>>>();
    dim3 gv(32, 8);
    k_vsplit<<<gv, 256>>>();

    cudaFuncSetAttribute(k_scores_mma, cudaFuncAttributeMaxDynamicSharedMemorySize, SMEM_PROJ);
    dim3 g2(8, 4, 32);
    k_scores_mma<<<g2, 256, SMEM_PROJ>>>();

    cudaFuncSetAttribute(k_fused, cudaFuncAttributeMaxDynamicSharedMemorySize, SMEM_FUSED);
    k_fused<<<2048, 512, SMEM_FUSED>>>(rels, heads, out);

    cudaFuncSetAttribute(k_ctx_mma, cudaFuncAttributeMaxDynamicSharedMemorySize, SMEM_PROJ);
    dim3 g4(4, 32, 2);
    k_ctx_mma<<<g4, 256, SMEM_PROJ>>>(out);
}

// round 12
// speedup vs baseline: 2.1640x; 1.1044x over previous
#include <cuda_runtime.h>
#include <cuda_bf16.h>
#include <cstdint>
#include <cstddef>

#define B_ 4
#define L_ 512
#define HID_ 512
#define H_ 8
#define DH_ 64

// ---------------- scratch (device globals; no allocations allowed) ----------
__device__ float g_v[B_ * L_ * HID_];
__device__ float g_sc[B_ * H_ * L_ * L_];            // qk scores (fp32)
__device__ __nv_bfloat16 g_Xs[2048 * 1536];          // proj A split
__device__ __nv_bfloat16 g_Ws[3 * 512 * 1536];       // proj B split
__device__ __nv_bfloat16 g_qs[32 * 512 * 128];       // q split [bh][l][qh|ql]
__device__ __nv_bfloat16 g_ks[32 * 512 * 128];       // k split [bh][l][kh|kl]
__device__ __nv_bfloat16 g_ps[32 * 512 * 1024];      // probs split [bh][q][ph|pl]
__device__ __nv_bfloat16 g_vT[32 * 64 * 1024];       // v^T split [bh][d][vh|vl]

// ---------------- cp.async helpers ------------------------------------------
__device__ __forceinline__ void cp_async16(void* smem, const void* gmem) {
    unsigned s = (unsigned)__cvta_generic_to_shared(smem);
    asm volatile("cp.async.cg.shared.global [%0], [%1], 16;\n" :: "r"(s), "l"(gmem));
}
__device__ __forceinline__ void cp_commit() {
    asm volatile("cp.async.commit_group;\n");
}
template <int N>
__device__ __forceinline__ void cp_wait() {
    asm volatile("cp.async.wait_group %0;\n" :: "n"(N));
}

// ---------------- warp mma / ldmatrix (sm_80+, no 'a' feature) ---------------
__device__ __forceinline__ void mma_bf16(float& c0, float& c1, float& c2, float& c3,
                                         uint32_t a0, uint32_t a1, uint32_t a2, uint32_t a3,
                                         uint32_t b0, uint32_t b1) {
    asm volatile(
        "mma.sync.aligned.m16n8k16.row.col.f32.bf16.bf16.f32 "
        "{%0,%1,%2,%3}, {%4,%5,%6,%7}, {%8,%9}, {%0,%1,%2,%3};"
        : "+f"(c0), "+f"(c1), "+f"(c2), "+f"(c3)
        : "r"(a0), "r"(a1), "r"(a2), "r"(a3), "r"(b0), "r"(b1));
}
__device__ __forceinline__ void ldm_x4(uint32_t* r, uint32_t addr) {
    asm volatile("ldmatrix.sync.aligned.m8n8.x4.shared.b16 {%0,%1,%2,%3}, [%4];"
                 : "=r"(r[0]), "=r"(r[1]), "=r"(r[2]), "=r"(r[3]) : "r"(addr));
}
__device__ __forceinline__ void ldm_x2(uint32_t& r0, uint32_t& r1, uint32_t addr) {
    asm volatile("ldmatrix.sync.aligned.m8n8.x2.shared.b16 {%0,%1}, [%2];"
                 : "=r"(r0), "=r"(r1) : "r"(addr));
}
__device__ __forceinline__ void ldm_x2_trans(uint32_t& r0, uint32_t& r1, uint32_t addr) {
    asm volatile("ldmatrix.sync.aligned.m8n8.x2.trans.shared.b16 {%0,%1}, [%2];"
                 : "=r"(r0), "=r"(r1) : "r"(addr));
}
__device__ __forceinline__ uint32_t cvt_bf16x2(float a, float b) {
    uint32_t w;
    asm("cvt.rn.bf16x2.f32 %0, %1, %2;" : "=r"(w) : "f"(b), "f"(a));
    return w;
}

// =============================================================================
// K0: build split-bf16 operands for the projection, K=1536.
// =============================================================================
__global__ __launch_bounds__(256) void k_prep(
    const float* __restrict__ X,
    const float* __restrict__ Wq, const float* __restrict__ Wk,
    const float* __restrict__ Wv)
{
    const int stride = gridDim.x * blockDim.x;
    for (int i = blockIdx.x * blockDim.x + threadIdx.x; i < 2048 * 512; i += stride) {
        int m = i >> 9, k = i & 511;
        float x = X[i];
        __nv_bfloat16 hi = __float2bfloat16(x);
        __nv_bfloat16 lo = __float2bfloat16(x - __bfloat162float(hi));
        __nv_bfloat16* row = g_Xs + (size_t)m * 1536;
        row[k] = hi; row[512 + k] = lo; row[1024 + k] = hi;
    }
    for (int i = blockIdx.x * blockDim.x + threadIdx.x; i < 3 * 512 * 512; i += stride) {
        int z = i >> 18;
        int r = i & 262143;
        const float* W = (z == 0) ? Wq : (z == 1) ? Wk : Wv;
        int n = r >> 9, k = r & 511;
        float x = W[r];
        __nv_bfloat16 hi = __float2bfloat16(x);
        __nv_bfloat16 lo = __float2bfloat16(x - __bfloat162float(hi));
        __nv_bfloat16* row = g_Ws + (size_t)z * 512 * 1536 + (size_t)n * 1536;
        row[k] = hi; row[512 + k] = hi; row[1024 + k] = lo;
    }
}

// =============================================================================
// K1: QKV projection via mma.sync.  z=0/1 write split bf16 q/k directly to
// g_qs/g_ks (no fp32 intermediate); z=2 writes fp32 v.
// =============================================================================
#define PADK 72
#define A_BUF_ELE (128 * PADK)
#define B_BUF_ELE (64 * PADK)
#define SMEM_PROJ ((2 * A_BUF_ELE + 2 * B_BUF_ELE) * 2 + 64 * 4)

__global__ __launch_bounds__(256) void k_proj_mma(
    const float* __restrict__ bq, const float* __restrict__ bk,
    const float* __restrict__ bv)
{
    extern __shared__ char smp[];
    __nv_bfloat16* As = (__nv_bfloat16*)smp;
    __nv_bfloat16* Bs = As + 2 * A_BUF_ELE;
    float* biasS = (float*)(Bs + 2 * B_BUF_ELE);

    const int n0 = blockIdx.x * 64;
    const int m0 = blockIdx.y * 128;
    const int z  = blockIdx.z;
    const float* bias = (z == 0) ? bq : (z == 1) ? bk : bv;
    const __nv_bfloat16* Wz = g_Ws + (size_t)z * 512 * 1536;

    const int tid = threadIdx.x;
    const int wid = tid >> 5, lane = tid & 31;
    const int wm = wid >> 1, wn = wid & 1;
    const int g  = lane >> 2, tg = lane & 3;

    if (tid < 64) biasS[tid] = bias[n0 + tid];

    float acc[2][4][4];
#pragma unroll
    for (int mt = 0; mt < 2; mt++)
#pragma unroll
        for (int nt = 0; nt < 4; nt++)
#pragma unroll
            for (int e = 0; e < 4; e++) acc[mt][nt][e] = 0.f;

    auto load_chunk = [&](int c, int buf) {
        __nv_bfloat16* Ad = As + buf * A_BUF_ELE;
        __nv_bfloat16* Bd = Bs + buf * B_BUF_ELE;
#pragma unroll
        for (int i = 0; i < 4; i++) {
            int flat = i * 256 + tid;
            int row = flat >> 3, seg = flat & 7;
            cp_async16(Ad + row * PADK + seg * 8,
                       g_Xs + (size_t)(m0 + row) * 1536 + c * 64 + seg * 8);
        }
#pragma unroll
        for (int i = 0; i < 2; i++) {
            int flat = i * 256 + tid;
            int row = flat >> 3, seg = flat & 7;
            cp_async16(Bd + row * PADK + seg * 8,
                       Wz + (size_t)(n0 + row) * 1536 + c * 64 + seg * 8);
        }
        cp_commit();
    };

    load_chunk(0, 0);

#pragma unroll 1
    for (int t = 0; t < 24; t++) {
        if (t < 23) load_chunk(t + 1, (t + 1) & 1);
        if (t < 23) cp_wait<1>(); else cp_wait<0>();
        __syncthreads();

        const __nv_bfloat16* Ab = As + (t & 1) * A_BUF_ELE;
        const __nv_bfloat16* Bb = Bs + (t & 1) * B_BUF_ELE;

#pragma unroll
        for (int ks = 0; ks < 4; ks++) {
            const int kb = ks * 16;
            uint32_t af[2][4], bf[4][2];
#pragma unroll
            for (int mt = 0; mt < 2; mt++) {
                int r0 = wm * 32 + mt * 16 + g;
                af[mt][0] = *(const uint32_t*)&Ab[(r0)      * PADK + kb + tg * 2];
                af[mt][1] = *(const uint32_t*)&Ab[(r0 + 8)  * PADK + kb + tg * 2];
                af[mt][2] = *(const uint32_t*)&Ab[(r0)      * PADK + kb + tg * 2 + 8];
                af[mt][3] = *(const uint32_t*)&Ab[(r0 + 8)  * PADK + kb + tg * 2 + 8];
            }
#pragma unroll
            for (int nt = 0; nt < 4; nt++) {
                int nr = wn * 32 + nt * 8 + g;
                bf[nt][0] = *(const uint32_t*)&Bb[nr * PADK + kb + tg * 2];
                bf[nt][1] = *(const uint32_t*)&Bb[nr * PADK + kb + tg * 2 + 8];
            }
#pragma unroll
            for (int mt = 0; mt < 2; mt++)
#pragma unroll
                for (int nt = 0; nt < 4; nt++)
                    mma_bf16(acc[mt][nt][0], acc[mt][nt][1], acc[mt][nt][2], acc[mt][nt][3],
                             af[mt][0], af[mt][1], af[mt][2], af[mt][3],
                             bf[nt][0], bf[nt][1]);
        }
        __syncthreads();
    }

    const int hh = n0 >> 6;                 // head (n0 is 64-aligned)
    __nv_bfloat16* QK = (z == 0) ? g_qs : g_ks;

#pragma unroll
    for (int mt = 0; mt < 2; mt++) {
        int r0 = m0 + wm * 32 + mt * 16 + g;
#pragma unroll
        for (int nt = 0; nt < 4; nt++) {
            int cl = wn * 32 + nt * 8 + tg * 2;
            float x00 = acc[mt][nt][0] + biasS[cl];
            float x01 = acc[mt][nt][1] + biasS[cl + 1];
            float x10 = acc[mt][nt][2] + biasS[cl];
            float x11 = acc[mt][nt][3] + biasS[cl + 1];
            if (z == 2) {
                *(float2*)&g_v[(size_t)r0 * 512 + n0 + cl] = make_float2(x00, x01);
                *(float2*)&g_v[(size_t)(r0 + 8) * 512 + n0 + cl] = make_float2(x10, x11);
            } else {
                int b0 = r0 >> 9, l0 = r0 & 511;
                int b1 = (r0 + 8) >> 9, l1 = (r0 + 8) & 511;
                __nv_bfloat16* d0 = QK + ((size_t)(b0 * 8 + hh) * 512 + l0) * 128 + cl;
                __nv_bfloat16* d1 = QK + ((size_t)(b1 * 8 + hh) * 512 + l1) * 128 + cl;
                __nv_bfloat16 h00 = __float2bfloat16(x00), h01 = __float2bfloat16(x01);
                __nv_bfloat16 h10 = __float2bfloat16(x10), h11 = __float2bfloat16(x11);
                *(uint32_t*)d0 = ((uint32_t)__bfloat16_as_ushort(h01) << 16)
                               | __bfloat16_as_ushort(h00);
                *(uint32_t*)d1 = ((uint32_t)__bfloat16_as_ushort(h11) << 16)
                               | __bfloat16_as_ushort(h10);
                *(uint32_t*)(d0 + 64) = cvt_bf16x2(x00 - __bfloat162float(h00),
                                                   x01 - __bfloat162float(h01));
                *(uint32_t*)(d1 + 64) = cvt_bf16x2(x10 - __bfloat162float(h10),
                                                   x11 - __bfloat162float(h11));
            }
        }
    }
}

// =============================================================================
// K1c: v -> v^T split bf16 [bh][d][vh(512)|vl(512)], smem-tiled transpose.
// =============================================================================
__global__ __launch_bounds__(256) void k_vsplit()
{
    __shared__ float ts[64][65];
    const int bh = blockIdx.x;
    const int k0 = blockIdx.y * 64;
    const int b = bh >> 3, h = bh & 7;
    const int tid = threadIdx.x;

    {
        int kr = tid >> 2, ds = (tid & 3) * 16;
        const float* src = g_v + ((size_t)(b * 512) + k0 + kr) * 512 + h * 64 + ds;
#pragma unroll
        for (int j = 0; j < 4; j++) {
            float4 v4 = ((const float4*)src)[j];
            ts[kr][ds + j * 4 + 0] = v4.x; ts[kr][ds + j * 4 + 1] = v4.y;
            ts[kr][ds + j * 4 + 2] = v4.z; ts[kr][ds + j * 4 + 3] = v4.w;
        }
    }
    __syncthreads();
    {
        int d = tid >> 2, ks = (tid & 3) * 16;
        union { __nv_bfloat16 bb[8]; uint4 u; } h0, h1, l0, l1;
#pragma unroll
        for (int j = 0; j < 8; j++) {
            float x = ts[ks + j][d];
            __nv_bfloat16 hb = __float2bfloat16(x);
            h0.bb[j] = hb; l0.bb[j] = __float2bfloat16(x - __bfloat162float(hb));
        }
#pragma unroll
        for (int j = 0; j < 8; j++) {
            float x = ts[ks + 8 + j][d];
            __nv_bfloat16 hb = __float2bfloat16(x);
            h1.bb[j] = hb; l1.bb[j] = __float2bfloat16(x - __bfloat162float(hb));
        }
        __nv_bfloat16* dst = g_vT + ((size_t)bh * 64 + d) * 1024 + k0 + ks;
        *(uint4*)(dst)       = h0.u;
        *(uint4*)(dst + 8)   = h1.u;
        *(uint4*)(dst + 512) = l0.u;
        *(uint4*)(dst + 520) = l1.u;
    }
}

// =============================================================================
// K2: scores = q . k^T per (b,h) via mma.sync, K = 3x64 split chunks.
// =============================================================================
__global__ __launch_bounds__(256) void k_scores_mma()
{
    extern __shared__ char smp[];
    __nv_bfloat16* As = (__nv_bfloat16*)smp;
    __nv_bfloat16* Bs = As + 2 * A_BUF_ELE;

    const int n0 = blockIdx.x * 64;
    const int m0 = blockIdx.y * 128;
    const int bh = blockIdx.z;
    const __nv_bfloat16* Aq = g_qs + (size_t)bh * 512 * 128;
    const __nv_bfloat16* Bk = g_ks + (size_t)bh * 512 * 128;
    float* C = g_sc + (size_t)bh * 262144;

    const int tid = threadIdx.x;
    const int wid = tid >> 5, lane = tid & 31;
    const int wm = wid >> 1, wn = wid & 1;
    const int g  = lane >> 2, tg = lane & 3;

    const int Aoff[3] = { 0, 64, 0 };
    const int Boff[3] = { 0, 0, 64 };

    float acc[2][4][4];
#pragma unroll
    for (int mt = 0; mt < 2; mt++)
#pragma unroll
        for (int nt = 0; nt < 4; nt++)
#pragma unroll
            for (int e = 0; e < 4; e++) acc[mt][nt][e] = 0.f;

    auto load_chunk = [&](int c, int buf) {
        __nv_bfloat16* Ad = As + buf * A_BUF_ELE;
        __nv_bfloat16* Bd = Bs + buf * B_BUF_ELE;
#pragma unroll
        for (int i = 0; i < 4; i++) {
            int flat = i * 256 + tid;
            int row = flat >> 3, seg = flat & 7;
            cp_async16(Ad + row * PADK + seg * 8,
                       Aq + (size_t)(m0 + row) * 128 + Aoff[c] + seg * 8);
        }
#pragma unroll
        for (int i = 0; i < 2; i++) {
            int flat = i * 256 + tid;
            int row = flat >> 3, seg = flat & 7;
            cp_async16(Bd + row * PADK + seg * 8,
                       Bk + (size_t)(n0 + row) * 128 + Boff[c] + seg * 8);
        }
        cp_commit();
    };

    load_chunk(0, 0);

#pragma unroll 1
    for (int t = 0; t < 3; t++) {
        if (t < 2) load_chunk(t + 1, (t + 1) & 1);
        if (t < 2) cp_wait<1>(); else cp_wait<0>();
        __syncthreads();

        const __nv_bfloat16* Ab = As + (t & 1) * A_BUF_ELE;
        const __nv_bfloat16* Bb = Bs + (t & 1) * B_BUF_ELE;

#pragma unroll
        for (int ks = 0; ks < 4; ks++) {
            const int kb = ks * 16;
            uint32_t af[2][4], bf[4][2];
#pragma unroll
            for (int mt = 0; mt < 2; mt++) {
                int r0 = wm * 32 + mt * 16 + g;
                af[mt][0] = *(const uint32_t*)&Ab[(r0)      * PADK + kb + tg * 2];
                af[mt][1] = *(const uint32_t*)&Ab[(r0 + 8)  * PADK + kb + tg * 2];
                af[mt][2] = *(const uint32_t*)&Ab[(r0)      * PADK + kb + tg * 2 + 8];
                af[mt][3] = *(const uint32_t*)&Ab[(r0 + 8)  * PADK + kb + tg * 2 + 8];
            }
#pragma unroll
            for (int nt = 0; nt < 4; nt++) {
                int nr = wn * 32 + nt * 8 + g;
                bf[nt][0] = *(const uint32_t*)&Bb[nr * PADK + kb + tg * 2];
                bf[nt][1] = *(const uint32_t*)&Bb[nr * PADK + kb + tg * 2 + 8];
            }
#pragma unroll
            for (int mt = 0; mt < 2; mt++)
#pragma unroll
                for (int nt = 0; nt < 4; nt++)
                    mma_bf16(acc[mt][nt][0], acc[mt][nt][1], acc[mt][nt][2], acc[mt][nt][3],
                             af[mt][0], af[mt][1], af[mt][2], af[mt][3],
                             bf[nt][0], bf[nt][1]);
        }
        __syncthreads();
    }

#pragma unroll
    for (int mt = 0; mt < 2; mt++) {
        int r0 = m0 + wm * 32 + mt * 16 + g;
#pragma unroll
        for (int nt = 0; nt < 4; nt++) {
            int cl = wn * 32 + nt * 8 + tg * 2;
            *(float2*)&C[(size_t)r0 * 512 + n0 + cl] =
                make_float2(acc[mt][nt][0], acc[mt][nt][1]);
            *(float2*)&C[(size_t)(r0 + 8) * 512 + n0 + cl] =
                make_float2(acc[mt][nt][2], acc[mt][nt][3]);
        }
    }
}

// =============================================================================
// K3: fused per-(b,q) — tensor-core [hi;lo] packing; 2 SUPERGROUPS of 256 rows
// (fewer syncs, longer latency-hiding window).  512 threads.
// =============================================================================
#define F_RH 0
#define F_RL 65536
#define F_SC 131072                  // float [8][516]
#define F_QS 147584                  // bf16 [16][136]
#define F_PS 151936                  // bf16 [16][520]
#define F_RED 168576                 // float2 [64][32]
#define SMEM_FUSED 184960

__global__ __launch_bounds__(512) void k_fused(
    const float* __restrict__ rels,
    const float* __restrict__ heads,
    float* __restrict__ out)
{
    extern __shared__ char smf[];
    const uint32_t sbase = (uint32_t)__cvta_generic_to_shared(smf);
    float* sc_s = (float*)(smf + F_SC);
    __nv_bfloat16* QS = (__nv_bfloat16*)(smf + F_QS);
    __nv_bfloat16* PS = (__nv_bfloat16*)(smf + F_PS);
    float* red = (float*)(smf + F_RED);

    const int bq = blockIdx.x;
    const int b = bq >> 9, q = bq & 511;
    const int tid = threadIdx.x;
    const int lane = tid & 31, w = tid >> 5;

    const float* rg = rels + (size_t)bq * (512 * 64);
    const size_t hoff = ((size_t)b * 512 + q) * 512;

    // ---- rels super-group 0 LDG (256 rows; 8 float4/thread) ----
    float4 stg[8];
    {
        int r = tid >> 1, f0 = (tid & 1) * 8;
        const float4* src = (const float4*)(rg + (size_t)r * 64) + f0;
#pragma unroll
        for (int j = 0; j < 8; j++) stg[j] = src[j];
    }

    // ---- qk/heads prefetch ----
    float2 qkPre[4], hvPre[4];
    {
        int hh = lane >> 2;
        int kkb = w * 8 + (lane & 3) * 2;
#pragma unroll
        for (int sgh = 0; sgh < 4; sgh++) {
            int kk = sgh * 128 + kkb;
            qkPre[sgh] = *(const float2*)&g_sc[(size_t)(b * 8 + hh) * 262144
                                               + (size_t)q * 512 + kk];
            hvPre[sgh] = *(const float2*)&heads[hoff + kk];
        }
    }

    // ---- build QS from g_qs (hi/lo precomputed) ----
    if (tid < 128) {
        int h = tid >> 4, dq = tid & 15;
        const __nv_bfloat16* src = g_qs + ((size_t)(b * 8 + h) * 512 + q) * 128 + dq * 4;
        *(uint2*)&QS[h * 136 + dq * 4]       = *(const uint2*)src;
        *(uint2*)&QS[(h + 8) * 136 + dq * 4] = *(const uint2*)(src + 64);
    }
    __syncthreads();

    // ---- load q A-fragments once ----
    uint32_t afr[4][4];
#pragma unroll
    for (int ds = 0; ds < 4; ds++) {
        uint32_t addr = sbase + F_QS + (lane & 15) * 272
                      + (ds * 16 + ((lane >> 4) << 3)) * 2;
        ldm_x4(afr[ds], addr);
    }

    auto ldg_group = [&](int sg) {
        int r = sg * 256 + (tid >> 1), f0 = (tid & 1) * 8;
        const float4* src = (const float4*)(rg + (size_t)r * 64) + f0;
#pragma unroll
        for (int j = 0; j < 8; j++) stg[j] = src[j];
    };
    auto sts_group = [&](int sg) {
        int rr = tid >> 1;
        int r = sg * 256 + rr;
        int c0 = (tid & 1) * 4;
        char* rhrow = smf + F_RH + r * 128;
        char* rlrow = smf + F_RL + r * 128;
        int s7 = rr & 7;
#pragma unroll
        for (int jj = 0; jj < 4; jj++) {
            const float* xs = (const float*)&stg[jj * 2];
            uint32_t hw[4], lw[4];
#pragma unroll
            for (int j = 0; j < 4; j++) {
                float x0 = xs[2 * j], x1 = xs[2 * j + 1];
                uint32_t u0 = __float_as_uint(x0), u1 = __float_as_uint(x1);
                hw[j] = __byte_perm(u0, u1, 0x7632);
                float h0f = __uint_as_float(u0 & 0xFFFF0000u);
                float h1f = __uint_as_float(u1 & 0xFFFF0000u);
                lw[j] = cvt_bf16x2(x0 - h0f, x1 - h1f);
            }
            int chunk = c0 + jj;
            *(uint4*)(rhrow + ((chunk ^ s7) << 4)) = make_uint4(hw[0], hw[1], hw[2], hw[3]);
            *(uint4*)(rlrow + ((chunk ^ s7) << 4)) = make_uint4(lw[0], lw[1], lw[2], lw[3]);
        }
    };

    // ---- stage B: warp w owns 2 n-tiles per supergroup ----
    auto stageB = [&](int sg) {
#pragma unroll
        for (int half = 0; half < 2; half++) {
            const int sgh = sg * 2 + half;
            const int k0 = sgh * 128 + w * 8;
            float p0c0 = 0.f, p0c1 = 0.f, p0c2 = 0.f, p0c3 = 0.f;
            float p1c0 = 0.f, p1c1 = 0.f, p1c2 = 0.f, p1c3 = 0.f;
            const int row = k0 + (lane & 7);
            const int s7 = row & 7;
            const int csel = (lane >> 3) & 1;
#pragma unroll
            for (int ds = 0; ds < 4; ds++) {
                int chunk = ds * 2 + csel;
                uint32_t b0, b1;
                ldm_x2(b0, b1, sbase + F_RH + row * 128 + ((chunk ^ s7) << 4));
                mma_bf16(p0c0, p0c1, p0c2, p0c3,
                         afr[ds][0], afr[ds][1], afr[ds][2], afr[ds][3], b0, b1);
            }
#pragma unroll
            for (int ds = 0; ds < 4; ds++) {
                int chunk = ds * 2 + csel;
                uint32_t b0, b1;
                ldm_x2(b0, b1, sbase + F_RL + row * 128 + ((chunk ^ s7) << 4));
                mma_bf16(p1c0, p1c1, p1c2, p1c3,
                         afr[ds][0], 0u, afr[ds][2], 0u, b0, b1);
            }
            float a0 = p0c0 + p0c2 + p1c0;
            float a1 = p0c1 + p0c3 + p1c1;
            int h = lane >> 2, kk = k0 + (lane & 3) * 2;
            sc_s[h * 516 + kk]     = (a0 + qkPre[sgh].x) * 0.125f + hvPre[sgh].x;
            sc_s[h * 516 + kk + 1] = (a1 + qkPre[sgh].y) * 0.125f + hvPre[sgh].y;
        }
    };

    // ---- 2 supergroups ----
    sts_group(0);
    ldg_group(1);
    __syncthreads();
    stageB(0);
    sts_group(1);
    __syncthreads();
    stageB(1);
    __syncthreads();

    // ---- softmax (warps 0..7) + PS rows [hi; lo] + g_ps global ----
    if (w < 8) {
        float* row = sc_s + w * 516;
        float vals[16];
        float mx = -1e30f;
#pragma unroll
        for (int i = 0; i < 16; i++) { vals[i] = row[i * 32 + lane]; mx = fmaxf(mx, vals[i]); }
#pragma unroll
        for (int o = 16; o; o >>= 1) mx = fmaxf(mx, __shfl_xor_sync(0xffffffffu, mx, o));
        float s = 0.f;
#pragma unroll
        for (int i = 0; i < 16; i++) { vals[i] = __expf(vals[i] - mx); s += vals[i]; }
#pragma unroll
        for (int o = 16; o; o >>= 1) s += __shfl_xor_sync(0xffffffffu, s, o);
        float inv = 1.f / s;
        __nv_bfloat16* pgp = g_ps + ((size_t)(b * 8 + w) * 512 + q) * 1024;
#pragma unroll
        for (int i = 0; i < 16; i++) {
            float pv = vals[i] * inv;
            int kk = i * 32 + lane;
            __nv_bfloat16 ph = __float2bfloat16(pv);
            __nv_bfloat16 pl = __float2bfloat16(pv - __bfloat162float(ph));
            PS[w * 520 + kk] = ph;
            PS[(w + 8) * 520 + kk] = pl;
            pgp[kk] = ph;
            pgp[512 + kk] = pl;
        }
    }
    __syncthreads();

    // ---- stage D: warp (kg = w>>1 of 8, ng = w&1), 4 n-tiles; 2 passes ----
    {
        const int kg = w >> 1, ng = w & 1;
        float aD[4][4];
#pragma unroll
        for (int i = 0; i < 4; i++)
#pragma unroll
            for (int j = 0; j < 4; j++) aD[i][j] = 0.f;

#pragma unroll
        for (int ks = 0; ks < 4; ks++) {
            const int k0 = kg * 64 + ks * 16;
            uint32_t af[4];
            uint32_t aaddr = sbase + F_PS + (lane & 15) * 1040
                           + (k0 + ((lane >> 4) << 3)) * 2;
            ldm_x4(af, aaddr);
            const int row = k0 + (lane & 7) + (((lane >> 3) & 1) << 3);
            const int s7 = row & 7;
#pragma unroll
            for (int ntl = 0; ntl < 4; ntl++) {
                int d0 = (ng * 4 + ntl) * 8;
                uint32_t b0, b1;
                ldm_x2_trans(b0, b1, sbase + F_RH + row * 128 + (((d0 >> 3) ^ s7) << 4));
                mma_bf16(aD[ntl][0], aD[ntl][1], aD[ntl][2], aD[ntl][3],
                         af[0], af[1], af[2], af[3], b0, b1);
            }
#pragma unroll
            for (int ntl = 0; ntl < 4; ntl++) {
                int d0 = (ng * 4 + ntl) * 8;
                uint32_t b0, b1;
                ldm_x2_trans(b0, b1, sbase + F_RL + row * 128 + (((d0 >> 3) ^ s7) << 4));
                mma_bf16(aD[ntl][0], aD[ntl][1], aD[ntl][2], aD[ntl][3],
                         af[0], 0u, af[2], 0u, b0, b1);
            }
        }
#pragma unroll
        for (int ntl = 0; ntl < 4; ntl++) {
            int slot = kg * 8 + ng * 4 + ntl;
            *(float2*)&red[(slot * 32 + lane) * 2] =
                make_float2(aD[ntl][0] + aD[ntl][2], aD[ntl][1] + aD[ntl][3]);
        }
    }
    __syncthreads();

    if (w < 8) {
        float rx = 0.f, ry = 0.f;
#pragma unroll
        for (int kg = 0; kg < 8; kg++) {
            float2 s = *(const float2*)&red[((kg * 8 + w) * 32 + lane) * 2];
            rx += s.x; ry += s.y;
        }
        int h = lane >> 2, d = w * 8 + (lane & 3) * 2;
        *(float2*)&out[(size_t)bq * 512 + h * 64 + d] = make_float2(rx, ry);
    }
}

// =============================================================================
// K4: ctx += probs @ v via mma.sync, K-split x2 (12 chunks each), atomicAdd.
// =============================================================================
__global__ __launch_bounds__(256) void k_ctx_mma(float* __restrict__ out)
{
    extern __shared__ char smp[];
    __nv_bfloat16* As = (__nv_bfloat16*)smp;
    __nv_bfloat16* Bs = As + 2 * A_BUF_ELE;

    const int m0 = blockIdx.x * 128;
    const int bh = blockIdx.y;
    const int tbase = blockIdx.z * 12;
    const int b = bh >> 3, h = bh & 7;
    const __nv_bfloat16* Ap = g_ps + (size_t)bh * 512 * 1024;
    const __nv_bfloat16* Bv = g_vT + (size_t)bh * 64 * 1024;

    const int tid = threadIdx.x;
    const int wid = tid >> 5, lane = tid & 31;
    const int wm = wid >> 1, wn = wid & 1;
    const int g  = lane >> 2, tg = lane & 3;

    float acc[2][4][4];
#pragma unroll
    for (int mt = 0; mt < 2; mt++)
#pragma unroll
        for (int nt = 0; nt < 4; nt++)
#pragma unroll
            for (int e = 0; e < 4; e++) acc[mt][nt][e] = 0.f;

    auto aoff = [](int t) { return t < 8 ? t * 64 : t < 16 ? 512 + (t - 8) * 64 : (t - 16) * 64; };
    auto boff = [](int t) { return t < 8 ? t * 64 : t < 16 ? (t - 8) * 64 : 512 + (t - 16) * 64; };

    auto load_chunk = [&](int c, int buf) {
        __nv_bfloat16* Ad = As + buf * A_BUF_ELE;
        __nv_bfloat16* Bd = Bs + buf * B_BUF_ELE;
        int ao = aoff(c), bo = boff(c);
#pragma unroll
        for (int i = 0; i < 4; i++) {
            int flat = i * 256 + tid;
            int row = flat >> 3, seg = flat & 7;
            cp_async16(Ad + row * PADK + seg * 8,
                       Ap + (size_t)(m0 + row) * 1024 + ao + seg * 8);
        }
#pragma unroll
        for (int i = 0; i < 2; i++) {
            int flat = i * 256 + tid;
            int row = flat >> 3, seg = flat & 7;
            cp_async16(Bd + row * PADK + seg * 8,
                       Bv + (size_t)row * 1024 + bo + seg * 8);
        }
        cp_commit();
    };

    load_chunk(tbase, 0);

#pragma unroll 1
    for (int t = 0; t < 12; t++) {
        if (t < 11) load_chunk(tbase + t + 1, (t + 1) & 1);
        if (t < 11) cp_wait<1>(); else cp_wait<0>();
        __syncthreads();

        const __nv_bfloat16* Ab = As + (t & 1) * A_BUF_ELE;
        const __nv_bfloat16* Bb = Bs + (t & 1) * B_BUF_ELE;

#pragma unroll
        for (int ks = 0; ks < 4; ks++) {
            const int kb = ks * 16;
            uint32_t af[2][4], bf[4][2];
#pragma unroll
            for (int mt = 0; mt < 2; mt++) {
                int r0 = wm * 32 + mt * 16 + g;
                af[mt][0] = *(const uint32_t*)&Ab[(r0)      * PADK + kb + tg * 2];
                af[mt][1] = *(const uint32_t*)&Ab[(r0 + 8)  * PADK + kb + tg * 2];
                af[mt][2] = *(const uint32_t*)&Ab[(r0)      * PADK + kb + tg * 2 + 8];
                af[mt][3] = *(const uint32_t*)&Ab[(r0 + 8)  * PADK + kb + tg * 2 + 8];
            }
#pragma unroll
            for (int nt = 0; nt < 4; nt++) {
                int nr = wn * 32 + nt * 8 + g;
                bf[nt][0] = *(const uint32_t*)&Bb[nr * PADK + kb + tg * 2];
                bf[nt][1] = *(const uint32_t*)&Bb[nr * PADK + kb + tg * 2 + 8];
            }
#pragma unroll
            for (int mt = 0; mt < 2; mt++)
#pragma unroll
                for (int nt = 0; nt < 4; nt++)
                    mma_bf16(acc[mt][nt][0], acc[mt][nt][1], acc[mt][nt][2], acc[mt][nt][3],
                             af[mt][0], af[mt][1], af[mt][2], af[mt][3],
                             bf[nt][0], bf[nt][1]);
        }
        __syncthreads();
    }

#pragma unroll
    for (int mt = 0; mt < 2; mt++) {
        int r0 = m0 + wm * 32 + mt * 16 + g;
#pragma unroll
        for (int nt = 0; nt < 4; nt++) {
            int cl = wn * 32 + nt * 8 + tg * 2;
            float* p0 = &out[((size_t)(b * 512 + r0)) * 512 + h * 64 + cl];
            atomicAdd(p0 + 0, acc[mt][nt][0]);
            atomicAdd(p0 + 1, acc[mt][nt][1]);
            float* p1 = &out[((size_t)(b * 512 + r0 + 8)) * 512 + h * 64 + cl];
            atomicAdd(p1 + 0, acc[mt][nt][2]);
            atomicAdd(p1 + 1, acc[mt][nt][3]);
        }
    }
}

// =============================================================================
extern "C" void kernel_launch(void* const* d_in, const int* in_sizes, int n_in,
                              void* d_out, int out_size)
{
    const float* hidden = (const float*)d_in[0];
    const float* heads  = (const float*)d_in[1];
    const float* rels   = (const float*)d_in[2];
    const float* Wq = (const float*)d_in[3];
    const float* bq = (const float*)d_in[4];
    const float* Wk = (const float*)d_in[5];
    const float* bk = (const float*)d_in[6];
    const float* Wv = (const float*)d_in[7];
    const float* bv = (const float*)d_in[8];
    float* out = (float*)d_out;

    k_prep<<<1024, 256>>>(hidden, Wq, Wk, Wv);

    cudaFuncSetAttribute(k_proj_mma, cudaFuncAttributeMaxDynamicSharedMemorySize, SMEM_PROJ);
    dim3 g1(8, 16, 3);
    k_proj_mma<<<g1, 256, SMEM_PROJ>>>(bq, bk, bv);

    dim3 gv(32, 8);
    k_vsplit<<<gv, 256>>>();

    cudaFuncSetAttribute(k_scores_mma, cudaFuncAttributeMaxDynamicSharedMemorySize, SMEM_PROJ);
    dim3 g2(8, 4, 32);
    k_scores_mma<<<g2, 256, SMEM_PROJ>>>();

    cudaFuncSetAttribute(k_fused, cudaFuncAttributeMaxDynamicSharedMemorySize, SMEM_FUSED);
    k_fused<<<2048, 512, SMEM_FUSED>>>(rels, heads, out);

    cudaFuncSetAttribute(k_ctx_mma, cudaFuncAttributeMaxDynamicSharedMemorySize, SMEM_PROJ);
    dim3 g4(4, 32, 2);
    k_ctx_mma<<<g4, 256, SMEM_PROJ>>>(out);
}

// round 13
// speedup vs baseline: 2.1867x; 1.0105x over previous
#include <cuda_runtime.h>
#include <cuda_bf16.h>
#include <cstdint>
#include <cstddef>

#define B_ 4
#define L_ 512
#define HID_ 512
#define H_ 8
#define DH_ 64

// ---------------- scratch (device globals; no allocations allowed) ----------
__device__ float g_v[B_ * L_ * HID_];
__device__ float g_sc[B_ * H_ * L_ * L_];            // qk scores (fp32)
__device__ __nv_bfloat16 g_Xs[2048 * 1536];          // proj A split
__device__ __nv_bfloat16 g_Ws[3 * 512 * 1536];       // proj B split
__device__ __nv_bfloat16 g_qs[32 * 512 * 128];       // q split [bh][l][qh|ql]
__device__ __nv_bfloat16 g_ks[32 * 512 * 128];       // k split [bh][l][kh|kl]
__device__ __nv_bfloat16 g_ps[32 * 512 * 1024];      // probs split [bh][q][ph|pl]
__device__ __nv_bfloat16 g_vT[32 * 64 * 1024];       // v^T split [bh][d][vh|vl]

// ---------------- cp.async helpers ------------------------------------------
__device__ __forceinline__ void cp_async16(void* smem, const void* gmem) {
    unsigned s = (unsigned)__cvta_generic_to_shared(smem);
    asm volatile("cp.async.cg.shared.global [%0], [%1], 16;\n" :: "r"(s), "l"(gmem));
}
__device__ __forceinline__ void cp_commit() {
    asm volatile("cp.async.commit_group;\n");
}
template <int N>
__device__ __forceinline__ void cp_wait() {
    asm volatile("cp.async.wait_group %0;\n" :: "n"(N));
}

// ---------------- warp mma / ldmatrix (sm_80+, no 'a' feature) ---------------
__device__ __forceinline__ void mma_bf16(float& c0, float& c1, float& c2, float& c3,
                                         uint32_t a0, uint32_t a1, uint32_t a2, uint32_t a3,
                                         uint32_t b0, uint32_t b1) {
    asm volatile(
        "mma.sync.aligned.m16n8k16.row.col.f32.bf16.bf16.f32 "
        "{%0,%1,%2,%3}, {%4,%5,%6,%7}, {%8,%9}, {%0,%1,%2,%3};"
        : "+f"(c0), "+f"(c1), "+f"(c2), "+f"(c3)
        : "r"(a0), "r"(a1), "r"(a2), "r"(a3), "r"(b0), "r"(b1));
}
__device__ __forceinline__ void ldm_x4(uint32_t* r, uint32_t addr) {
    asm volatile("ldmatrix.sync.aligned.m8n8.x4.shared.b16 {%0,%1,%2,%3}, [%4];"
                 : "=r"(r[0]), "=r"(r[1]), "=r"(r[2]), "=r"(r[3]) : "r"(addr));
}
__device__ __forceinline__ void ldm_x2(uint32_t& r0, uint32_t& r1, uint32_t addr) {
    asm volatile("ldmatrix.sync.aligned.m8n8.x2.shared.b16 {%0,%1}, [%2];"
                 : "=r"(r0), "=r"(r1) : "r"(addr));
}
__device__ __forceinline__ void ldm_x2_trans(uint32_t& r0, uint32_t& r1, uint32_t addr) {
    asm volatile("ldmatrix.sync.aligned.m8n8.x2.trans.shared.b16 {%0,%1}, [%2];"
                 : "=r"(r0), "=r"(r1) : "r"(addr));
}
__device__ __forceinline__ uint32_t cvt_bf16x2(float a, float b) {
    uint32_t w;
    asm("cvt.rn.bf16x2.f32 %0, %1, %2;" : "=r"(w) : "f"(b), "f"(a));
    return w;
}

// =============================================================================
// K0: build split-bf16 operands for the projection, K=1536.
// =============================================================================
__global__ __launch_bounds__(256) void k_prep(
    const float* __restrict__ X,
    const float* __restrict__ Wq, const float* __restrict__ Wk,
    const float* __restrict__ Wv)
{
    const int stride = gridDim.x * blockDim.x;
    for (int i = blockIdx.x * blockDim.x + threadIdx.x; i < 2048 * 512; i += stride) {
        int m = i >> 9, k = i & 511;
        float x = X[i];
        __nv_bfloat16 hi = __float2bfloat16(x);
        __nv_bfloat16 lo = __float2bfloat16(x - __bfloat162float(hi));
        __nv_bfloat16* row = g_Xs + (size_t)m * 1536;
        row[k] = hi; row[512 + k] = lo; row[1024 + k] = hi;
    }
    for (int i = blockIdx.x * blockDim.x + threadIdx.x; i < 3 * 512 * 512; i += stride) {
        int z = i >> 18;
        int r = i & 262143;
        const float* W = (z == 0) ? Wq : (z == 1) ? Wk : Wv;
        int n = r >> 9, k = r & 511;
        float x = W[r];
        __nv_bfloat16 hi = __float2bfloat16(x);
        __nv_bfloat16 lo = __float2bfloat16(x - __bfloat162float(hi));
        __nv_bfloat16* row = g_Ws + (size_t)z * 512 * 1536 + (size_t)n * 1536;
        row[k] = hi; row[512 + k] = hi; row[1024 + k] = lo;
    }
}

// =============================================================================
// K1: QKV projection via mma.sync (unchanged from R12).
// =============================================================================
#define PADK 72
#define A_BUF_ELE (128 * PADK)
#define B_BUF_ELE (64 * PADK)
#define SMEM_PROJ ((2 * A_BUF_ELE + 2 * B_BUF_ELE) * 2 + 64 * 4)

__global__ __launch_bounds__(256) void k_proj_mma(
    const float* __restrict__ bq, const float* __restrict__ bk,
    const float* __restrict__ bv)
{
    extern __shared__ char smp[];
    __nv_bfloat16* As = (__nv_bfloat16*)smp;
    __nv_bfloat16* Bs = As + 2 * A_BUF_ELE;
    float* biasS = (float*)(Bs + 2 * B_BUF_ELE);

    const int n0 = blockIdx.x * 64;
    const int m0 = blockIdx.y * 128;
    const int z  = blockIdx.z;
    const float* bias = (z == 0) ? bq : (z == 1) ? bk : bv;
    const __nv_bfloat16* Wz = g_Ws + (size_t)z * 512 * 1536;

    const int tid = threadIdx.x;
    const int wid = tid >> 5, lane = tid & 31;
    const int wm = wid >> 1, wn = wid & 1;
    const int g  = lane >> 2, tg = lane & 3;

    if (tid < 64) biasS[tid] = bias[n0 + tid];

    float acc[2][4][4];
#pragma unroll
    for (int mt = 0; mt < 2; mt++)
#pragma unroll
        for (int nt = 0; nt < 4; nt++)
#pragma unroll
            for (int e = 0; e < 4; e++) acc[mt][nt][e] = 0.f;

    auto load_chunk = [&](int c, int buf) {
        __nv_bfloat16* Ad = As + buf * A_BUF_ELE;
        __nv_bfloat16* Bd = Bs + buf * B_BUF_ELE;
#pragma unroll
        for (int i = 0; i < 4; i++) {
            int flat = i * 256 + tid;
            int row = flat >> 3, seg = flat & 7;
            cp_async16(Ad + row * PADK + seg * 8,
                       g_Xs + (size_t)(m0 + row) * 1536 + c * 64 + seg * 8);
        }
#pragma unroll
        for (int i = 0; i < 2; i++) {
            int flat = i * 256 + tid;
            int row = flat >> 3, seg = flat & 7;
            cp_async16(Bd + row * PADK + seg * 8,
                       Wz + (size_t)(n0 + row) * 1536 + c * 64 + seg * 8);
        }
        cp_commit();
    };

    load_chunk(0, 0);

#pragma unroll 1
    for (int t = 0; t < 24; t++) {
        if (t < 23) load_chunk(t + 1, (t + 1) & 1);
        if (t < 23) cp_wait<1>(); else cp_wait<0>();
        __syncthreads();

        const __nv_bfloat16* Ab = As + (t & 1) * A_BUF_ELE;
        const __nv_bfloat16* Bb = Bs + (t & 1) * B_BUF_ELE;

#pragma unroll
        for (int ks = 0; ks < 4; ks++) {
            const int kb = ks * 16;
            uint32_t af[2][4], bf[4][2];
#pragma unroll
            for (int mt = 0; mt < 2; mt++) {
                int r0 = wm * 32 + mt * 16 + g;
                af[mt][0] = *(const uint32_t*)&Ab[(r0)      * PADK + kb + tg * 2];
                af[mt][1] = *(const uint32_t*)&Ab[(r0 + 8)  * PADK + kb + tg * 2];
                af[mt][2] = *(const uint32_t*)&Ab[(r0)      * PADK + kb + tg * 2 + 8];
                af[mt][3] = *(const uint32_t*)&Ab[(r0 + 8)  * PADK + kb + tg * 2 + 8];
            }
#pragma unroll
            for (int nt = 0; nt < 4; nt++) {
                int nr = wn * 32 + nt * 8 + g;
                bf[nt][0] = *(const uint32_t*)&Bb[nr * PADK + kb + tg * 2];
                bf[nt][1] = *(const uint32_t*)&Bb[nr * PADK + kb + tg * 2 + 8];
            }
#pragma unroll
            for (int mt = 0; mt < 2; mt++)
#pragma unroll
                for (int nt = 0; nt < 4; nt++)
                    mma_bf16(acc[mt][nt][0], acc[mt][nt][1], acc[mt][nt][2], acc[mt][nt][3],
                             af[mt][0], af[mt][1], af[mt][2], af[mt][3],
                             bf[nt][0], bf[nt][1]);
        }
        __syncthreads();
    }

    const int hh = n0 >> 6;
    __nv_bfloat16* QK = (z == 0) ? g_qs : g_ks;

#pragma unroll
    for (int mt = 0; mt < 2; mt++) {
        int r0 = m0 + wm * 32 + mt * 16 + g;
#pragma unroll
        for (int nt = 0; nt < 4; nt++) {
            int cl = wn * 32 + nt * 8 + tg * 2;
            float x00 = acc[mt][nt][0] + biasS[cl];
            float x01 = acc[mt][nt][1] + biasS[cl + 1];
            float x10 = acc[mt][nt][2] + biasS[cl];
            float x11 = acc[mt][nt][3] + biasS[cl + 1];
            if (z == 2) {
                *(float2*)&g_v[(size_t)r0 * 512 + n0 + cl] = make_float2(x00, x01);
                *(float2*)&g_v[(size_t)(r0 + 8) * 512 + n0 + cl] = make_float2(x10, x11);
            } else {
                int b0 = r0 >> 9, l0 = r0 & 511;
                int b1 = (r0 + 8) >> 9, l1 = (r0 + 8) & 511;
                __nv_bfloat16* d0 = QK + ((size_t)(b0 * 8 + hh) * 512 + l0) * 128 + cl;
                __nv_bfloat16* d1 = QK + ((size_t)(b1 * 8 + hh) * 512 + l1) * 128 + cl;
                __nv_bfloat16 h00 = __float2bfloat16(x00), h01 = __float2bfloat16(x01);
                __nv_bfloat16 h10 = __float2bfloat16(x10), h11 = __float2bfloat16(x11);
                *(uint32_t*)d0 = ((uint32_t)__bfloat16_as_ushort(h01) << 16)
                               | __bfloat16_as_ushort(h00);
                *(uint32_t*)d1 = ((uint32_t)__bfloat16_as_ushort(h11) << 16)
                               | __bfloat16_as_ushort(h10);
                *(uint32_t*)(d0 + 64) = cvt_bf16x2(x00 - __bfloat162float(h00),
                                                   x01 - __bfloat162float(h01));
                *(uint32_t*)(d1 + 64) = cvt_bf16x2(x10 - __bfloat162float(h10),
                                                   x11 - __bfloat162float(h11));
            }
        }
    }
}

// =============================================================================
// K1c: v -> v^T split bf16 (unchanged).
// =============================================================================
__global__ __launch_bounds__(256) void k_vsplit()
{
    __shared__ float ts[64][65];
    const int bh = blockIdx.x;
    const int k0 = blockIdx.y * 64;
    const int b = bh >> 3, h = bh & 7;
    const int tid = threadIdx.x;

    {
        int kr = tid >> 2, ds = (tid & 3) * 16;
        const float* src = g_v + ((size_t)(b * 512) + k0 + kr) * 512 + h * 64 + ds;
#pragma unroll
        for (int j = 0; j < 4; j++) {
            float4 v4 = ((const float4*)src)[j];
            ts[kr][ds + j * 4 + 0] = v4.x; ts[kr][ds + j * 4 + 1] = v4.y;
            ts[kr][ds + j * 4 + 2] = v4.z; ts[kr][ds + j * 4 + 3] = v4.w;
        }
    }
    __syncthreads();
    {
        int d = tid >> 2, ks = (tid & 3) * 16;
        union { __nv_bfloat16 bb[8]; uint4 u; } h0, h1, l0, l1;
#pragma unroll
        for (int j = 0; j < 8; j++) {
            float x = ts[ks + j][d];
            __nv_bfloat16 hb = __float2bfloat16(x);
            h0.bb[j] = hb; l0.bb[j] = __float2bfloat16(x - __bfloat162float(hb));
        }
#pragma unroll
        for (int j = 0; j < 8; j++) {
            float x = ts[ks + 8 + j][d];
            __nv_bfloat16 hb = __float2bfloat16(x);
            h1.bb[j] = hb; l1.bb[j] = __float2bfloat16(x - __bfloat162float(hb));
        }
        __nv_bfloat16* dst = g_vT + ((size_t)bh * 64 + d) * 1024 + k0 + ks;
        *(uint4*)(dst)       = h0.u;
        *(uint4*)(dst + 8)   = h1.u;
        *(uint4*)(dst + 512) = l0.u;
        *(uint4*)(dst + 520) = l1.u;
    }
}

// =============================================================================
// K2: scores via mma.sync, BM=128, BN=128 (halved L2 traffic), 256 threads.
// grid (4, 4, 32) = 512 CTAs, 74KB smem -> 2 CTAs/SM.
// =============================================================================
#define SC_ABUF (128 * PADK)
#define SMEM_SC ((4 * 128 * PADK) * 2)

__global__ __launch_bounds__(256) void k_scores_mma()
{
    extern __shared__ char smp[];
    __nv_bfloat16* As = (__nv_bfloat16*)smp;
    __nv_bfloat16* Bs = As + 2 * SC_ABUF;

    const int n0 = blockIdx.x * 128;
    const int m0 = blockIdx.y * 128;
    const int bh = blockIdx.z;
    const __nv_bfloat16* Aq = g_qs + (size_t)bh * 512 * 128;
    const __nv_bfloat16* Bk = g_ks + (size_t)bh * 512 * 128;
    float* C = g_sc + (size_t)bh * 262144;

    const int tid = threadIdx.x;
    const int wid = tid >> 5, lane = tid & 31;
    const int wm = wid >> 1, wn = wid & 1;
    const int g  = lane >> 2, tg = lane & 3;

    const int Aoff[3] = { 0, 64, 0 };
    const int Boff[3] = { 0, 0, 64 };

    float acc[2][8][4];
#pragma unroll
    for (int mt = 0; mt < 2; mt++)
#pragma unroll
        for (int nt = 0; nt < 8; nt++)
#pragma unroll
            for (int e = 0; e < 4; e++) acc[mt][nt][e] = 0.f;

    auto load_chunk = [&](int c, int buf) {
        __nv_bfloat16* Ad = As + buf * SC_ABUF;
        __nv_bfloat16* Bd = Bs + buf * SC_ABUF;
#pragma unroll
        for (int i = 0; i < 4; i++) {
            int flat = i * 256 + tid;
            int row = flat >> 3, seg = flat & 7;
            cp_async16(Ad + row * PADK + seg * 8,
                       Aq + (size_t)(m0 + row) * 128 + Aoff[c] + seg * 8);
        }
#pragma unroll
        for (int i = 0; i < 4; i++) {
            int flat = i * 256 + tid;
            int row = flat >> 3, seg = flat & 7;
            cp_async16(Bd + row * PADK + seg * 8,
                       Bk + (size_t)(n0 + row) * 128 + Boff[c] + seg * 8);
        }
        cp_commit();
    };

    load_chunk(0, 0);

#pragma unroll 1
    for (int t = 0; t < 3; t++) {
        if (t < 2) load_chunk(t + 1, (t + 1) & 1);
        if (t < 2) cp_wait<1>(); else cp_wait<0>();
        __syncthreads();

        const __nv_bfloat16* Ab = As + (t & 1) * SC_ABUF;
        const __nv_bfloat16* Bb = Bs + (t & 1) * SC_ABUF;

#pragma unroll
        for (int ks = 0; ks < 4; ks++) {
            const int kb = ks * 16;
            uint32_t af[2][4], bf[8][2];
#pragma unroll
            for (int mt = 0; mt < 2; mt++) {
                int r0 = wm * 32 + mt * 16 + g;
                af[mt][0] = *(const uint32_t*)&Ab[(r0)      * PADK + kb + tg * 2];
                af[mt][1] = *(const uint32_t*)&Ab[(r0 + 8)  * PADK + kb + tg * 2];
                af[mt][2] = *(const uint32_t*)&Ab[(r0)      * PADK + kb + tg * 2 + 8];
                af[mt][3] = *(const uint32_t*)&Ab[(r0 + 8)  * PADK + kb + tg * 2 + 8];
            }
#pragma unroll
            for (int nt = 0; nt < 8; nt++) {
                int nr = wn * 64 + nt * 8 + g;
                bf[nt][0] = *(const uint32_t*)&Bb[nr * PADK + kb + tg * 2];
                bf[nt][1] = *(const uint32_t*)&Bb[nr * PADK + kb + tg * 2 + 8];
            }
#pragma unroll
            for (int mt = 0; mt < 2; mt++)
#pragma unroll
                for (int nt = 0; nt < 8; nt++)
                    mma_bf16(acc[mt][nt][0], acc[mt][nt][1], acc[mt][nt][2], acc[mt][nt][3],
                             af[mt][0], af[mt][1], af[mt][2], af[mt][3],
                             bf[nt][0], bf[nt][1]);
        }
        __syncthreads();
    }

#pragma unroll
    for (int mt = 0; mt < 2; mt++) {
        int r0 = m0 + wm * 32 + mt * 16 + g;
#pragma unroll
        for (int nt = 0; nt < 8; nt++) {
            int cl = wn * 64 + nt * 8 + tg * 2;
            *(float2*)&C[(size_t)r0 * 512 + n0 + cl] =
                make_float2(acc[mt][nt][0], acc[mt][nt][1]);
            *(float2*)&C[(size_t)(r0 + 8) * 512 + n0 + cl] =
                make_float2(acc[mt][nt][2], acc[mt][nt][3]);
        }
    }
}

// =============================================================================
// K3: fused — 2 q-rows per CTA with cross-q prefetch.  512 threads, grid 1024.
// =============================================================================
#define F_RH 0
#define F_RL 65536
#define F_SC 131072
#define F_QS 147584
#define F_PS 151936
#define F_RED 168576
#define SMEM_FUSED 184960

__global__ __launch_bounds__(512) void k_fused(
    const float* __restrict__ rels,
    const float* __restrict__ heads,
    float* __restrict__ out)
{
    extern __shared__ char smf[];
    const uint32_t sbase = (uint32_t)__cvta_generic_to_shared(smf);
    float* sc_s = (float*)(smf + F_SC);
    __nv_bfloat16* QS = (__nv_bfloat16*)(smf + F_QS);
    __nv_bfloat16* PS = (__nv_bfloat16*)(smf + F_PS);
    float* red = (float*)(smf + F_RED);

    const int q0 = (blockIdx.x * 2) & 511;
    const int b  = (blockIdx.x * 2) >> 9;
    const int tid = threadIdx.x;
    const int lane = tid & 31, w = tid >> 5;

    // ---- prologue: q0's rels sg0 LDG + qk/heads + QS ----
    float4 stg[8];
    {
        const float* rg0 = rels + ((size_t)(b * 512 + q0)) * (512 * 64);
        int r = tid >> 1, f0 = (tid & 1) * 8;
        const float4* src = (const float4*)(rg0 + (size_t)r * 64) + f0;
#pragma unroll
        for (int j = 0; j < 8; j++) stg[j] = src[j];
    }

    float2 qkPre[4], hvPre[4], qkN[4], hvN[4];
    {
        int hh = lane >> 2;
        int kkb = w * 8 + (lane & 3) * 2;
#pragma unroll
        for (int sgh = 0; sgh < 4; sgh++) {
            int kk = sgh * 128 + kkb;
            qkPre[sgh] = *(const float2*)&g_sc[(size_t)(b * 8 + hh) * 262144
                                               + (size_t)q0 * 512 + kk];
            hvPre[sgh] = *(const float2*)&heads[((size_t)b * 512 + q0) * 512 + kk];
        }
    }

    if (tid < 128) {
        int h = tid >> 4, dq = tid & 15;
        const __nv_bfloat16* src = g_qs + ((size_t)(b * 8 + h) * 512 + q0) * 128 + dq * 4;
        *(uint2*)&QS[h * 136 + dq * 4]       = *(const uint2*)src;
        *(uint2*)&QS[(h + 8) * 136 + dq * 4] = *(const uint2*)(src + 64);
    }
    __syncthreads();

    uint32_t afr[4][4];
#pragma unroll
    for (int ds = 0; ds < 4; ds++) {
        uint32_t addr = sbase + F_QS + (lane & 15) * 272
                      + (ds * 16 + ((lane >> 4) << 3)) * 2;
        ldm_x4(afr[ds], addr);
    }

#pragma unroll 1
    for (int qi = 0; qi < 2; qi++) {
        const int q = q0 + qi;
        const float* rg = rels + ((size_t)(b * 512 + q)) * (512 * 64);
        const size_t hoff = ((size_t)b * 512 + q) * 512;

        auto sts_group = [&](int sg) {
            int rr = tid >> 1;
            int r = sg * 256 + rr;
            int c0 = (tid & 1) * 4;
            char* rhrow = smf + F_RH + r * 128;
            char* rlrow = smf + F_RL + r * 128;
            int s7 = rr & 7;
#pragma unroll
            for (int jj = 0; jj < 4; jj++) {
                const float* xs = (const float*)&stg[jj * 2];
                uint32_t hw[4], lw[4];
#pragma unroll
                for (int j = 0; j < 4; j++) {
                    float x0 = xs[2 * j], x1 = xs[2 * j + 1];
                    uint32_t u0 = __float_as_uint(x0), u1 = __float_as_uint(x1);
                    hw[j] = __byte_perm(u0, u1, 0x7632);
                    float h0f = __uint_as_float(u0 & 0xFFFF0000u);
                    float h1f = __uint_as_float(u1 & 0xFFFF0000u);
                    lw[j] = cvt_bf16x2(x0 - h0f, x1 - h1f);
                }
                int chunk = c0 + jj;
                *(uint4*)(rhrow + ((chunk ^ s7) << 4)) = make_uint4(hw[0], hw[1], hw[2], hw[3]);
                *(uint4*)(rlrow + ((chunk ^ s7) << 4)) = make_uint4(lw[0], lw[1], lw[2], lw[3]);
            }
        };

        auto stageB = [&](int sg) {
#pragma unroll
            for (int half = 0; half < 2; half++) {
                const int sgh = sg * 2 + half;
                const int k0 = sgh * 128 + w * 8;
                float p0c0 = 0.f, p0c1 = 0.f, p0c2 = 0.f, p0c3 = 0.f;
                float p1c0 = 0.f, p1c1 = 0.f, p1c2 = 0.f, p1c3 = 0.f;
                const int row = k0 + (lane & 7);
                const int s7 = row & 7;
                const int csel = (lane >> 3) & 1;
#pragma unroll
                for (int ds = 0; ds < 4; ds++) {
                    int chunk = ds * 2 + csel;
                    uint32_t b0, b1;
                    ldm_x2(b0, b1, sbase + F_RH + row * 128 + ((chunk ^ s7) << 4));
                    mma_bf16(p0c0, p0c1, p0c2, p0c3,
                             afr[ds][0], afr[ds][1], afr[ds][2], afr[ds][3], b0, b1);
                }
#pragma unroll
                for (int ds = 0; ds < 4; ds++) {
                    int chunk = ds * 2 + csel;
                    uint32_t b0, b1;
                    ldm_x2(b0, b1, sbase + F_RL + row * 128 + ((chunk ^ s7) << 4));
                    mma_bf16(p1c0, p1c1, p1c2, p1c3,
                             afr[ds][0], 0u, afr[ds][2], 0u, b0, b1);
                }
                float a0 = p0c0 + p0c2 + p1c0;
                float a1 = p0c1 + p0c3 + p1c1;
                int h = lane >> 2, kk = k0 + (lane & 3) * 2;
                sc_s[h * 516 + kk]     = (a0 + qkPre[sgh].x) * 0.125f + hvPre[sgh].x;
                sc_s[h * 516 + kk + 1] = (a1 + qkPre[sgh].y) * 0.125f + hvPre[sgh].y;
            }
        };

        // ---- main: sts(0); ldg(1); sync; B(0); sts(1); [prefetch q+1]; sync; B(1)
        sts_group(0);
        {   // ldg supergroup 1 (this q)
            int r = 256 + (tid >> 1), f0 = (tid & 1) * 8;
            const float4* src = (const float4*)(rg + (size_t)r * 64) + f0;
#pragma unroll
            for (int j = 0; j < 8; j++) stg[j] = src[j];
        }
        __syncthreads();
        stageB(0);
        sts_group(1);
        if (qi == 0) {
            // prefetch next q's sg0 rels + qk/heads (lands during B(1)/softmax/D)
            const float* rgN = rels + ((size_t)(b * 512 + q0 + 1)) * (512 * 64);
            int r = tid >> 1, f0 = (tid & 1) * 8;
            const float4* src = (const float4*)(rgN + (size_t)r * 64) + f0;
#pragma unroll
            for (int j = 0; j < 8; j++) stg[j] = src[j];
            int hh = lane >> 2;
            int kkb = w * 8 + (lane & 3) * 2;
#pragma unroll
            for (int sgh = 0; sgh < 4; sgh++) {
                int kk = sgh * 128 + kkb;
                qkN[sgh] = *(const float2*)&g_sc[(size_t)(b * 8 + hh) * 262144
                                                 + (size_t)(q0 + 1) * 512 + kk];
                hvN[sgh] = *(const float2*)&heads[((size_t)b * 512 + q0 + 1) * 512 + kk];
            }
        }
        __syncthreads();
        stageB(1);
        __syncthreads();

        // ---- softmax (warps 0..7); warps 8..15 build next q's QS ----
        if (w < 8) {
            float* row = sc_s + w * 516;
            float vals[16];
            float mx = -1e30f;
#pragma unroll
            for (int i = 0; i < 16; i++) { vals[i] = row[i * 32 + lane]; mx = fmaxf(mx, vals[i]); }
#pragma unroll
            for (int o = 16; o; o >>= 1) mx = fmaxf(mx, __shfl_xor_sync(0xffffffffu, mx, o));
            float s = 0.f;
#pragma unroll
            for (int i = 0; i < 16; i++) { vals[i] = __expf(vals[i] - mx); s += vals[i]; }
#pragma unroll
            for (int o = 16; o; o >>= 1) s += __shfl_xor_sync(0xffffffffu, s, o);
            float inv = 1.f / s;
            __nv_bfloat16* pgp = g_ps + ((size_t)(b * 8 + w) * 512 + q) * 1024;
#pragma unroll
            for (int i = 0; i < 16; i++) {
                float pv = vals[i] * inv;
                int kk = i * 32 + lane;
                __nv_bfloat16 ph = __float2bfloat16(pv);
                __nv_bfloat16 pl = __float2bfloat16(pv - __bfloat162float(ph));
                PS[w * 520 + kk] = ph;
                PS[(w + 8) * 520 + kk] = pl;
                pgp[kk] = ph;
                pgp[512 + kk] = pl;
            }
        } else if (qi == 0 && tid >= 256 && tid < 384) {
            int t2 = tid - 256;
            int h = t2 >> 4, dq = t2 & 15;
            const __nv_bfloat16* src = g_qs + ((size_t)(b * 8 + h) * 512 + q0 + 1) * 128 + dq * 4;
            *(uint2*)&QS[h * 136 + dq * 4]       = *(const uint2*)src;
            *(uint2*)&QS[(h + 8) * 136 + dq * 4] = *(const uint2*)(src + 64);
        }
        __syncthreads();

        // afr for next q (QS now holds next q's data)
        if (qi == 0) {
#pragma unroll
            for (int ds = 0; ds < 4; ds++) {
                uint32_t addr = sbase + F_QS + (lane & 15) * 272
                              + (ds * 16 + ((lane >> 4) << 3)) * 2;
                ldm_x4(afr[ds], addr);
            }
#pragma unroll
            for (int i = 0; i < 4; i++) { qkPre[i] = qkN[i]; hvPre[i] = hvN[i]; }
        }

        // ---- stage D ----
        {
            const int kg = w >> 1, ng = w & 1;
            float aD[4][4];
#pragma unroll
            for (int i = 0; i < 4; i++)
#pragma unroll
                for (int j = 0; j < 4; j++) aD[i][j] = 0.f;

#pragma unroll
            for (int ks = 0; ks < 4; ks++) {
                const int k0 = kg * 64 + ks * 16;
                uint32_t af[4];
                uint32_t aaddr = sbase + F_PS + (lane & 15) * 1040
                               + (k0 + ((lane >> 4) << 3)) * 2;
                ldm_x4(af, aaddr);
                const int row = k0 + (lane & 7) + (((lane >> 3) & 1) << 3);
                const int s7 = row & 7;
#pragma unroll
                for (int ntl = 0; ntl < 4; ntl++) {
                    int d0 = (ng * 4 + ntl) * 8;
                    uint32_t b0, b1;
                    ldm_x2_trans(b0, b1, sbase + F_RH + row * 128 + (((d0 >> 3) ^ s7) << 4));
                    mma_bf16(aD[ntl][0], aD[ntl][1], aD[ntl][2], aD[ntl][3],
                             af[0], af[1], af[2], af[3], b0, b1);
                }
#pragma unroll
                for (int ntl = 0; ntl < 4; ntl++) {
                    int d0 = (ng * 4 + ntl) * 8;
                    uint32_t b0, b1;
                    ldm_x2_trans(b0, b1, sbase + F_RL + row * 128 + (((d0 >> 3) ^ s7) << 4));
                    mma_bf16(aD[ntl][0], aD[ntl][1], aD[ntl][2], aD[ntl][3],
                             af[0], 0u, af[2], 0u, b0, b1);
                }
            }
#pragma unroll
            for (int ntl = 0; ntl < 4; ntl++) {
                int slot = kg * 8 + ng * 4 + ntl;
                *(float2*)&red[(slot * 32 + lane) * 2] =
                    make_float2(aD[ntl][0] + aD[ntl][2], aD[ntl][1] + aD[ntl][3]);
            }
        }
        __syncthreads();

        if (w < 8) {
            float rx = 0.f, ry = 0.f;
#pragma unroll
            for (int kg = 0; kg < 8; kg++) {
                float2 s = *(const float2*)&red[((kg * 8 + w) * 32 + lane) * 2];
                rx += s.x; ry += s.y;
            }
            int h = lane >> 2, d = w * 8 + (lane & 3) * 2;
            *(float2*)&out[((size_t)b * 512 + q) * 512 + h * 64 + d] = make_float2(rx, ry);
        }
        __syncthreads();
    }
}

// =============================================================================
// K4: ctx += probs @ v via mma.sync (unchanged from R12).
// =============================================================================
__global__ __launch_bounds__(256) void k_ctx_mma(float* __restrict__ out)
{
    extern __shared__ char smp[];
    __nv_bfloat16* As = (__nv_bfloat16*)smp;
    __nv_bfloat16* Bs = As + 2 * A_BUF_ELE;

    const int m0 = blockIdx.x * 128;
    const int bh = blockIdx.y;
    const int tbase = blockIdx.z * 12;
    const int b = bh >> 3, h = bh & 7;
    const __nv_bfloat16* Ap = g_ps + (size_t)bh * 512 * 1024;
    const __nv_bfloat16* Bv = g_vT + (size_t)bh * 64 * 1024;

    const int tid = threadIdx.x;
    const int wid = tid >> 5, lane = tid & 31;
    const int wm = wid >> 1, wn = wid & 1;
    const int g  = lane >> 2, tg = lane & 3;

    float acc[2][4][4];
#pragma unroll
    for (int mt = 0; mt < 2; mt++)
#pragma unroll
        for (int nt = 0; nt < 4; nt++)
#pragma unroll
            for (int e = 0; e < 4; e++) acc[mt][nt][e] = 0.f;

    auto aoff = [](int t) { return t < 8 ? t * 64 : t < 16 ? 512 + (t - 8) * 64 : (t - 16) * 64; };
    auto boff = [](int t) { return t < 8 ? t * 64 : t < 16 ? (t - 8) * 64 : 512 + (t - 16) * 64; };

    auto load_chunk = [&](int c, int buf) {
        __nv_bfloat16* Ad = As + buf * A_BUF_ELE;
        __nv_bfloat16* Bd = Bs + buf * B_BUF_ELE;
        int ao = aoff(c), bo = boff(c);
#pragma unroll
        for (int i = 0; i < 4; i++) {
            int flat = i * 256 + tid;
            int row = flat >> 3, seg = flat & 7;
            cp_async16(Ad + row * PADK + seg * 8,
                       Ap + (size_t)(m0 + row) * 1024 + ao + seg * 8);
        }
#pragma unroll
        for (int i = 0; i < 2; i++) {
            int flat = i * 256 + tid;
            int row = flat >> 3, seg = flat & 7;
            cp_async16(Bd + row * PADK + seg * 8,
                       Bv + (size_t)row * 1024 + bo + seg * 8);
        }
        cp_commit();
    };

    load_chunk(tbase, 0);

#pragma unroll 1
    for (int t = 0; t < 12; t++) {
        if (t < 11) load_chunk(tbase + t + 1, (t + 1) & 1);
        if (t < 11) cp_wait<1>(); else cp_wait<0>();
        __syncthreads();

        const __nv_bfloat16* Ab = As + (t & 1) * A_BUF_ELE;
        const __nv_bfloat16* Bb = Bs + (t & 1) * B_BUF_ELE;

#pragma unroll
        for (int ks = 0; ks < 4; ks++) {
            const int kb = ks * 16;
            uint32_t af[2][4], bf[4][2];
#pragma unroll
            for (int mt = 0; mt < 2; mt++) {
                int r0 = wm * 32 + mt * 16 + g;
                af[mt][0] = *(const uint32_t*)&Ab[(r0)      * PADK + kb + tg * 2];
                af[mt][1] = *(const uint32_t*)&Ab[(r0 + 8)  * PADK + kb + tg * 2];
                af[mt][2] = *(const uint32_t*)&Ab[(r0)      * PADK + kb + tg * 2 + 8];
                af[mt][3] = *(const uint32_t*)&Ab[(r0 + 8)  * PADK + kb + tg * 2 + 8];
            }
#pragma unroll
            for (int nt = 0; nt < 4; nt++) {
                int nr = wn * 32 + nt * 8 + g;
                bf[nt][0] = *(const uint32_t*)&Bb[nr * PADK + kb + tg * 2];
                bf[nt][1] = *(const uint32_t*)&Bb[nr * PADK + kb + tg * 2 + 8];
            }
#pragma unroll
            for (int mt = 0; mt < 2; mt++)
#pragma unroll
                for (int nt = 0; nt < 4; nt++)
                    mma_bf16(acc[mt][nt][0], acc[mt][nt][1], acc[mt][nt][2], acc[mt][nt][3],
                             af[mt][0], af[mt][1], af[mt][2], af[mt][3],
                             bf[nt][0], bf[nt][1]);
        }
        __syncthreads();
    }

#pragma unroll
    for (int mt = 0; mt < 2; mt++) {
        int r0 = m0 + wm * 32 + mt * 16 + g;
#pragma unroll
        for (int nt = 0; nt < 4; nt++) {
            int cl = wn * 32 + nt * 8 + tg * 2;
            float* p0 = &out[((size_t)(b * 512 + r0)) * 512 + h * 64 + cl];
            atomicAdd(p0 + 0, acc[mt][nt][0]);
            atomicAdd(p0 + 1, acc[mt][nt][1]);
            float* p1 = &out[((size_t)(b * 512 + r0 + 8)) * 512 + h * 64 + cl];
            atomicAdd(p1 + 0, acc[mt][nt][2]);
            atomicAdd(p1 + 1, acc[mt][nt][3]);
        }
    }
}

// =============================================================================
extern "C" void kernel_launch(void* const* d_in, const int* in_sizes, int n_in,
                              void* d_out, int out_size)
{
    const float* hidden = (const float*)d_in[0];
    const float* heads  = (const float*)d_in[1];
    const float* rels   = (const float*)d_in[2];
    const float* Wq = (const float*)d_in[3];
    const float* bq = (const float*)d_in[4];
    const float* Wk = (const float*)d_in[5];
    const float* bk = (const float*)d_in[6];
    const float* Wv = (const float*)d_in[7];
    const float* bv = (const float*)d_in[8];
    float* out = (float*)d_out;

    k_prep<<<1024, 256>>>(hidden, Wq, Wk, Wv);

    cudaFuncSetAttribute(k_proj_mma, cudaFuncAttributeMaxDynamicSharedMemorySize, SMEM_PROJ);
    dim3 g1(8, 16, 3);
    k_proj_mma<<<g1, 256, SMEM_PROJ>>>(bq, bk, bv);

    dim3 gv(32, 8);
    k_vsplit<<<gv, 256>>>();

    cudaFuncSetAttribute(k_scores_mma, cudaFuncAttributeMaxDynamicSharedMemorySize, SMEM_SC);
    dim3 g2(4, 4, 32);
    k_scores_mma<<<g2, 256, SMEM_SC>>>();

    cudaFuncSetAttribute(k_fused, cudaFuncAttributeMaxDynamicSharedMemorySize, SMEM_FUSED);
    k_fused<<<1024, 512, SMEM_FUSED>>>(rels, heads, out);

    cudaFuncSetAttribute(k_ctx_mma, cudaFuncAttributeMaxDynamicSharedMemorySize, SMEM_PROJ);
    dim3 g4(4, 32, 2);
    k_ctx_mma<<<g4, 256, SMEM_PROJ>>>(out);
}

// round 14
// speedup vs baseline: 2.2286x; 1.0192x over previous
#include <cuda_runtime.h>
#include <cuda_bf16.h>
#include <cstdint>
#include <cstddef>

#define B_ 4
#define L_ 512
#define HID_ 512
#define H_ 8
#define DH_ 64

// ---------------- scratch (device globals; no allocations allowed) ----------
__device__ float g_v[B_ * L_ * HID_];
__device__ float g_sc[B_ * H_ * L_ * L_];            // qk scores (fp32)
__device__ __nv_bfloat16 g_Xs[2048 * 1536];          // proj A split
__device__ __nv_bfloat16 g_Ws[3 * 512 * 1536];       // proj B split
__device__ __nv_bfloat16 g_qs[32 * 512 * 128];       // q split [bh][l][qh|ql]
__device__ __nv_bfloat16 g_ks[32 * 512 * 128];       // k split [bh][l][kh|kl]
__device__ __nv_bfloat16 g_ps[32 * 512 * 1024];      // probs split [bh][q][ph|pl]
__device__ __nv_bfloat16 g_vT[32 * 64 * 1024];       // v^T split [bh][d][vh|vl]

// ---------------- cp.async helpers ------------------------------------------
__device__ __forceinline__ void cp_async16(void* smem, const void* gmem) {
    unsigned s = (unsigned)__cvta_generic_to_shared(smem);
    asm volatile("cp.async.cg.shared.global [%0], [%1], 16;\n" :: "r"(s), "l"(gmem));
}
__device__ __forceinline__ void cp_commit() {
    asm volatile("cp.async.commit_group;\n");
}
template <int N>
__device__ __forceinline__ void cp_wait() {
    asm volatile("cp.async.wait_group %0;\n" :: "n"(N));
}

// ---------------- warp mma / ldmatrix (sm_80+, no 'a' feature) ---------------
__device__ __forceinline__ void mma_bf16(float& c0, float& c1, float& c2, float& c3,
                                         uint32_t a0, uint32_t a1, uint32_t a2, uint32_t a3,
                                         uint32_t b0, uint32_t b1) {
    asm volatile(
        "mma.sync.aligned.m16n8k16.row.col.f32.bf16.bf16.f32 "
        "{%0,%1,%2,%3}, {%4,%5,%6,%7}, {%8,%9}, {%0,%1,%2,%3};"
        : "+f"(c0), "+f"(c1), "+f"(c2), "+f"(c3)
        : "r"(a0), "r"(a1), "r"(a2), "r"(a3), "r"(b0), "r"(b1));
}
__device__ __forceinline__ void ldm_x4(uint32_t* r, uint32_t addr) {
    asm volatile("ldmatrix.sync.aligned.m8n8.x4.shared.b16 {%0,%1,%2,%3}, [%4];"
                 : "=r"(r[0]), "=r"(r[1]), "=r"(r[2]), "=r"(r[3]) : "r"(addr));
}
__device__ __forceinline__ void ldm_x2(uint32_t& r0, uint32_t& r1, uint32_t addr) {
    asm volatile("ldmatrix.sync.aligned.m8n8.x2.shared.b16 {%0,%1}, [%2];"
                 : "=r"(r0), "=r"(r1) : "r"(addr));
}
__device__ __forceinline__ void ldm_x2_trans(uint32_t& r0, uint32_t& r1, uint32_t addr) {
    asm volatile("ldmatrix.sync.aligned.m8n8.x2.trans.shared.b16 {%0,%1}, [%2];"
                 : "=r"(r0), "=r"(r1) : "r"(addr));
}
__device__ __forceinline__ uint32_t cvt_bf16x2(float a, float b) {
    uint32_t w;
    asm("cvt.rn.bf16x2.f32 %0, %1, %2;" : "=r"(w) : "f"(b), "f"(a));
    return w;
}
#define NBAR_SYNC(id, cnt) \
    asm volatile("bar.sync %0, %1;" :: "r"(id), "r"(cnt) : "memory")
#define NBAR_ARRIVE(id, cnt) \
    asm volatile("bar.arrive %0, %1;" :: "r"(id), "r"(cnt) : "memory")

// =============================================================================
// K0: build split-bf16 operands for the projection, K=1536.
// =============================================================================
__global__ __launch_bounds__(256) void k_prep(
    const float* __restrict__ X,
    const float* __restrict__ Wq, const float* __restrict__ Wk,
    const float* __restrict__ Wv)
{
    const int stride = gridDim.x * blockDim.x;
    for (int i = blockIdx.x * blockDim.x + threadIdx.x; i < 2048 * 512; i += stride) {
        int m = i >> 9, k = i & 511;
        float x = X[i];
        __nv_bfloat16 hi = __float2bfloat16(x);
        __nv_bfloat16 lo = __float2bfloat16(x - __bfloat162float(hi));
        __nv_bfloat16* row = g_Xs + (size_t)m * 1536;
        row[k] = hi; row[512 + k] = lo; row[1024 + k] = hi;
    }
    for (int i = blockIdx.x * blockDim.x + threadIdx.x; i < 3 * 512 * 512; i += stride) {
        int z = i >> 18;
        int r = i & 262143;
        const float* W = (z == 0) ? Wq : (z == 1) ? Wk : Wv;
        int n = r >> 9, k = r & 511;
        float x = W[r];
        __nv_bfloat16 hi = __float2bfloat16(x);
        __nv_bfloat16 lo = __float2bfloat16(x - __bfloat162float(hi));
        __nv_bfloat16* row = g_Ws + (size_t)z * 512 * 1536 + (size_t)n * 1536;
        row[k] = hi; row[512 + k] = hi; row[1024 + k] = lo;
    }
}

// =============================================================================
// K1: QKV projection via mma.sync (unchanged).
// =============================================================================
#define PADK 72
#define A_BUF_ELE (128 * PADK)
#define B_BUF_ELE (64 * PADK)
#define SMEM_PROJ ((2 * A_BUF_ELE + 2 * B_BUF_ELE) * 2 + 64 * 4)

__global__ __launch_bounds__(256) void k_proj_mma(
    const float* __restrict__ bq, const float* __restrict__ bk,
    const float* __restrict__ bv)
{
    extern __shared__ char smp[];
    __nv_bfloat16* As = (__nv_bfloat16*)smp;
    __nv_bfloat16* Bs = As + 2 * A_BUF_ELE;
    float* biasS = (float*)(Bs + 2 * B_BUF_ELE);

    const int n0 = blockIdx.x * 64;
    const int m0 = blockIdx.y * 128;
    const int z  = blockIdx.z;
    const float* bias = (z == 0) ? bq : (z == 1) ? bk : bv;
    const __nv_bfloat16* Wz = g_Ws + (size_t)z * 512 * 1536;

    const int tid = threadIdx.x;
    const int wid = tid >> 5, lane = tid & 31;
    const int wm = wid >> 1, wn = wid & 1;
    const int g  = lane >> 2, tg = lane & 3;

    if (tid < 64) biasS[tid] = bias[n0 + tid];

    float acc[2][4][4];
#pragma unroll
    for (int mt = 0; mt < 2; mt++)
#pragma unroll
        for (int nt = 0; nt < 4; nt++)
#pragma unroll
            for (int e = 0; e < 4; e++) acc[mt][nt][e] = 0.f;

    auto load_chunk = [&](int c, int buf) {
        __nv_bfloat16* Ad = As + buf * A_BUF_ELE;
        __nv_bfloat16* Bd = Bs + buf * B_BUF_ELE;
#pragma unroll
        for (int i = 0; i < 4; i++) {
            int flat = i * 256 + tid;
            int row = flat >> 3, seg = flat & 7;
            cp_async16(Ad + row * PADK + seg * 8,
                       g_Xs + (size_t)(m0 + row) * 1536 + c * 64 + seg * 8);
        }
#pragma unroll
        for (int i = 0; i < 2; i++) {
            int flat = i * 256 + tid;
            int row = flat >> 3, seg = flat & 7;
            cp_async16(Bd + row * PADK + seg * 8,
                       Wz + (size_t)(n0 + row) * 1536 + c * 64 + seg * 8);
        }
        cp_commit();
    };

    load_chunk(0, 0);

#pragma unroll 1
    for (int t = 0; t < 24; t++) {
        if (t < 23) load_chunk(t + 1, (t + 1) & 1);
        if (t < 23) cp_wait<1>(); else cp_wait<0>();
        __syncthreads();

        const __nv_bfloat16* Ab = As + (t & 1) * A_BUF_ELE;
        const __nv_bfloat16* Bb = Bs + (t & 1) * B_BUF_ELE;

#pragma unroll
        for (int ks = 0; ks < 4; ks++) {
            const int kb = ks * 16;
            uint32_t af[2][4], bf[4][2];
#pragma unroll
            for (int mt = 0; mt < 2; mt++) {
                int r0 = wm * 32 + mt * 16 + g;
                af[mt][0] = *(const uint32_t*)&Ab[(r0)      * PADK + kb + tg * 2];
                af[mt][1] = *(const uint32_t*)&Ab[(r0 + 8)  * PADK + kb + tg * 2];
                af[mt][2] = *(const uint32_t*)&Ab[(r0)      * PADK + kb + tg * 2 + 8];
                af[mt][3] = *(const uint32_t*)&Ab[(r0 + 8)  * PADK + kb + tg * 2 + 8];
            }
#pragma unroll
            for (int nt = 0; nt < 4; nt++) {
                int nr = wn * 32 + nt * 8 + g;
                bf[nt][0] = *(const uint32_t*)&Bb[nr * PADK + kb + tg * 2];
                bf[nt][1] = *(const uint32_t*)&Bb[nr * PADK + kb + tg * 2 + 8];
            }
#pragma unroll
            for (int mt = 0; mt < 2; mt++)
#pragma unroll
                for (int nt = 0; nt < 4; nt++)
                    mma_bf16(acc[mt][nt][0], acc[mt][nt][1], acc[mt][nt][2], acc[mt][nt][3],
                             af[mt][0], af[mt][1], af[mt][2], af[mt][3],
                             bf[nt][0], bf[nt][1]);
        }
        __syncthreads();
    }

    const int hh = n0 >> 6;
    __nv_bfloat16* QK = (z == 0) ? g_qs : g_ks;

#pragma unroll
    for (int mt = 0; mt < 2; mt++) {
        int r0 = m0 + wm * 32 + mt * 16 + g;
#pragma unroll
        for (int nt = 0; nt < 4; nt++) {
            int cl = wn * 32 + nt * 8 + tg * 2;
            float x00 = acc[mt][nt][0] + biasS[cl];
            float x01 = acc[mt][nt][1] + biasS[cl + 1];
            float x10 = acc[mt][nt][2] + biasS[cl];
            float x11 = acc[mt][nt][3] + biasS[cl + 1];
            if (z == 2) {
                *(float2*)&g_v[(size_t)r0 * 512 + n0 + cl] = make_float2(x00, x01);
                *(float2*)&g_v[(size_t)(r0 + 8) * 512 + n0 + cl] = make_float2(x10, x11);
            } else {
                int b0 = r0 >> 9, l0 = r0 & 511;
                int b1 = (r0 + 8) >> 9, l1 = (r0 + 8) & 511;
                __nv_bfloat16* d0 = QK + ((size_t)(b0 * 8 + hh) * 512 + l0) * 128 + cl;
                __nv_bfloat16* d1 = QK + ((size_t)(b1 * 8 + hh) * 512 + l1) * 128 + cl;
                __nv_bfloat16 h00 = __float2bfloat16(x00), h01 = __float2bfloat16(x01);
                __nv_bfloat16 h10 = __float2bfloat16(x10), h11 = __float2bfloat16(x11);
                *(uint32_t*)d0 = ((uint32_t)__bfloat16_as_ushort(h01) << 16)
                               | __bfloat16_as_ushort(h00);
                *(uint32_t*)d1 = ((uint32_t)__bfloat16_as_ushort(h11) << 16)
                               | __bfloat16_as_ushort(h10);
                *(uint32_t*)(d0 + 64) = cvt_bf16x2(x00 - __bfloat162float(h00),
                                                   x01 - __bfloat162float(h01));
                *(uint32_t*)(d1 + 64) = cvt_bf16x2(x10 - __bfloat162float(h10),
                                                   x11 - __bfloat162float(h11));
            }
        }
    }
}

// =============================================================================
// K1c: v -> v^T split bf16 (unchanged).
// =============================================================================
__global__ __launch_bounds__(256) void k_vsplit()
{
    __shared__ float ts[64][65];
    const int bh = blockIdx.x;
    const int k0 = blockIdx.y * 64;
    const int b = bh >> 3, h = bh & 7;
    const int tid = threadIdx.x;

    {
        int kr = tid >> 2, ds = (tid & 3) * 16;
        const float* src = g_v + ((size_t)(b * 512) + k0 + kr) * 512 + h * 64 + ds;
#pragma unroll
        for (int j = 0; j < 4; j++) {
            float4 v4 = ((const float4*)src)[j];
            ts[kr][ds + j * 4 + 0] = v4.x; ts[kr][ds + j * 4 + 1] = v4.y;
            ts[kr][ds + j * 4 + 2] = v4.z; ts[kr][ds + j * 4 + 3] = v4.w;
        }
    }
    __syncthreads();
    {
        int d = tid >> 2, ks = (tid & 3) * 16;
        union { __nv_bfloat16 bb[8]; uint4 u; } h0, h1, l0, l1;
#pragma unroll
        for (int j = 0; j < 8; j++) {
            float x = ts[ks + j][d];
            __nv_bfloat16 hb = __float2bfloat16(x);
            h0.bb[j] = hb; l0.bb[j] = __float2bfloat16(x - __bfloat162float(hb));
        }
#pragma unroll
        for (int j = 0; j < 8; j++) {
            float x = ts[ks + 8 + j][d];
            __nv_bfloat16 hb = __float2bfloat16(x);
            h1.bb[j] = hb; l1.bb[j] = __float2bfloat16(x - __bfloat162float(hb));
        }
        __nv_bfloat16* dst = g_vT + ((size_t)bh * 64 + d) * 1024 + k0 + ks;
        *(uint4*)(dst)       = h0.u;
        *(uint4*)(dst + 8)   = h1.u;
        *(uint4*)(dst + 512) = l0.u;
        *(uint4*)(dst + 520) = l1.u;
    }
}

// =============================================================================
// K2: scores via mma.sync, BM=128, BN=128 (unchanged from R13).
// =============================================================================
#define SC_ABUF (128 * PADK)
#define SMEM_SC ((4 * 128 * PADK) * 2)

__global__ __launch_bounds__(256) void k_scores_mma()
{
    extern __shared__ char smp[];
    __nv_bfloat16* As = (__nv_bfloat16*)smp;
    __nv_bfloat16* Bs = As + 2 * SC_ABUF;

    const int n0 = blockIdx.x * 128;
    const int m0 = blockIdx.y * 128;
    const int bh = blockIdx.z;
    const __nv_bfloat16* Aq = g_qs + (size_t)bh * 512 * 128;
    const __nv_bfloat16* Bk = g_ks + (size_t)bh * 512 * 128;
    float* C = g_sc + (size_t)bh * 262144;

    const int tid = threadIdx.x;
    const int wid = tid >> 5, lane = tid & 31;
    const int wm = wid >> 1, wn = wid & 1;
    const int g  = lane >> 2, tg = lane & 3;

    const int Aoff[3] = { 0, 64, 0 };
    const int Boff[3] = { 0, 0, 64 };

    float acc[2][8][4];
#pragma unroll
    for (int mt = 0; mt < 2; mt++)
#pragma unroll
        for (int nt = 0; nt < 8; nt++)
#pragma unroll
            for (int e = 0; e < 4; e++) acc[mt][nt][e] = 0.f;

    auto load_chunk = [&](int c, int buf) {
        __nv_bfloat16* Ad = As + buf * SC_ABUF;
        __nv_bfloat16* Bd = Bs + buf * SC_ABUF;
#pragma unroll
        for (int i = 0; i < 4; i++) {
            int flat = i * 256 + tid;
            int row = flat >> 3, seg = flat & 7;
            cp_async16(Ad + row * PADK + seg * 8,
                       Aq + (size_t)(m0 + row) * 128 + Aoff[c] + seg * 8);
        }
#pragma unroll
        for (int i = 0; i < 4; i++) {
            int flat = i * 256 + tid;
            int row = flat >> 3, seg = flat & 7;
            cp_async16(Bd + row * PADK + seg * 8,
                       Bk + (size_t)(n0 + row) * 128 + Boff[c] + seg * 8);
        }
        cp_commit();
    };

    load_chunk(0, 0);

#pragma unroll 1
    for (int t = 0; t < 3; t++) {
        if (t < 2) load_chunk(t + 1, (t + 1) & 1);
        if (t < 2) cp_wait<1>(); else cp_wait<0>();
        __syncthreads();

        const __nv_bfloat16* Ab = As + (t & 1) * SC_ABUF;
        const __nv_bfloat16* Bb = Bs + (t & 1) * SC_ABUF;

#pragma unroll
        for (int ks = 0; ks < 4; ks++) {
            const int kb = ks * 16;
            uint32_t af[2][4], bf[8][2];
#pragma unroll
            for (int mt = 0; mt < 2; mt++) {
                int r0 = wm * 32 + mt * 16 + g;
                af[mt][0] = *(const uint32_t*)&Ab[(r0)      * PADK + kb + tg * 2];
                af[mt][1] = *(const uint32_t*)&Ab[(r0 + 8)  * PADK + kb + tg * 2];
                af[mt][2] = *(const uint32_t*)&Ab[(r0)      * PADK + kb + tg * 2 + 8];
                af[mt][3] = *(const uint32_t*)&Ab[(r0 + 8)  * PADK + kb + tg * 2 + 8];
            }
#pragma unroll
            for (int nt = 0; nt < 8; nt++) {
                int nr = wn * 64 + nt * 8 + g;
                bf[nt][0] = *(const uint32_t*)&Bb[nr * PADK + kb + tg * 2];
                bf[nt][1] = *(const uint32_t*)&Bb[nr * PADK + kb + tg * 2 + 8];
            }
#pragma unroll
            for (int mt = 0; mt < 2; mt++)
#pragma unroll
                for (int nt = 0; nt < 8; nt++)
                    mma_bf16(acc[mt][nt][0], acc[mt][nt][1], acc[mt][nt][2], acc[mt][nt][3],
                             af[mt][0], af[mt][1], af[mt][2], af[mt][3],
                             bf[nt][0], bf[nt][1]);
        }
        __syncthreads();
    }

#pragma unroll
    for (int mt = 0; mt < 2; mt++) {
        int r0 = m0 + wm * 32 + mt * 16 + g;
#pragma unroll
        for (int nt = 0; nt < 8; nt++) {
            int cl = wn * 64 + nt * 8 + tg * 2;
            *(float2*)&C[(size_t)r0 * 512 + n0 + cl] =
                make_float2(acc[mt][nt][0], acc[mt][nt][1]);
            *(float2*)&C[(size_t)(r0 + 8) * 512 + n0 + cl] =
                make_float2(acc[mt][nt][2], acc[mt][nt][3]);
        }
    }
}

// =============================================================================
// K3: fused per-(b,q) — WARP-SPECIALIZED: warps 8-15 produce (LDG+cvt+STS of
// rels, 8 groups x 64 rows, bar.arrive per group); warps 0-7 consume (stage B
// per group on bar.sync).  Softmax on consumers; stage D on all 16 warps.
// =============================================================================
#define F_RH 0
#define F_RL 65536
#define F_SC 131072
#define F_QS 147584
#define F_PS 151936
#define F_RED 168576
#define SMEM_FUSED 184960

__global__ __launch_bounds__(512) void k_fused(
    const float* __restrict__ rels,
    const float* __restrict__ heads,
    float* __restrict__ out)
{
    extern __shared__ char smf[];
    const uint32_t sbase = (uint32_t)__cvta_generic_to_shared(smf);
    float* sc_s = (float*)(smf + F_SC);
    __nv_bfloat16* QS = (__nv_bfloat16*)(smf + F_QS);
    __nv_bfloat16* PS = (__nv_bfloat16*)(smf + F_PS);
    float* red = (float*)(smf + F_RED);

    const int bq = blockIdx.x;
    const int b = bq >> 9, q = bq & 511;
    const int tid = threadIdx.x;
    const int lane = tid & 31, w = tid >> 5;

    const float* rg = rels + (size_t)bq * (512 * 64);

    if (w >= 8) {
        // ===================== PRODUCERS (warps 8-15) =======================
        const int pt = tid - 256;
        const int rr = pt >> 2;              // 0..63 local row
        const int dseg = (pt & 3) * 16;      // float column base
        const int c0 = (pt & 3) * 2;         // chunk base
        const int s7 = rr & 7;

        float4 cur[4], nxt[4];
        {
            const float4* s = (const float4*)(rg + (size_t)rr * 64 + dseg);
            cur[0] = s[0]; cur[1] = s[1]; cur[2] = s[2]; cur[3] = s[3];
        }
#pragma unroll 1
        for (int g = 0; g < 8; g++) {
            if (g < 7) {
                const float4* s = (const float4*)(rg + (size_t)((g + 1) * 64 + rr) * 64 + dseg);
                nxt[0] = s[0]; nxt[1] = s[1]; nxt[2] = s[2]; nxt[3] = s[3];
            }
            int row = g * 64 + rr;
            char* rhrow = smf + F_RH + row * 128;
            char* rlrow = smf + F_RL + row * 128;
#pragma unroll
            for (int jj = 0; jj < 2; jj++) {
                const float* xs = (const float*)&cur[jj * 2];
                uint32_t hw[4], lw[4];
#pragma unroll
                for (int j = 0; j < 4; j++) {
                    float x0 = xs[2 * j], x1 = xs[2 * j + 1];
                    uint32_t u0 = __float_as_uint(x0), u1 = __float_as_uint(x1);
                    hw[j] = __byte_perm(u0, u1, 0x7632);
                    float h0f = __uint_as_float(u0 & 0xFFFF0000u);
                    float h1f = __uint_as_float(u1 & 0xFFFF0000u);
                    lw[j] = cvt_bf16x2(x0 - h0f, x1 - h1f);
                }
                int chunk = c0 + jj;
                *(uint4*)(rhrow + ((chunk ^ s7) << 4)) = make_uint4(hw[0], hw[1], hw[2], hw[3]);
                *(uint4*)(rlrow + ((chunk ^ s7) << 4)) = make_uint4(lw[0], lw[1], lw[2], lw[3]);
            }
            NBAR_ARRIVE(g + 1, 512);
            cur[0] = nxt[0]; cur[1] = nxt[1]; cur[2] = nxt[2]; cur[3] = nxt[3];
        }
    } else {
        // ===================== CONSUMERS (warps 0-7) ========================
        if (tid < 128) {
            int h = tid >> 4, dq = tid & 15;
            const __nv_bfloat16* src = g_qs + ((size_t)(b * 8 + h) * 512 + q) * 128 + dq * 4;
            *(uint2*)&QS[h * 136 + dq * 4]       = *(const uint2*)src;
            *(uint2*)&QS[(h + 8) * 136 + dq * 4] = *(const uint2*)(src + 64);
        }
        NBAR_SYNC(9, 256);

        uint32_t afr[4][4];
#pragma unroll
        for (int ds = 0; ds < 4; ds++) {
            uint32_t addr = sbase + F_QS + (lane & 15) * 272
                          + (ds * 16 + ((lane >> 4) << 3)) * 2;
            ldm_x4(afr[ds], addr);
        }

        float2 qkPre[8], hvPre[8];
        {
            int hh = lane >> 2;
            int kkb = w * 8 + (lane & 3) * 2;
#pragma unroll
            for (int g = 0; g < 8; g++) {
                int kk = g * 64 + kkb;
                qkPre[g] = *(const float2*)&g_sc[(size_t)(b * 8 + hh) * 262144
                                                 + (size_t)q * 512 + kk];
                hvPre[g] = *(const float2*)&heads[((size_t)b * 512 + q) * 512 + kk];
            }
        }

#pragma unroll 1
        for (int g = 0; g < 8; g++) {
            NBAR_SYNC(g + 1, 512);
            const int k0 = g * 64 + w * 8;
            float p0c0 = 0.f, p0c1 = 0.f, p0c2 = 0.f, p0c3 = 0.f;
            float p1c0 = 0.f, p1c1 = 0.f, p1c2 = 0.f, p1c3 = 0.f;
            const int row = k0 + (lane & 7);
            const int s7 = row & 7;
            const int csel = (lane >> 3) & 1;
#pragma unroll
            for (int ds = 0; ds < 4; ds++) {
                int chunk = ds * 2 + csel;
                uint32_t b0, b1;
                ldm_x2(b0, b1, sbase + F_RH + row * 128 + ((chunk ^ s7) << 4));
                mma_bf16(p0c0, p0c1, p0c2, p0c3,
                         afr[ds][0], afr[ds][1], afr[ds][2], afr[ds][3], b0, b1);
            }
#pragma unroll
            for (int ds = 0; ds < 4; ds++) {
                int chunk = ds * 2 + csel;
                uint32_t b0, b1;
                ldm_x2(b0, b1, sbase + F_RL + row * 128 + ((chunk ^ s7) << 4));
                mma_bf16(p1c0, p1c1, p1c2, p1c3,
                         afr[ds][0], 0u, afr[ds][2], 0u, b0, b1);
            }
            float a0 = p0c0 + p0c2 + p1c0;
            float a1 = p0c1 + p0c3 + p1c1;
            int h = lane >> 2, kk = k0 + (lane & 3) * 2;
            sc_s[h * 516 + kk]     = (a0 + qkPre[g].x) * 0.125f + hvPre[g].x;
            sc_s[h * 516 + kk + 1] = (a1 + qkPre[g].y) * 0.125f + hvPre[g].y;
        }
        NBAR_SYNC(9, 256);

        // ---- softmax (consumer warp w == head w) + PS + g_ps ----
        {
            float* row = sc_s + w * 516;
            float vals[16];
            float mx = -1e30f;
#pragma unroll
            for (int i = 0; i < 16; i++) { vals[i] = row[i * 32 + lane]; mx = fmaxf(mx, vals[i]); }
#pragma unroll
            for (int o = 16; o; o >>= 1) mx = fmaxf(mx, __shfl_xor_sync(0xffffffffu, mx, o));
            float s = 0.f;
#pragma unroll
            for (int i = 0; i < 16; i++) { vals[i] = __expf(vals[i] - mx); s += vals[i]; }
#pragma unroll
            for (int o = 16; o; o >>= 1) s += __shfl_xor_sync(0xffffffffu, s, o);
            float inv = 1.f / s;
            __nv_bfloat16* pgp = g_ps + ((size_t)(b * 8 + w) * 512 + q) * 1024;
#pragma unroll
            for (int i = 0; i < 16; i++) {
                float pv = vals[i] * inv;
                int kk = i * 32 + lane;
                __nv_bfloat16 ph = __float2bfloat16(pv);
                __nv_bfloat16 pl = __float2bfloat16(pv - __bfloat162float(ph));
                PS[w * 520 + kk] = ph;
                PS[(w + 8) * 520 + kk] = pl;
                pgp[kk] = ph;
                pgp[512 + kk] = pl;
            }
        }
    }
    __syncthreads();   // PS + all rels groups visible to all 16 warps

    // ---- stage D: warp (kg = w>>1 of 8, ng = w&1), 4 n-tiles; 2 passes ----
    {
        const int kg = w >> 1, ng = w & 1;
        float aD[4][4];
#pragma unroll
        for (int i = 0; i < 4; i++)
#pragma unroll
            for (int j = 0; j < 4; j++) aD[i][j] = 0.f;

#pragma unroll
        for (int ks = 0; ks < 4; ks++) {
            const int k0 = kg * 64 + ks * 16;
            uint32_t af[4];
            uint32_t aaddr = sbase + F_PS + (lane & 15) * 1040
                           + (k0 + ((lane >> 4) << 3)) * 2;
            ldm_x4(af, aaddr);
            const int row = k0 + (lane & 7) + (((lane >> 3) & 1) << 3);
            const int s7 = row & 7;
#pragma unroll
            for (int ntl = 0; ntl < 4; ntl++) {
                int d0 = (ng * 4 + ntl) * 8;
                uint32_t b0, b1;
                ldm_x2_trans(b0, b1, sbase + F_RH + row * 128 + (((d0 >> 3) ^ s7) << 4));
                mma_bf16(aD[ntl][0], aD[ntl][1], aD[ntl][2], aD[ntl][3],
                         af[0], af[1], af[2], af[3], b0, b1);
            }
#pragma unroll
            for (int ntl = 0; ntl < 4; ntl++) {
                int d0 = (ng * 4 + ntl) * 8;
                uint32_t b0, b1;
                ldm_x2_trans(b0, b1, sbase + F_RL + row * 128 + (((d0 >> 3) ^ s7) << 4));
                mma_bf16(aD[ntl][0], aD[ntl][1], aD[ntl][2], aD[ntl][3],
                         af[0], 0u, af[2], 0u, b0, b1);
            }
        }
#pragma unroll
        for (int ntl = 0; ntl < 4; ntl++) {
            int slot = kg * 8 + ng * 4 + ntl;
            *(float2*)&red[(slot * 32 + lane) * 2] =
                make_float2(aD[ntl][0] + aD[ntl][2], aD[ntl][1] + aD[ntl][3]);
        }
    }
    __syncthreads();

    if (w < 8) {
        float rx = 0.f, ry = 0.f;
#pragma unroll
        for (int kg = 0; kg < 8; kg++) {
            float2 s = *(const float2*)&red[((kg * 8 + w) * 32 + lane) * 2];
            rx += s.x; ry += s.y;
        }
        int h = lane >> 2, d = w * 8 + (lane & 3) * 2;
        *(float2*)&out[((size_t)b * 512 + q) * 512 + h * 64 + d] = make_float2(rx, ry);
    }
}

// =============================================================================
// K4: ctx += probs @ v via mma.sync (unchanged).
// =============================================================================
__global__ __launch_bounds__(256) void k_ctx_mma(float* __restrict__ out)
{
    extern __shared__ char smp[];
    __nv_bfloat16* As = (__nv_bfloat16*)smp;
    __nv_bfloat16* Bs = As + 2 * A_BUF_ELE;

    const int m0 = blockIdx.x * 128;
    const int bh = blockIdx.y;
    const int tbase = blockIdx.z * 12;
    const int b = bh >> 3, h = bh & 7;
    const __nv_bfloat16* Ap = g_ps + (size_t)bh * 512 * 1024;
    const __nv_bfloat16* Bv = g_vT + (size_t)bh * 64 * 1024;

    const int tid = threadIdx.x;
    const int wid = tid >> 5, lane = tid & 31;
    const int wm = wid >> 1, wn = wid & 1;
    const int g  = lane >> 2, tg = lane & 3;

    float acc[2][4][4];
#pragma unroll
    for (int mt = 0; mt < 2; mt++)
#pragma unroll
        for (int nt = 0; nt < 4; nt++)
#pragma unroll
            for (int e = 0; e < 4; e++) acc[mt][nt][e] = 0.f;

    auto aoff = [](int t) { return t < 8 ? t * 64 : t < 16 ? 512 + (t - 8) * 64 : (t - 16) * 64; };
    auto boff = [](int t) { return t < 8 ? t * 64 : t < 16 ? (t - 8) * 64 : 512 + (t - 16) * 64; };

    auto load_chunk = [&](int c, int buf) {
        __nv_bfloat16* Ad = As + buf * A_BUF_ELE;
        __nv_bfloat16* Bd = Bs + buf * B_BUF_ELE;
        int ao = aoff(c), bo = boff(c);
#pragma unroll
        for (int i = 0; i < 4; i++) {
            int flat = i * 256 + tid;
            int row = flat >> 3, seg = flat & 7;
            cp_async16(Ad + row * PADK + seg * 8,
                       Ap + (size_t)(m0 + row) * 1024 + ao + seg * 8);
        }
#pragma unroll
        for (int i = 0; i < 2; i++) {
            int flat = i * 256 + tid;
            int row = flat >> 3, seg = flat & 7;
            cp_async16(Bd + row * PADK + seg * 8,
                       Bv + (size_t)row * 1024 + bo + seg * 8);
        }
        cp_commit();
    };

    load_chunk(tbase, 0);

#pragma unroll 1
    for (int t = 0; t < 12; t++) {
        if (t < 11) load_chunk(tbase + t + 1, (t + 1) & 1);
        if (t < 11) cp_wait<1>(); else cp_wait<0>();
        __syncthreads();

        const __nv_bfloat16* Ab = As + (t & 1) * A_BUF_ELE;
        const __nv_bfloat16* Bb = Bs + (t & 1) * B_BUF_ELE;

#pragma unroll
        for (int ks = 0; ks < 4; ks++) {
            const int kb = ks * 16;
            uint32_t af[2][4], bf[4][2];
#pragma unroll
            for (int mt = 0; mt < 2; mt++) {
                int r0 = wm * 32 + mt * 16 + g;
                af[mt][0] = *(const uint32_t*)&Ab[(r0)      * PADK + kb + tg * 2];
                af[mt][1] = *(const uint32_t*)&Ab[(r0 + 8)  * PADK + kb + tg * 2];
                af[mt][2] = *(const uint32_t*)&Ab[(r0)      * PADK + kb + tg * 2 + 8];
                af[mt][3] = *(const uint32_t*)&Ab[(r0 + 8)  * PADK + kb + tg * 2 + 8];
            }
#pragma unroll
            for (int nt = 0; nt < 4; nt++) {
                int nr = wn * 32 + nt * 8 + g;
                bf[nt][0] = *(const uint32_t*)&Bb[nr * PADK + kb + tg * 2];
                bf[nt][1] = *(const uint32_t*)&Bb[nr * PADK + kb + tg * 2 + 8];
            }
#pragma unroll
            for (int mt = 0; mt < 2; mt++)
#pragma unroll
                for (int nt = 0; nt < 4; nt++)
                    mma_bf16(acc[mt][nt][0], acc[mt][nt][1], acc[mt][nt][2], acc[mt][nt][3],
                             af[mt][0], af[mt][1], af[mt][2], af[mt][3],
                             bf[nt][0], bf[nt][1]);
        }
        __syncthreads();
    }

#pragma unroll
    for (int mt = 0; mt < 2; mt++) {
        int r0 = m0 + wm * 32 + mt * 16 + g;
#pragma unroll
        for (int nt = 0; nt < 4; nt++) {
            int cl = wn * 32 + nt * 8 + tg * 2;
            float* p0 = &out[((size_t)(b * 512 + r0)) * 512 + h * 64 + cl];
            atomicAdd(p0 + 0, acc[mt][nt][0]);
            atomicAdd(p0 + 1, acc[mt][nt][1]);
            float* p1 = &out[((size_t)(b * 512 + r0 + 8)) * 512 + h * 64 + cl];
            atomicAdd(p1 + 0, acc[mt][nt][2]);
            atomicAdd(p1 + 1, acc[mt][nt][3]);
        }
    }
}

// =============================================================================
extern "C" void kernel_launch(void* const* d_in, const int* in_sizes, int n_in,
                              void* d_out, int out_size)
{
    const float* hidden = (const float*)d_in[0];
    const float* heads  = (const float*)d_in[1];
    const float* rels   = (const float*)d_in[2];
    const float* Wq = (const float*)d_in[3];
    const float* bq = (const float*)d_in[4];
    const float* Wk = (const float*)d_in[5];
    const float* bk = (const float*)d_in[6];
    const float* Wv = (const float*)d_in[7];
    const float* bv = (const float*)d_in[8];
    float* out = (float*)d_out;

    k_prep<<<1024, 256>>>(hidden, Wq, Wk, Wv);

    cudaFuncSetAttribute(k_proj_mma, cudaFuncAttributeMaxDynamicSharedMemorySize, SMEM_PROJ);
    dim3 g1(8, 16, 3);
    k_proj_mma<<<g1, 256, SMEM_PROJ>>>(bq, bk, bv);

    dim3 gv(32, 8);
    k_vsplit<<<gv, 256>>>();

    cudaFuncSetAttribute(k_scores_mma, cudaFuncAttributeMaxDynamicSharedMemorySize, SMEM_SC);
    dim3 g2(4, 4, 32);
    k_scores_mma<<<g2, 256, SMEM_SC>>>();

    cudaFuncSetAttribute(k_fused, cudaFuncAttributeMaxDynamicSharedMemorySize, SMEM_FUSED);
    k_fused<<<2048, 512, SMEM_FUSED>>>(rels, heads, out);

    cudaFuncSetAttribute(k_ctx_mma, cudaFuncAttributeMaxDynamicSharedMemorySize, SMEM_PROJ);
    dim3 g4(4, 32, 2);
    k_ctx_mma<<<g4, 256, SMEM_PROJ>>>(out);
}

// round 15
// speedup vs baseline: 2.2741x; 1.0204x over previous
#include <cuda_runtime.h>
#include <cuda_bf16.h>
#include <cstdint>
#include <cstddef>

#define B_ 4
#define L_ 512
#define HID_ 512
#define H_ 8
#define DH_ 64

// ---------------- scratch (device globals; no allocations allowed) ----------
__device__ float g_sc[B_ * H_ * L_ * L_];            // qk scores (fp32)
__device__ __nv_bfloat16 g_Xs[2048 * 1536];          // proj A split
__device__ __nv_bfloat16 g_Ws[3 * 512 * 1536];       // proj B split
__device__ __nv_bfloat16 g_qs[32 * 512 * 128];       // q split [bh][l][qh|ql]
__device__ __nv_bfloat16 g_ks[32 * 512 * 128];       // k split [bh][l][kh|kl]
__device__ __nv_bfloat16 g_ps[32 * 512 * 1024];      // probs split [bh][q][ph|pl]
__device__ __nv_bfloat16 g_vT[32 * 64 * 1024];       // v^T split [bh][d][vh|vl]

// ---------------- cp.async helpers ------------------------------------------
__device__ __forceinline__ void cp_async16(void* smem, const void* gmem) {
    unsigned s = (unsigned)__cvta_generic_to_shared(smem);
    asm volatile("cp.async.cg.shared.global [%0], [%1], 16;\n" :: "r"(s), "l"(gmem));
}
__device__ __forceinline__ void cp_commit() {
    asm volatile("cp.async.commit_group;\n");
}
template <int N>
__device__ __forceinline__ void cp_wait() {
    asm volatile("cp.async.wait_group %0;\n" :: "n"(N));
}

// ---------------- warp mma / ldmatrix (sm_80+, no 'a' feature) ---------------
__device__ __forceinline__ void mma_bf16(float& c0, float& c1, float& c2, float& c3,
                                         uint32_t a0, uint32_t a1, uint32_t a2, uint32_t a3,
                                         uint32_t b0, uint32_t b1) {
    asm volatile(
        "mma.sync.aligned.m16n8k16.row.col.f32.bf16.bf16.f32 "
        "{%0,%1,%2,%3}, {%4,%5,%6,%7}, {%8,%9}, {%0,%1,%2,%3};"
        : "+f"(c0), "+f"(c1), "+f"(c2), "+f"(c3)
        : "r"(a0), "r"(a1), "r"(a2), "r"(a3), "r"(b0), "r"(b1));
}
__device__ __forceinline__ void ldm_x4(uint32_t* r, uint32_t addr) {
    asm volatile("ldmatrix.sync.aligned.m8n8.x4.shared.b16 {%0,%1,%2,%3}, [%4];"
                 : "=r"(r[0]), "=r"(r[1]), "=r"(r[2]), "=r"(r[3]) : "r"(addr));
}
__device__ __forceinline__ void ldm_x2(uint32_t& r0, uint32_t& r1, uint32_t addr) {
    asm volatile("ldmatrix.sync.aligned.m8n8.x2.shared.b16 {%0,%1}, [%2];"
                 : "=r"(r0), "=r"(r1) : "r"(addr));
}
__device__ __forceinline__ void ldm_x2_trans(uint32_t& r0, uint32_t& r1, uint32_t addr) {
    asm volatile("ldmatrix.sync.aligned.m8n8.x2.trans.shared.b16 {%0,%1}, [%2];"
                 : "=r"(r0), "=r"(r1) : "r"(addr));
}
__device__ __forceinline__ uint32_t cvt_bf16x2(float a, float b) {
    uint32_t w;
    asm("cvt.rn.bf16x2.f32 %0, %1, %2;" : "=r"(w) : "f"(b), "f"(a));
    return w;
}
#define NBAR_SYNC(id, cnt) \
    asm volatile("bar.sync %0, %1;" :: "r"(id), "r"(cnt) : "memory")
#define NBAR_ARRIVE(id, cnt) \
    asm volatile("bar.arrive %0, %1;" :: "r"(id), "r"(cnt) : "memory")

// =============================================================================
// K0: build split-bf16 operands for the projection, K=1536.
// =============================================================================
__global__ __launch_bounds__(256) void k_prep(
    const float* __restrict__ X,
    const float* __restrict__ Wq, const float* __restrict__ Wk,
    const float* __restrict__ Wv)
{
    const int stride = gridDim.x * blockDim.x;
    for (int i = blockIdx.x * blockDim.x + threadIdx.x; i < 2048 * 512; i += stride) {
        int m = i >> 9, k = i & 511;
        float x = X[i];
        __nv_bfloat16 hi = __float2bfloat16(x);
        __nv_bfloat16 lo = __float2bfloat16(x - __bfloat162float(hi));
        __nv_bfloat16* row = g_Xs + (size_t)m * 1536;
        row[k] = hi; row[512 + k] = lo; row[1024 + k] = hi;
    }
    for (int i = blockIdx.x * blockDim.x + threadIdx.x; i < 3 * 512 * 512; i += stride) {
        int z = i >> 18;
        int r = i & 262143;
        const float* W = (z == 0) ? Wq : (z == 1) ? Wk : Wv;
        int n = r >> 9, k = r & 511;
        float x = W[r];
        __nv_bfloat16 hi = __float2bfloat16(x);
        __nv_bfloat16 lo = __float2bfloat16(x - __bfloat162float(hi));
        __nv_bfloat16* row = g_Ws + (size_t)z * 512 * 1536 + (size_t)n * 1536;
        row[k] = hi; row[512 + k] = hi; row[1024 + k] = lo;
    }
}

// =============================================================================
// K1: QKV projection via mma.sync.  z=0/1 -> split bf16 q/k; z=2 -> smem
// transpose + split write straight to g_vT (k_vsplit eliminated).
// =============================================================================
#define PADK 72
#define A_BUF_ELE (128 * PADK)
#define B_BUF_ELE (64 * PADK)
#define SMEM_PROJ ((2 * A_BUF_ELE + 2 * B_BUF_ELE) * 2 + 64 * 4)

__global__ __launch_bounds__(256) void k_proj_mma(
    const float* __restrict__ bq, const float* __restrict__ bk,
    const float* __restrict__ bv)
{
    extern __shared__ char smp[];
    __nv_bfloat16* As = (__nv_bfloat16*)smp;
    __nv_bfloat16* Bs = As + 2 * A_BUF_ELE;
    float* biasS = (float*)(Bs + 2 * B_BUF_ELE);

    const int n0 = blockIdx.x * 64;
    const int m0 = blockIdx.y * 128;
    const int z  = blockIdx.z;
    const float* bias = (z == 0) ? bq : (z == 1) ? bk : bv;
    const __nv_bfloat16* Wz = g_Ws + (size_t)z * 512 * 1536;

    const int tid = threadIdx.x;
    const int wid = tid >> 5, lane = tid & 31;
    const int wm = wid >> 1, wn = wid & 1;
    const int g  = lane >> 2, tg = lane & 3;

    if (tid < 64) biasS[tid] = bias[n0 + tid];

    float acc[2][4][4];
#pragma unroll
    for (int mt = 0; mt < 2; mt++)
#pragma unroll
        for (int nt = 0; nt < 4; nt++)
#pragma unroll
            for (int e = 0; e < 4; e++) acc[mt][nt][e] = 0.f;

    auto load_chunk = [&](int c, int buf) {
        __nv_bfloat16* Ad = As + buf * A_BUF_ELE;
        __nv_bfloat16* Bd = Bs + buf * B_BUF_ELE;
#pragma unroll
        for (int i = 0; i < 4; i++) {
            int flat = i * 256 + tid;
            int row = flat >> 3, seg = flat & 7;
            cp_async16(Ad + row * PADK + seg * 8,
                       g_Xs + (size_t)(m0 + row) * 1536 + c * 64 + seg * 8);
        }
#pragma unroll
        for (int i = 0; i < 2; i++) {
            int flat = i * 256 + tid;
            int row = flat >> 3, seg = flat & 7;
            cp_async16(Bd + row * PADK + seg * 8,
                       Wz + (size_t)(n0 + row) * 1536 + c * 64 + seg * 8);
        }
        cp_commit();
    };

    load_chunk(0, 0);

#pragma unroll 1
    for (int t = 0; t < 24; t++) {
        if (t < 23) load_chunk(t + 1, (t + 1) & 1);
        if (t < 23) cp_wait<1>(); else cp_wait<0>();
        __syncthreads();

        const __nv_bfloat16* Ab = As + (t & 1) * A_BUF_ELE;
        const __nv_bfloat16* Bb = Bs + (t & 1) * B_BUF_ELE;

#pragma unroll
        for (int ks = 0; ks < 4; ks++) {
            const int kb = ks * 16;
            uint32_t af[2][4], bf[4][2];
#pragma unroll
            for (int mt = 0; mt < 2; mt++) {
                int r0 = wm * 32 + mt * 16 + g;
                af[mt][0] = *(const uint32_t*)&Ab[(r0)      * PADK + kb + tg * 2];
                af[mt][1] = *(const uint32_t*)&Ab[(r0 + 8)  * PADK + kb + tg * 2];
                af[mt][2] = *(const uint32_t*)&Ab[(r0)      * PADK + kb + tg * 2 + 8];
                af[mt][3] = *(const uint32_t*)&Ab[(r0 + 8)  * PADK + kb + tg * 2 + 8];
            }
#pragma unroll
            for (int nt = 0; nt < 4; nt++) {
                int nr = wn * 32 + nt * 8 + g;
                bf[nt][0] = *(const uint32_t*)&Bb[nr * PADK + kb + tg * 2];
                bf[nt][1] = *(const uint32_t*)&Bb[nr * PADK + kb + tg * 2 + 8];
            }
#pragma unroll
            for (int mt = 0; mt < 2; mt++)
#pragma unroll
                for (int nt = 0; nt < 4; nt++)
                    mma_bf16(acc[mt][nt][0], acc[mt][nt][1], acc[mt][nt][2], acc[mt][nt][3],
                             af[mt][0], af[mt][1], af[mt][2], af[mt][3],
                             bf[nt][0], bf[nt][1]);
        }
        __syncthreads();
    }

    const int hh = n0 >> 6;

    if (z == 2) {
        // ---- V path: stage fp32 tile in smem, transpose + split to g_vT ----
        float* vts = (float*)smp;           // 128 x 68 floats (smem now free)
#pragma unroll
        for (int mt = 0; mt < 2; mt++) {
            int rl = wm * 32 + mt * 16 + g;
#pragma unroll
            for (int nt = 0; nt < 4; nt++) {
                int cl = wn * 32 + nt * 8 + tg * 2;
                vts[rl * 68 + cl]           = acc[mt][nt][0] + biasS[cl];
                vts[rl * 68 + cl + 1]       = acc[mt][nt][1] + biasS[cl + 1];
                vts[(rl + 8) * 68 + cl]     = acc[mt][nt][2] + biasS[cl];
                vts[(rl + 8) * 68 + cl + 1] = acc[mt][nt][3] + biasS[cl + 1];
            }
        }
        __syncthreads();
        const int d = tid & 63, ksb = tid >> 6;   // 64 d x 4 l-quads
        const int bh = (m0 >> 9) * 8 + hh;
        const int l0 = (m0 & 511) + ksb * 32;
        __nv_bfloat16* dst = g_vT + ((size_t)bh * 64 + d) * 1024 + l0;
#pragma unroll
        for (int seg = 0; seg < 4; seg++) {
            union { __nv_bfloat16 bb[8]; uint4 u; } hu, lu;
#pragma unroll
            for (int j = 0; j < 8; j++) {
                float x = vts[(ksb * 32 + seg * 8 + j) * 68 + d];
                __nv_bfloat16 hb = __float2bfloat16(x);
                hu.bb[j] = hb;
                lu.bb[j] = __float2bfloat16(x - __bfloat162float(hb));
            }
            *(uint4*)(dst + seg * 8)       = hu.u;
            *(uint4*)(dst + 512 + seg * 8) = lu.u;
        }
    } else {
        __nv_bfloat16* QK = (z == 0) ? g_qs : g_ks;
#pragma unroll
        for (int mt = 0; mt < 2; mt++) {
            int r0 = m0 + wm * 32 + mt * 16 + g;
#pragma unroll
            for (int nt = 0; nt < 4; nt++) {
                int cl = wn * 32 + nt * 8 + tg * 2;
                float x00 = acc[mt][nt][0] + biasS[cl];
                float x01 = acc[mt][nt][1] + biasS[cl + 1];
                float x10 = acc[mt][nt][2] + biasS[cl];
                float x11 = acc[mt][nt][3] + biasS[cl + 1];
                int b0 = r0 >> 9, l0 = r0 & 511;
                int b1 = (r0 + 8) >> 9, l1 = (r0 + 8) & 511;
                __nv_bfloat16* d0 = QK + ((size_t)(b0 * 8 + hh) * 512 + l0) * 128 + cl;
                __nv_bfloat16* d1 = QK + ((size_t)(b1 * 8 + hh) * 512 + l1) * 128 + cl;
                __nv_bfloat16 h00 = __float2bfloat16(x00), h01 = __float2bfloat16(x01);
                __nv_bfloat16 h10 = __float2bfloat16(x10), h11 = __float2bfloat16(x11);
                *(uint32_t*)d0 = ((uint32_t)__bfloat16_as_ushort(h01) << 16)
                               | __bfloat16_as_ushort(h00);
                *(uint32_t*)d1 = ((uint32_t)__bfloat16_as_ushort(h11) << 16)
                               | __bfloat16_as_ushort(h10);
                *(uint32_t*)(d0 + 64) = cvt_bf16x2(x00 - __bfloat162float(h00),
                                                   x01 - __bfloat162float(h01));
                *(uint32_t*)(d1 + 64) = cvt_bf16x2(x10 - __bfloat162float(h10),
                                                   x11 - __bfloat162float(h11));
            }
        }
    }
}

// =============================================================================
// K2: scores via mma.sync, BM=BN=128, SINGLE-PHASE: all 3 K-chunks resident
// (108KB smem, one cp.async batch, one sync, 12 straight MMA steps).
// grid (4, 4, 32) = 512 CTAs, 2 CTAs/SM.
// =============================================================================
#define SC_TILE (128 * PADK)
#define SMEM_SC2 (6 * SC_TILE * 2)

__global__ __launch_bounds__(256) void k_scores_mma()
{
    extern __shared__ char smp[];
    __nv_bfloat16* As = (__nv_bfloat16*)smp;          // 3 chunk tiles
    __nv_bfloat16* Bs = As + 3 * SC_TILE;             // 3 chunk tiles

    const int n0 = blockIdx.x * 128;
    const int m0 = blockIdx.y * 128;
    const int bh = blockIdx.z;
    const __nv_bfloat16* Aq = g_qs + (size_t)bh * 512 * 128;
    const __nv_bfloat16* Bk = g_ks + (size_t)bh * 512 * 128;
    float* C = g_sc + (size_t)bh * 262144;

    const int tid = threadIdx.x;
    const int wid = tid >> 5, lane = tid & 31;
    const int wm = wid >> 1, wn = wid & 1;
    const int g  = lane >> 2, tg = lane & 3;

    const int Aoff[3] = { 0, 64, 0 };
    const int Boff[3] = { 0, 0, 64 };

    // one-shot load of all 3 chunks (A and B)
#pragma unroll
    for (int c = 0; c < 3; c++) {
#pragma unroll
        for (int i = 0; i < 4; i++) {
            int flat = i * 256 + tid;
            int row = flat >> 3, seg = flat & 7;
            cp_async16(As + c * SC_TILE + row * PADK + seg * 8,
                       Aq + (size_t)(m0 + row) * 128 + Aoff[c] + seg * 8);
        }
#pragma unroll
        for (int i = 0; i < 4; i++) {
            int flat = i * 256 + tid;
            int row = flat >> 3, seg = flat & 7;
            cp_async16(Bs + c * SC_TILE + row * PADK + seg * 8,
                       Bk + (size_t)(n0 + row) * 128 + Boff[c] + seg * 8);
        }
    }
    cp_commit();
    cp_wait<0>();
    __syncthreads();

    float acc[2][8][4];
#pragma unroll
    for (int mt = 0; mt < 2; mt++)
#pragma unroll
        for (int nt = 0; nt < 8; nt++)
#pragma unroll
            for (int e = 0; e < 4; e++) acc[mt][nt][e] = 0.f;

#pragma unroll
    for (int c = 0; c < 3; c++) {
        const __nv_bfloat16* Ab = As + c * SC_TILE;
        const __nv_bfloat16* Bb = Bs + c * SC_TILE;
#pragma unroll
        for (int ks = 0; ks < 4; ks++) {
            const int kb = ks * 16;
            uint32_t af[2][4], bf[8][2];
#pragma unroll
            for (int mt = 0; mt < 2; mt++) {
                int r0 = wm * 32 + mt * 16 + g;
                af[mt][0] = *(const uint32_t*)&Ab[(r0)      * PADK + kb + tg * 2];
                af[mt][1] = *(const uint32_t*)&Ab[(r0 + 8)  * PADK + kb + tg * 2];
                af[mt][2] = *(const uint32_t*)&Ab[(r0)      * PADK + kb + tg * 2 + 8];
                af[mt][3] = *(const uint32_t*)&Ab[(r0 + 8)  * PADK + kb + tg * 2 + 8];
            }
#pragma unroll
            for (int nt = 0; nt < 8; nt++) {
                int nr = wn * 64 + nt * 8 + g;
                bf[nt][0] = *(const uint32_t*)&Bb[nr * PADK + kb + tg * 2];
                bf[nt][1] = *(const uint32_t*)&Bb[nr * PADK + kb + tg * 2 + 8];
            }
#pragma unroll
            for (int mt = 0; mt < 2; mt++)
#pragma unroll
                for (int nt = 0; nt < 8; nt++)
                    mma_bf16(acc[mt][nt][0], acc[mt][nt][1], acc[mt][nt][2], acc[mt][nt][3],
                             af[mt][0], af[mt][1], af[mt][2], af[mt][3],
                             bf[nt][0], bf[nt][1]);
        }
    }

#pragma unroll
    for (int mt = 0; mt < 2; mt++) {
        int r0 = m0 + wm * 32 + mt * 16 + g;
#pragma unroll
        for (int nt = 0; nt < 8; nt++) {
            int cl = wn * 64 + nt * 8 + tg * 2;
            *(float2*)&C[(size_t)r0 * 512 + n0 + cl] =
                make_float2(acc[mt][nt][0], acc[mt][nt][1]);
            *(float2*)&C[(size_t)(r0 + 8) * 512 + n0 + cl] =
                make_float2(acc[mt][nt][2], acc[mt][nt][3]);
        }
    }
}

// =============================================================================
// K3: fused per-(b,q) — warp-specialized (unchanged from R14).
// =============================================================================
#define F_RH 0
#define F_RL 65536
#define F_SC 131072
#define F_QS 147584
#define F_PS 151936
#define F_RED 168576
#define SMEM_FUSED 184960

__global__ __launch_bounds__(512) void k_fused(
    const float* __restrict__ rels,
    const float* __restrict__ heads,
    float* __restrict__ out)
{
    extern __shared__ char smf[];
    const uint32_t sbase = (uint32_t)__cvta_generic_to_shared(smf);
    float* sc_s = (float*)(smf + F_SC);
    __nv_bfloat16* QS = (__nv_bfloat16*)(smf + F_QS);
    __nv_bfloat16* PS = (__nv_bfloat16*)(smf + F_PS);
    float* red = (float*)(smf + F_RED);

    const int bq = blockIdx.x;
    const int b = bq >> 9, q = bq & 511;
    const int tid = threadIdx.x;
    const int lane = tid & 31, w = tid >> 5;

    const float* rg = rels + (size_t)bq * (512 * 64);

    if (w >= 8) {
        const int pt = tid - 256;
        const int rr = pt >> 2;
        const int dseg = (pt & 3) * 16;
        const int c0 = (pt & 3) * 2;
        const int s7 = rr & 7;

        float4 cur[4], nxt[4];
        {
            const float4* s = (const float4*)(rg + (size_t)rr * 64 + dseg);
            cur[0] = s[0]; cur[1] = s[1]; cur[2] = s[2]; cur[3] = s[3];
        }
#pragma unroll 1
        for (int g = 0; g < 8; g++) {
            if (g < 7) {
                const float4* s = (const float4*)(rg + (size_t)((g + 1) * 64 + rr) * 64 + dseg);
                nxt[0] = s[0]; nxt[1] = s[1]; nxt[2] = s[2]; nxt[3] = s[3];
            }
            int row = g * 64 + rr;
            char* rhrow = smf + F_RH + row * 128;
            char* rlrow = smf + F_RL + row * 128;
#pragma unroll
            for (int jj = 0; jj < 2; jj++) {
                const float* xs = (const float*)&cur[jj * 2];
                uint32_t hw[4], lw[4];
#pragma unroll
                for (int j = 0; j < 4; j++) {
                    float x0 = xs[2 * j], x1 = xs[2 * j + 1];
                    uint32_t u0 = __float_as_uint(x0), u1 = __float_as_uint(x1);
                    hw[j] = __byte_perm(u0, u1, 0x7632);
                    float h0f = __uint_as_float(u0 & 0xFFFF0000u);
                    float h1f = __uint_as_float(u1 & 0xFFFF0000u);
                    lw[j] = cvt_bf16x2(x0 - h0f, x1 - h1f);
                }
                int chunk = c0 + jj;
                *(uint4*)(rhrow + ((chunk ^ s7) << 4)) = make_uint4(hw[0], hw[1], hw[2], hw[3]);
                *(uint4*)(rlrow + ((chunk ^ s7) << 4)) = make_uint4(lw[0], lw[1], lw[2], lw[3]);
            }
            NBAR_ARRIVE(g + 1, 512);
            cur[0] = nxt[0]; cur[1] = nxt[1]; cur[2] = nxt[2]; cur[3] = nxt[3];
        }
    } else {
        if (tid < 128) {
            int h = tid >> 4, dq = tid & 15;
            const __nv_bfloat16* src = g_qs + ((size_t)(b * 8 + h) * 512 + q) * 128 + dq * 4;
            *(uint2*)&QS[h * 136 + dq * 4]       = *(const uint2*)src;
            *(uint2*)&QS[(h + 8) * 136 + dq * 4] = *(const uint2*)(src + 64);
        }
        NBAR_SYNC(9, 256);

        uint32_t afr[4][4];
#pragma unroll
        for (int ds = 0; ds < 4; ds++) {
            uint32_t addr = sbase + F_QS + (lane & 15) * 272
                          + (ds * 16 + ((lane >> 4) << 3)) * 2;
            ldm_x4(afr[ds], addr);
        }

        float2 qkPre[8], hvPre[8];
        {
            int hh = lane >> 2;
            int kkb = w * 8 + (lane & 3) * 2;
#pragma unroll
            for (int g = 0; g < 8; g++) {
                int kk = g * 64 + kkb;
                qkPre[g] = *(const float2*)&g_sc[(size_t)(b * 8 + hh) * 262144
                                                 + (size_t)q * 512 + kk];
                hvPre[g] = *(const float2*)&heads[((size_t)b * 512 + q) * 512 + kk];
            }
        }

#pragma unroll 1
        for (int g = 0; g < 8; g++) {
            NBAR_SYNC(g + 1, 512);
            const int k0 = g * 64 + w * 8;
            float p0c0 = 0.f, p0c1 = 0.f, p0c2 = 0.f, p0c3 = 0.f;
            float p1c0 = 0.f, p1c1 = 0.f, p1c2 = 0.f, p1c3 = 0.f;
            const int row = k0 + (lane & 7);
            const int s7 = row & 7;
            const int csel = (lane >> 3) & 1;
#pragma unroll
            for (int ds = 0; ds < 4; ds++) {
                int chunk = ds * 2 + csel;
                uint32_t b0, b1;
                ldm_x2(b0, b1, sbase + F_RH + row * 128 + ((chunk ^ s7) << 4));
                mma_bf16(p0c0, p0c1, p0c2, p0c3,
                         afr[ds][0], afr[ds][1], afr[ds][2], afr[ds][3], b0, b1);
            }
#pragma unroll
            for (int ds = 0; ds < 4; ds++) {
                int chunk = ds * 2 + csel;
                uint32_t b0, b1;
                ldm_x2(b0, b1, sbase + F_RL + row * 128 + ((chunk ^ s7) << 4));
                mma_bf16(p1c0, p1c1, p1c2, p1c3,
                         afr[ds][0], 0u, afr[ds][2], 0u, b0, b1);
            }
            float a0 = p0c0 + p0c2 + p1c0;
            float a1 = p0c1 + p0c3 + p1c1;
            int h = lane >> 2, kk = k0 + (lane & 3) * 2;
            sc_s[h * 516 + kk]     = (a0 + qkPre[g].x) * 0.125f + hvPre[g].x;
            sc_s[h * 516 + kk + 1] = (a1 + qkPre[g].y) * 0.125f + hvPre[g].y;
        }
        NBAR_SYNC(9, 256);

        {
            float* row = sc_s + w * 516;
            float vals[16];
            float mx = -1e30f;
#pragma unroll
            for (int i = 0; i < 16; i++) { vals[i] = row[i * 32 + lane]; mx = fmaxf(mx, vals[i]); }
#pragma unroll
            for (int o = 16; o; o >>= 1) mx = fmaxf(mx, __shfl_xor_sync(0xffffffffu, mx, o));
            float s = 0.f;
#pragma unroll
            for (int i = 0; i < 16; i++) { vals[i] = __expf(vals[i] - mx); s += vals[i]; }
#pragma unroll
            for (int o = 16; o; o >>= 1) s += __shfl_xor_sync(0xffffffffu, s, o);
            float inv = 1.f / s;
            __nv_bfloat16* pgp = g_ps + ((size_t)(b * 8 + w) * 512 + q) * 1024;
#pragma unroll
            for (int i = 0; i < 16; i++) {
                float pv = vals[i] * inv;
                int kk = i * 32 + lane;
                __nv_bfloat16 ph = __float2bfloat16(pv);
                __nv_bfloat16 pl = __float2bfloat16(pv - __bfloat162float(ph));
                PS[w * 520 + kk] = ph;
                PS[(w + 8) * 520 + kk] = pl;
                pgp[kk] = ph;
                pgp[512 + kk] = pl;
            }
        }
    }
    __syncthreads();

    {
        const int kg = w >> 1, ng = w & 1;
        float aD[4][4];
#pragma unroll
        for (int i = 0; i < 4; i++)
#pragma unroll
            for (int j = 0; j < 4; j++) aD[i][j] = 0.f;

#pragma unroll
        for (int ks = 0; ks < 4; ks++) {
            const int k0 = kg * 64 + ks * 16;
            uint32_t af[4];
            uint32_t aaddr = sbase + F_PS + (lane & 15) * 1040
                           + (k0 + ((lane >> 4) << 3)) * 2;
            ldm_x4(af, aaddr);
            const int row = k0 + (lane & 7) + (((lane >> 3) & 1) << 3);
            const int s7 = row & 7;
#pragma unroll
            for (int ntl = 0; ntl < 4; ntl++) {
                int d0 = (ng * 4 + ntl) * 8;
                uint32_t b0, b1;
                ldm_x2_trans(b0, b1, sbase + F_RH + row * 128 + (((d0 >> 3) ^ s7) << 4));
                mma_bf16(aD[ntl][0], aD[ntl][1], aD[ntl][2], aD[ntl][3],
                         af[0], af[1], af[2], af[3], b0, b1);
            }
#pragma unroll
            for (int ntl = 0; ntl < 4; ntl++) {
                int d0 = (ng * 4 + ntl) * 8;
                uint32_t b0, b1;
                ldm_x2_trans(b0, b1, sbase + F_RL + row * 128 + (((d0 >> 3) ^ s7) << 4));
                mma_bf16(aD[ntl][0], aD[ntl][1], aD[ntl][2], aD[ntl][3],
                         af[0], 0u, af[2], 0u, b0, b1);
            }
        }
#pragma unroll
        for (int ntl = 0; ntl < 4; ntl++) {
            int slot = kg * 8 + ng * 4 + ntl;
            *(float2*)&red[(slot * 32 + lane) * 2] =
                make_float2(aD[ntl][0] + aD[ntl][2], aD[ntl][1] + aD[ntl][3]);
        }
    }
    __syncthreads();

    if (w < 8) {
        float rx = 0.f, ry = 0.f;
#pragma unroll
        for (int kg = 0; kg < 8; kg++) {
            float2 s = *(const float2*)&red[((kg * 8 + w) * 32 + lane) * 2];
            rx += s.x; ry += s.y;
        }
        int h = lane >> 2, d = w * 8 + (lane & 3) * 2;
        *(float2*)&out[((size_t)b * 512 + q) * 512 + h * 64 + d] = make_float2(rx, ry);
    }
}

// =============================================================================
// K4: ctx += probs @ v via mma.sync (unchanged).
// =============================================================================
__global__ __launch_bounds__(256) void k_ctx_mma(float* __restrict__ out)
{
    extern __shared__ char smp[];
    __nv_bfloat16* As = (__nv_bfloat16*)smp;
    __nv_bfloat16* Bs = As + 2 * A_BUF_ELE;

    const int m0 = blockIdx.x * 128;
    const int bh = blockIdx.y;
    const int tbase = blockIdx.z * 12;
    const int b = bh >> 3, h = bh & 7;
    const __nv_bfloat16* Ap = g_ps + (size_t)bh * 512 * 1024;
    const __nv_bfloat16* Bv = g_vT + (size_t)bh * 64 * 1024;

    const int tid = threadIdx.x;
    const int wid = tid >> 5, lane = tid & 31;
    const int wm = wid >> 1, wn = wid & 1;
    const int g  = lane >> 2, tg = lane & 3;

    float acc[2][4][4];
#pragma unroll
    for (int mt = 0; mt < 2; mt++)
#pragma unroll
        for (int nt = 0; nt < 4; nt++)
#pragma unroll
            for (int e = 0; e < 4; e++) acc[mt][nt][e] = 0.f;

    auto aoff = [](int t) { return t < 8 ? t * 64 : t < 16 ? 512 + (t - 8) * 64 : (t - 16) * 64; };
    auto boff = [](int t) { return t < 8 ? t * 64 : t < 16 ? (t - 8) * 64 : 512 + (t - 16) * 64; };

    auto load_chunk = [&](int c, int buf) {
        __nv_bfloat16* Ad = As + buf * A_BUF_ELE;
        __nv_bfloat16* Bd = Bs + buf * B_BUF_ELE;
        int ao = aoff(c), bo = boff(c);
#pragma unroll
        for (int i = 0; i < 4; i++) {
            int flat = i * 256 + tid;
            int row = flat >> 3, seg = flat & 7;
            cp_async16(Ad + row * PADK + seg * 8,
                       Ap + (size_t)(m0 + row) * 1024 + ao + seg * 8);
        }
#pragma unroll
        for (int i = 0; i < 2; i++) {
            int flat = i * 256 + tid;
            int row = flat >> 3, seg = flat & 7;
            cp_async16(Bd + row * PADK + seg * 8,
                       Bv + (size_t)row * 1024 + bo + seg * 8);
        }
        cp_commit();
    };

    load_chunk(tbase, 0);

#pragma unroll 1
    for (int t = 0; t < 12; t++) {
        if (t < 11) load_chunk(tbase + t + 1, (t + 1) & 1);
        if (t < 11) cp_wait<1>(); else cp_wait<0>();
        __syncthreads();

        const __nv_bfloat16* Ab = As + (t & 1) * A_BUF_ELE;
        const __nv_bfloat16* Bb = Bs + (t & 1) * B_BUF_ELE;

#pragma unroll
        for (int ks = 0; ks < 4; ks++) {
            const int kb = ks * 16;
            uint32_t af[2][4], bf[4][2];
#pragma unroll
            for (int mt = 0; mt < 2; mt++) {
                int r0 = wm * 32 + mt * 16 + g;
                af[mt][0] = *(const uint32_t*)&Ab[(r0)      * PADK + kb + tg * 2];
                af[mt][1] = *(const uint32_t*)&Ab[(r0 + 8)  * PADK + kb + tg * 2];
                af[mt][2] = *(const uint32_t*)&Ab[(r0)      * PADK + kb + tg * 2 + 8];
                af[mt][3] = *(const uint32_t*)&Ab[(r0 + 8)  * PADK + kb + tg * 2 + 8];
            }
#pragma unroll
            for (int nt = 0; nt < 4; nt++) {
                int nr = wn * 32 + nt * 8 + g;
                bf[nt][0] = *(const uint32_t*)&Bb[nr * PADK + kb + tg * 2];
                bf[nt][1] = *(const uint32_t*)&Bb[nr * PADK + kb + tg * 2 + 8];
            }
#pragma unroll
            for (int mt = 0; mt < 2; mt++)
#pragma unroll
                for (int nt = 0; nt < 4; nt++)
                    mma_bf16(acc[mt][nt][0], acc[mt][nt][1], acc[mt][nt][2], acc[mt][nt][3],
                             af[mt][0], af[mt][1], af[mt][2], af[mt][3],
                             bf[nt][0], bf[nt][1]);
        }
        __syncthreads();
    }

#pragma unroll
    for (int mt = 0; mt < 2; mt++) {
        int r0 = m0 + wm * 32 + mt * 16 + g;
#pragma unroll
        for (int nt = 0; nt < 4; nt++) {
            int cl = wn * 32 + nt * 8 + tg * 2;
            float* p0 = &out[((size_t)(b * 512 + r0)) * 512 + h * 64 + cl];
            atomicAdd(p0 + 0, acc[mt][nt][0]);
            atomicAdd(p0 + 1, acc[mt][nt][1]);
            float* p1 = &out[((size_t)(b * 512 + r0 + 8)) * 512 + h * 64 + cl];
            atomicAdd(p1 + 0, acc[mt][nt][2]);
            atomicAdd(p1 + 1, acc[mt][nt][3]);
        }
    }
}

// =============================================================================
extern "C" void kernel_launch(void* const* d_in, const int* in_sizes, int n_in,
                              void* d_out, int out_size)
{
    const float* hidden = (const float*)d_in[0];
    const float* heads  = (const float*)d_in[1];
    const float* rels   = (const float*)d_in[2];
    const float* Wq = (const float*)d_in[3];
    const float* bq = (const float*)d_in[4];
    const float* Wk = (const float*)d_in[5];
    const float* bk = (const float*)d_in[6];
    const float* Wv = (const float*)d_in[7];
    const float* bv = (const float*)d_in[8];
    float* out = (float*)d_out;

    k_prep<<<1024, 256>>>(hidden, Wq, Wk, Wv);

    cudaFuncSetAttribute(k_proj_mma, cudaFuncAttributeMaxDynamicSharedMemorySize, SMEM_PROJ);
    dim3 g1(8, 16, 3);
    k_proj_mma<<<g1, 256, SMEM_PROJ>>>(bq, bk, bv);

    cudaFuncSetAttribute(k_scores_mma, cudaFuncAttributeMaxDynamicSharedMemorySize, SMEM_SC2);
    dim3 g2(4, 4, 32);
    k_scores_mma<<<g2, 256, SMEM_SC2>>>();

    cudaFuncSetAttribute(k_fused, cudaFuncAttributeMaxDynamicSharedMemorySize, SMEM_FUSED);
    k_fused<<<2048, 512, SMEM_FUSED>>>(rels, heads, out);

    cudaFuncSetAttribute(k_ctx_mma, cudaFuncAttributeMaxDynamicSharedMemorySize, SMEM_PROJ);
    dim3 g4(4, 32, 2);
    k_ctx_mma<<<g4, 256, SMEM_PROJ>>>(out);
}